// round 9
// baseline (speedup 1.0000x reference)
#include <cuda_runtime.h>
#include <cuda_fp16.h>
#include <math.h>
#include <stdint.h>

// Problem shapes (fixed by the reference)
#define BB      2
#define LL      1024
#define DIM     1024
#define DI      2048          // d_inner
#define MROWS   (BB*LL)       // 2048
#define DTRANK  64
#define DSTATE  16
#define XPROJ_N (DTRANK + 2*DSTATE)  // 96
#define NSPLIT  8

typedef __half fp16;

// ---------------- scratch (device globals; no allocation allowed) ----------
__device__ float g_xz  [MROWS * 2 * DI];
__device__ float g_u   [MROWS * DI];
__device__ float g_xdbl[MROWS * XPROJ_N];
__device__ float g_dt  [MROWS * DI];
__device__ float g_part[NSPLIT * MROWS * XPROJ_N];

__device__ fp16 g_xnh [MROWS * DIM];
__device__ fp16 g_winh[2*DI * DIM];
__device__ fp16 g_yh  [MROWS * DI];
__device__ fp16 g_woh [DIM * DI];
__device__ fp16 g_dtrh[MROWS * DTRANK];
__device__ fp16 g_wdth[DI * DTRANK];

// =================== baseline PTX helpers (no arch-'a' features) ============
__device__ __forceinline__ uint32_t smem_u32(const void* p) {
    uint32_t a;
    asm("{ .reg .u64 t; cvta.to.shared.u64 t, %1; cvt.u32.u64 %0, t; }" : "=r"(a) : "l"(p));
    return a;
}
#define CP_ASYNC16(dst, src) \
    asm volatile("cp.async.cg.shared.global [%0], [%1], 16;" :: "r"(dst), "l"(src))
#define CP_COMMIT() asm volatile("cp.async.commit_group;" ::: "memory")
#define CP_WAIT(n)  asm volatile("cp.async.wait_group %0;" :: "n"(n) : "memory")

__device__ __forceinline__ void ldsm4(uint32_t* r, uint32_t addr) {
    asm volatile("ldmatrix.sync.aligned.m8n8.x4.shared.b16 {%0,%1,%2,%3}, [%4];"
                 : "=r"(r[0]), "=r"(r[1]), "=r"(r[2]), "=r"(r[3]) : "r"(addr));
}
__device__ __forceinline__ void mma_fp16(float* c, const uint32_t* a, const uint32_t* b) {
    asm volatile("mma.sync.aligned.m16n8k16.row.col.f32.f16.f16.f32 "
                 "{%0,%1,%2,%3}, {%4,%5,%6,%7}, {%8,%9}, {%0,%1,%2,%3};"
                 : "+f"(c[0]), "+f"(c[1]), "+f"(c[2]), "+f"(c[3])
                 : "r"(a[0]), "r"(a[1]), "r"(a[2]), "r"(a[3]), "r"(b[0]), "r"(b[1]));
}
// SW64 swizzle for 64-byte stage rows (verified conflict-free for ldsm phases)
__device__ __forceinline__ uint32_t sw64(uint32_t off) { return off ^ ((off >> 3) & 0x30); }

// =================== fp16 mma.sync GEMM: C = A @ B^T ========================
// Pure fp16 A and B. BM=128, BN in {128,64}, BK=32/stage, 3-stage cp.async
// ring, 8 warps, 2 CTAs/SM. All ldsm of a k16-slice hoisted before MMAs.
// EPI: 0 none, 1 softplus+bias, 2 +resid
template<int EPI, int BN>
__global__ void __launch_bounds__(256, 2)
gemm_f16(const fp16* __restrict__ Ah, const fp16* __restrict__ Bh,
         float* __restrict__ C, const float* __restrict__ aux,
         int K, int ldc) {
    extern __shared__ char smem[];
    const uint32_t sb = smem_u32(smem);
    constexpr int ABY = 128 * 64;            // bytes for A per stage
    constexpr int BBY = BN * 64;             // bytes for B per stage
    constexpr int STG = ABY + BBY;           // stage size
    constexpr int MT  = (BN == 128) ? 4 : 2; // m16 tiles per warp
    const int tid = threadIdx.x, wid = tid >> 5, lane = tid & 31;
    const int m0 = blockIdx.y * 128, n0 = blockIdx.x * BN;
    const int wm = (BN == 128) ? (wid >> 2) : (wid >> 1);
    const int wn = (BN == 128) ? (wid & 3)  : (wid & 1);

    float acc[MT][4][4];
    #pragma unroll
    for (int a = 0; a < MT; a++)
        #pragma unroll
        for (int b = 0; b < 4; b++)
            #pragma unroll
            for (int c = 0; c < 4; c++) acc[a][b][c] = 0.f;

    // stage s: [Ah | Bh], 64B SW64 rows of 32 fp16
    auto load_stage = [&](int s, int kc) {
        uint32_t base = sb + s * STG;
        #pragma unroll
        for (int it = 0; it < 2; it++) {          // A: 128 rows
            int i = tid + it * 256;
            int row = i >> 2, j = i & 3;
            uint32_t so = sw64(row * 64 + j * 16);
            CP_ASYNC16(base + so,
                       Ah + (size_t)(m0 + row) * K + kc * 32 + j * 8);
        }
        #pragma unroll
        for (int it = 0; it < BN / 64; it++) {    // B: BN rows
            int i = tid + it * 256;
            int row = i >> 2, j = i & 3;
            uint32_t so = sw64(row * 64 + j * 16);
            CP_ASYNC16(base + ABY + so,
                       Bh + (size_t)(n0 + row) * K + kc * 32 + j * 8);
        }
        CP_COMMIT();
    };

    auto compute = [&](int s) {
        uint32_t pAh = sb + s * STG;
        uint32_t pBh = pAh + ABY;
        #pragma unroll
        for (int kk = 0; kk < 2; kk++) {
            uint32_t bh[2][4], ah[MT][4];
            int grp = lane >> 3, l8 = lane & 7;
            int kbB = kk * 32 + ((grp & 1) << 4);
            #pragma unroll
            for (int pr = 0; pr < 2; pr++) {
                int row = wn * 32 + pr * 16 + ((grp >> 1) << 3) + l8;
                ldsm4(bh[pr], pBh + sw64(row * 64 + kbB));
            }
            int kbA = kk * 32 + ((lane >> 4) << 4);
            #pragma unroll
            for (int mt = 0; mt < MT; mt++) {
                int row = wm * (MT * 16) + mt * 16 + (lane & 15);
                ldsm4(ah[mt], pAh + sw64(row * 64 + kbA));
            }
            #pragma unroll
            for (int mt = 0; mt < MT; mt++)
                #pragma unroll
                for (int pr = 0; pr < 2; pr++)
                    #pragma unroll
                    for (int half = 0; half < 2; half++)
                        mma_fp16(acc[mt][pr * 2 + half], ah[mt], &bh[pr][half * 2]);
        }
    };

    const int nst = K >> 5;
    load_stage(0, 0);
    if (nst > 1) load_stage(1, 1);
    int slot = 0;
    for (int kc = 0; kc < nst; kc++) {
        if (kc + 1 < nst) CP_WAIT(1); else CP_WAIT(0);
        __syncthreads();                       // stage kc ready, prev compute done
        if (kc + 2 < nst) load_stage((kc + 2) % 3, kc + 2);
        compute(slot);
        slot = (slot + 1 == 3) ? 0 : slot + 1;
    }

    // epilogue: write fp32 directly from fragments
    #pragma unroll
    for (int mt = 0; mt < MT; mt++) {
        #pragma unroll
        for (int nt = 0; nt < 4; nt++) {
            int row = m0 + wm * (MT * 16) + mt * 16 + (lane >> 2);
            int col = n0 + wn * 32 + nt * 8 + (lane & 3) * 2;
            float v[4] = {acc[mt][nt][0], acc[mt][nt][1], acc[mt][nt][2], acc[mt][nt][3]};
            if (EPI == 1) {
                #pragma unroll
                for (int i = 0; i < 4; i++) {
                    float t = v[i] + aux[col + (i & 1)];
                    v[i] = fmaxf(t, 0.f) + log1pf(__expf(-fabsf(t)));
                }
            } else if (EPI == 2) {
                v[0] += aux[(size_t)row * ldc + col];
                v[1] += aux[(size_t)row * ldc + col + 1];
                v[2] += aux[(size_t)(row + 8) * ldc + col];
                v[3] += aux[(size_t)(row + 8) * ldc + col + 1];
            }
            *reinterpret_cast<float2*>(&C[(size_t)row * ldc + col])       = make_float2(v[0], v[1]);
            *reinterpret_cast<float2*>(&C[(size_t)(row + 8) * ldc + col]) = make_float2(v[2], v[3]);
        }
    }
}

// ---------------- merged weight conversion (w_in | w_out | w_dt) ------------
__global__ void cvt_all(const float* __restrict__ w_in, const float* __restrict__ w_out,
                        const float* __restrict__ w_dt,
                        fp16* __restrict__ winh, fp16* __restrict__ woh,
                        fp16* __restrict__ wdth) {
    const int N1 = 2*DI*DIM/4, N2 = DIM*DI/4, N3 = DI*DTRANK/4;
    int i = blockIdx.x * blockDim.x + threadIdx.x;
    const float* s; fp16* d; int k;
    if (i < N1)            { s = w_in;  d = winh; k = i; }
    else if (i < N1 + N2)  { s = w_out; d = woh;  k = i - N1; }
    else if (i < N1+N2+N3) { s = w_dt;  d = wdth; k = i - N1 - N2; }
    else return;
    float4 v = reinterpret_cast<const float4*>(s)[k];
    __half2* hp = reinterpret_cast<__half2*>(d);
    hp[k*2]   = __floats2half2_rn(v.x, v.y);
    hp[k*2+1] = __floats2half2_rn(v.z, v.w);
}

// ---------------- LayerNorm (fp16 output) -----------------------------------
__global__ void ln_kernel(const float* __restrict__ x,
                          const float* __restrict__ w,
                          const float* __restrict__ b,
                          fp16* __restrict__ xnh) {
    int row = blockIdx.x;
    int tid = threadIdx.x;
    const float4* xr = reinterpret_cast<const float4*>(x + row * DIM);
    float4 v = xr[tid];
    float s  = v.x + v.y + v.z + v.w;
    float sq = v.x*v.x + v.y*v.y + v.z*v.z + v.w*v.w;
    __shared__ float red[2][8];
    for (int off = 16; off > 0; off >>= 1) {
        s  += __shfl_xor_sync(0xffffffffu, s,  off);
        sq += __shfl_xor_sync(0xffffffffu, sq, off);
    }
    int warp = tid >> 5, lane = tid & 31;
    if (lane == 0) { red[0][warp] = s; red[1][warp] = sq; }
    __syncthreads();
    if (warp == 0) {
        float a = (lane < 8) ? red[0][lane] : 0.f;
        float c = (lane < 8) ? red[1][lane] : 0.f;
        for (int off = 4; off > 0; off >>= 1) {
            a += __shfl_xor_sync(0xffffffffu, a, off);
            c += __shfl_xor_sync(0xffffffffu, c, off);
        }
        if (lane == 0) { red[0][0] = a; red[1][0] = c; }
    }
    __syncthreads();
    float mu  = red[0][0] * (1.f / DIM);
    float var = red[1][0] * (1.f / DIM) - mu * mu;
    float rs  = rsqrtf(var + 1e-5f);
    const float4* w4 = reinterpret_cast<const float4*>(w);
    const float4* b4 = reinterpret_cast<const float4*>(b);
    float4 ww = w4[tid], bb = b4[tid];
    float o0 = (v.x - mu) * rs * ww.x + bb.x;
    float o1 = (v.y - mu) * rs * ww.y + bb.y;
    float o2 = (v.z - mu) * rs * ww.z + bb.z;
    float o3 = (v.w - mu) * rs * ww.w + bb.w;
    __half2* hp = reinterpret_cast<__half2*>(xnh + (size_t)row * DIM + tid * 4);
    hp[0] = __floats2half2_rn(o0, o1);
    hp[1] = __floats2half2_rn(o2, o3);
}

// ---------------- xproj split-K with FUSED conv+SiLU ------------------------
// Block (m0, split): A tile rows m0..m0+31, cols e in [split*256,(split+1)*256).
// A element = u(row, e) = silu(conv(xz)) computed in place (each (row,e) is
// owned by exactly one block) and written to u_out for the scan.
__global__ void xproj_partial(const float* __restrict__ xz,
                              const float* __restrict__ cw,
                              const float* __restrict__ cb,
                              const float* __restrict__ W,
                              float* __restrict__ part,
                              float* __restrict__ u_out) {
    __shared__ float As[32][33];
    __shared__ float Ws[32][97];
    int tid = threadIdx.x;
    int m0 = blockIdx.x * 32;
    int split = blockIdx.y;
    int kbase = split * (DI / NSPLIT);
    int tx = tid & 15, ty = tid >> 4;
    float acc[2][6];
    #pragma unroll
    for (int i = 0; i < 2; i++)
        #pragma unroll
        for (int j = 0; j < 6; j++) acc[i][j] = 0.f;

    for (int k0 = 0; k0 < DI / NSPLIT; k0 += 32) {
        {   // A tile 32x32: compute u = silu(conv(xz)) on the fly
            int row = tid >> 3, j = tid & 7;
            int grow = m0 + row;
            int l = grow & (LL - 1);
            int e0 = kbase + k0 + j * 4;
            float a[4];
            #pragma unroll
            for (int ee = 0; ee < 4; ee++) a[ee] = cb[e0 + ee];
            #pragma unroll
            for (int k = 0; k < 4; k++) {
                if (l + k - 3 >= 0) {
                    const float* xr = xz + (size_t)(grow + k - 3) * (2 * DI) + e0;
                    #pragma unroll
                    for (int ee = 0; ee < 4; ee++)
                        a[ee] = fmaf(cw[(e0 + ee) * 4 + k], xr[ee], a[ee]);
                }
            }
            float uu[4];
            #pragma unroll
            for (int ee = 0; ee < 4; ee++) {
                uu[ee] = a[ee] / (1.f + __expf(-a[ee]));
                As[j * 4 + ee][row] = uu[ee];
            }
            *reinterpret_cast<float4*>(u_out + (size_t)grow * DI + e0) =
                make_float4(uu[0], uu[1], uu[2], uu[3]);
        }
        #pragma unroll
        for (int it = 0; it < 3; it++) {   // W tile 96x32
            int i = tid + it * 256;
            int row = i >> 3, j = i & 7;
            float4 v = *reinterpret_cast<const float4*>(&W[(size_t)row * DI + kbase + k0 + j * 4]);
            Ws[j*4+0][row] = v.x; Ws[j*4+1][row] = v.y;
            Ws[j*4+2][row] = v.z; Ws[j*4+3][row] = v.w;
        }
        __syncthreads();
        #pragma unroll
        for (int kk = 0; kk < 32; kk++) {
            float a0 = As[kk][ty * 2 + 0], a1 = As[kk][ty * 2 + 1];
            float w[6];
            #pragma unroll
            for (int j = 0; j < 6; j++) w[j] = Ws[kk][tx * 6 + j];
            #pragma unroll
            for (int j = 0; j < 6; j++) {
                acc[0][j] = fmaf(a0, w[j], acc[0][j]);
                acc[1][j] = fmaf(a1, w[j], acc[1][j]);
            }
        }
        __syncthreads();
    }
    float* dst = part + (size_t)split * MROWS * XPROJ_N;
    #pragma unroll
    for (int i = 0; i < 2; i++)
        #pragma unroll
        for (int j = 0; j < 6; j++)
            dst[(size_t)(m0 + ty * 2 + i) * XPROJ_N + tx * 6 + j] = acc[i][j];
}

// reduce over splits; cols<64 also emit dt_r fp16 (packed ld=64)
__global__ void xproj_reduce(const float* __restrict__ part, float* __restrict__ xdbl,
                             fp16* __restrict__ dtrh) {
    int i = blockIdx.x * blockDim.x + threadIdx.x;   // over MROWS*24 float4s
    const int TOT4 = MROWS * XPROJ_N / 4;
    if (i >= TOT4) return;
    float4 s = reinterpret_cast<const float4*>(part)[i];
    #pragma unroll
    for (int sp = 1; sp < NSPLIT; sp++) {
        float4 v = reinterpret_cast<const float4*>(part + (size_t)sp * MROWS * XPROJ_N)[i];
        s.x += v.x; s.y += v.y; s.z += v.z; s.w += v.w;
    }
    reinterpret_cast<float4*>(xdbl)[i] = s;
    int row = i / 24, c4 = (i % 24) * 4;
    if (c4 < DTRANK) {
        __half2* hp = reinterpret_cast<__half2*>(dtrh + (size_t)row * DTRANK + c4);
        hp[0] = __floats2half2_rn(s.x, s.y);
        hp[1] = __floats2half2_rn(s.z, s.w);
    }
}

// ---------------- SSM selective scan (writes y as fp16) ---------------------
#define CHUNK 64
__global__ void scan_kernel(const float* __restrict__ dt,
                            const float* __restrict__ u,
                            const float* __restrict__ xdbl,
                            const float* __restrict__ xz,
                            const float* __restrict__ a_log,
                            const float* __restrict__ d_skip,
                            fp16* __restrict__ yh) {
    __shared__ float sB [CHUNK][DSTATE];
    __shared__ float sC [CHUNK][DSTATE];
    __shared__ float sDt[CHUNK][16];
    __shared__ float sU [CHUNK][16];
    __shared__ float sZ [CHUNK][16];
    int tid  = threadIdx.x;
    int g    = tid >> 4;
    int lane = tid & 15;
    int c0   = blockIdx.x * 16;
    int b    = c0 >> 11;
    int e0   = c0 & (DI - 1);
    int e    = e0 + g;
    float A_n = -__expf(a_log[e * DSTATE + lane]);
    float dsk = d_skip[e];
    float h = 0.f;
    int rowbase = b * LL;
    for (int l0 = 0; l0 < LL; l0 += CHUNK) {
        __syncthreads();
        for (int i = tid; i < CHUNK * 2 * DSTATE; i += 256) {
            int r = i >> 5, j = i & 31;
            float v = xdbl[(size_t)(rowbase + l0 + r) * XPROJ_N + DTRANK + j];
            if (j < DSTATE) sB[r][j] = v; else sC[r][j - DSTATE] = v;
        }
        for (int i = tid; i < CHUNK * 16; i += 256) {
            int r = i >> 4, j = i & 15;
            size_t m = (size_t)(rowbase + l0 + r);
            sDt[r][j] = dt[m * DI + e0 + j];
            sU [r][j] = u [m * DI + e0 + j];
            sZ [r][j] = xz[m * (2 * DI) + DI + e0 + j];
        }
        __syncthreads();
        #pragma unroll 4
        for (int r = 0; r < CHUNK; r++) {
            float dtv = sDt[r][g];
            float uv  = sU [r][g];
            float dA  = __expf(dtv * A_n);
            float dBu = dtv * sB[r][lane] * uv;
            h = fmaf(dA, h, dBu);
            float yv = h * sC[r][lane];
            yv += __shfl_xor_sync(0xffffffffu, yv, 8);
            yv += __shfl_xor_sync(0xffffffffu, yv, 4);
            yv += __shfl_xor_sync(0xffffffffu, yv, 2);
            yv += __shfl_xor_sync(0xffffffffu, yv, 1);
            if (lane == 0) {
                float zv = sZ[r][g];
                float sz = zv / (1.f + __expf(-zv));
                float yo = (yv + uv * dsk) * sz;
                yh[(size_t)(rowbase + l0 + r) * DI + e] = __float2half_rn(yo);
            }
        }
    }
}

// ---------------- launch -----------------------------------------------------
extern "C" void kernel_launch(void* const* d_in, const int* in_sizes, int n_in,
                              void* d_out, int out_size) {
    const float* x      = (const float*)d_in[0];
    const float* ln_w   = (const float*)d_in[1];
    const float* ln_b   = (const float*)d_in[2];
    const float* w_in   = (const float*)d_in[3];
    const float* conv_w = (const float*)d_in[4];
    const float* conv_b = (const float*)d_in[5];
    const float* w_xpr  = (const float*)d_in[6];
    const float* w_dt   = (const float*)d_in[7];
    const float* b_dt   = (const float*)d_in[8];
    const float* a_log  = (const float*)d_in[9];
    const float* d_skip = (const float*)d_in[10];
    const float* w_out  = (const float*)d_in[11];
    float* out = (float*)d_out;

    float *xz, *u, *xdbl, *dt, *part;
    fp16 *xnh, *winh, *yh, *woh, *dtrh, *wdth;
    cudaGetSymbolAddress((void**)&xz,   g_xz);
    cudaGetSymbolAddress((void**)&u,    g_u);
    cudaGetSymbolAddress((void**)&xdbl, g_xdbl);
    cudaGetSymbolAddress((void**)&dt,   g_dt);
    cudaGetSymbolAddress((void**)&part, g_part);
    cudaGetSymbolAddress((void**)&xnh,  g_xnh);
    cudaGetSymbolAddress((void**)&winh, g_winh);
    cudaGetSymbolAddress((void**)&yh,   g_yh);
    cudaGetSymbolAddress((void**)&woh,  g_woh);
    cudaGetSymbolAddress((void**)&dtrh, g_dtrh);
    cudaGetSymbolAddress((void**)&wdth, g_wdth);

    const int SMEM128 = 3 * 16384;   // BN=128: 48 KB, 3-stage ring
    const int SMEM64  = 3 * 12288;   // BN=64:  36 KB, 3-stage ring
    cudaFuncSetAttribute((const void*)gemm_f16<0,128>, cudaFuncAttributeMaxDynamicSharedMemorySize, SMEM128);
    cudaFuncSetAttribute((const void*)gemm_f16<1,128>, cudaFuncAttributeMaxDynamicSharedMemorySize, SMEM128);
    cudaFuncSetAttribute((const void*)gemm_f16<2,64>,  cudaFuncAttributeMaxDynamicSharedMemorySize, SMEM64);

    const int NCVT = (2*DI*DIM + DIM*DI + DI*DTRANK) / 4;
    // 1. all weight conversions (one launch)
    cvt_all<<<(NCVT + 255)/256, 256>>>(w_in, w_out, w_dt, winh, woh, wdth);
    // 2. LayerNorm (fp16 output)
    ln_kernel<<<MROWS, 256>>>(x, ln_w, ln_b, xnh);
    // 3. xz = xn @ w_in^T   (2048 x 4096 x 1024)  [fp16 mma, BN=128]
    gemm_f16<0,128><<<dim3(4096/128, MROWS/128), 256, SMEM128>>>(
        xnh, winh, xz, nullptr, DIM, 2*DI);
    // 4. x_dbl partial = silu(conv(xz)) @ w_xproj^T  [fused conv, split-K fp32]
    xproj_partial<<<dim3(MROWS/32, NSPLIT), 256>>>(xz, conv_w, conv_b, w_xpr, part, u);
    // 5. reduce + dt_r fp16 extract
    xproj_reduce<<<(MROWS*XPROJ_N/4 + 255)/256, 256>>>(part, xdbl, dtrh);
    // 6. dt = softplus(dt_r @ w_dt^T + b_dt)  (2048 x 2048 x 64)  [BN=128]
    gemm_f16<1,128><<<dim3(DI/128, MROWS/128), 256, SMEM128>>>(
        dtrh, wdth, dt, b_dt, DTRANK, DI);
    // 7. selective scan (+ skip + gate, fp16 output)
    scan_kernel<<<(BB*DI)/16, 256>>>(dt, u, xdbl, xz, a_log, d_skip, yh);
    // 8. out = residual + y @ w_out^T  (2048 x 1024 x 2048)  [BN=64, 256 CTAs]
    gemm_f16<2,64><<<dim3(DIM/64, MROWS/128), 256, SMEM64>>>(
        yh, woh, out, x, DI, DIM);
}

// round 10
// speedup vs baseline: 1.0805x; 1.0805x over previous
#include <cuda_runtime.h>
#include <cuda_fp16.h>
#include <math.h>
#include <stdint.h>

// Problem shapes (fixed by the reference)
#define BB      2
#define LL      1024
#define DIM     1024
#define DI      2048          // d_inner
#define MROWS   (BB*LL)       // 2048
#define DTRANK  64
#define DSTATE  16
#define XPROJ_N (DTRANK + 2*DSTATE)  // 96
#define NSPLIT  8

typedef __half fp16;

// ---------------- scratch (device globals; no allocation allowed) ----------
__device__ float g_xz  [MROWS * 2 * DI];
__device__ float g_u   [MROWS * DI];
__device__ float g_xdbl[MROWS * XPROJ_N];
__device__ float g_dt  [MROWS * DI];
__device__ float g_part[NSPLIT * MROWS * XPROJ_N];

__device__ fp16 g_xnh [MROWS * DIM];
__device__ fp16 g_winh[2*DI * DIM];
__device__ fp16 g_yh  [MROWS * DI];
__device__ fp16 g_woh [DIM * DI];
__device__ fp16 g_dtrh[MROWS * DTRANK];
__device__ fp16 g_wdth[DI * DTRANK];

// =================== baseline PTX helpers (no arch-'a' features) ============
__device__ __forceinline__ uint32_t smem_u32(const void* p) {
    uint32_t a;
    asm("{ .reg .u64 t; cvta.to.shared.u64 t, %1; cvt.u32.u64 %0, t; }" : "=r"(a) : "l"(p));
    return a;
}
#define CP_ASYNC16(dst, src) \
    asm volatile("cp.async.cg.shared.global [%0], [%1], 16;" :: "r"(dst), "l"(src))
#define CP_COMMIT() asm volatile("cp.async.commit_group;" ::: "memory")
#define CP_WAIT(n)  asm volatile("cp.async.wait_group %0;" :: "n"(n) : "memory")

__device__ __forceinline__ void ldsm4(uint32_t* r, uint32_t addr) {
    asm volatile("ldmatrix.sync.aligned.m8n8.x4.shared.b16 {%0,%1,%2,%3}, [%4];"
                 : "=r"(r[0]), "=r"(r[1]), "=r"(r[2]), "=r"(r[3]) : "r"(addr));
}
__device__ __forceinline__ void mma_fp16(float* c, const uint32_t* a, const uint32_t* b) {
    asm volatile("mma.sync.aligned.m16n8k16.row.col.f32.f16.f16.f32 "
                 "{%0,%1,%2,%3}, {%4,%5,%6,%7}, {%8,%9}, {%0,%1,%2,%3};"
                 : "+f"(c[0]), "+f"(c[1]), "+f"(c[2]), "+f"(c[3])
                 : "r"(a[0]), "r"(a[1]), "r"(a[2]), "r"(a[3]), "r"(b[0]), "r"(b[1]));
}
// SW64 swizzle for 64-byte stage rows (verified conflict-free for ldsm phases)
__device__ __forceinline__ uint32_t sw64(uint32_t off) { return off ^ ((off >> 3) & 0x30); }

// =================== fp16 mma.sync GEMM: C = A @ B^T ========================
// Pure fp16 A and B. BM=128, BN in {128,64}, BK=32/stage, 3-stage cp.async
// ring, 8 warps, 2 CTAs/SM. All ldsm of a k16-slice hoisted before MMAs.
// EPI: 0 none, 1 softplus+bias, 2 +resid
template<int EPI, int BN>
__global__ void __launch_bounds__(256, 2)
gemm_f16(const fp16* __restrict__ Ah, const fp16* __restrict__ Bh,
         float* __restrict__ C, const float* __restrict__ aux,
         int K, int ldc) {
    extern __shared__ char smem[];
    const uint32_t sb = smem_u32(smem);
    constexpr int ABY = 128 * 64;            // bytes for A per stage
    constexpr int BBY = BN * 64;             // bytes for B per stage
    constexpr int STG = ABY + BBY;           // stage size
    constexpr int MT  = (BN == 128) ? 4 : 2; // m16 tiles per warp
    const int tid = threadIdx.x, wid = tid >> 5, lane = tid & 31;
    const int m0 = blockIdx.y * 128, n0 = blockIdx.x * BN;
    const int wm = (BN == 128) ? (wid >> 2) : (wid >> 1);
    const int wn = (BN == 128) ? (wid & 3)  : (wid & 1);

    float acc[MT][4][4];
    #pragma unroll
    for (int a = 0; a < MT; a++)
        #pragma unroll
        for (int b = 0; b < 4; b++)
            #pragma unroll
            for (int c = 0; c < 4; c++) acc[a][b][c] = 0.f;

    // stage s: [Ah | Bh], 64B SW64 rows of 32 fp16
    auto load_stage = [&](int s, int kc) {
        uint32_t base = sb + s * STG;
        #pragma unroll
        for (int it = 0; it < 2; it++) {          // A: 128 rows
            int i = tid + it * 256;
            int row = i >> 2, j = i & 3;
            uint32_t so = sw64(row * 64 + j * 16);
            CP_ASYNC16(base + so,
                       Ah + (size_t)(m0 + row) * K + kc * 32 + j * 8);
        }
        #pragma unroll
        for (int it = 0; it < BN / 64; it++) {    // B: BN rows
            int i = tid + it * 256;
            int row = i >> 2, j = i & 3;
            uint32_t so = sw64(row * 64 + j * 16);
            CP_ASYNC16(base + ABY + so,
                       Bh + (size_t)(n0 + row) * K + kc * 32 + j * 8);
        }
        CP_COMMIT();
    };

    auto compute = [&](int s) {
        uint32_t pAh = sb + s * STG;
        uint32_t pBh = pAh + ABY;
        #pragma unroll
        for (int kk = 0; kk < 2; kk++) {
            uint32_t bh[2][4], ah[MT][4];
            int grp = lane >> 3, l8 = lane & 7;
            int kbB = kk * 32 + ((grp & 1) << 4);
            #pragma unroll
            for (int pr = 0; pr < 2; pr++) {
                int row = wn * 32 + pr * 16 + ((grp >> 1) << 3) + l8;
                ldsm4(bh[pr], pBh + sw64(row * 64 + kbB));
            }
            int kbA = kk * 32 + ((lane >> 4) << 4);
            #pragma unroll
            for (int mt = 0; mt < MT; mt++) {
                int row = wm * (MT * 16) + mt * 16 + (lane & 15);
                ldsm4(ah[mt], pAh + sw64(row * 64 + kbA));
            }
            #pragma unroll
            for (int mt = 0; mt < MT; mt++)
                #pragma unroll
                for (int pr = 0; pr < 2; pr++)
                    #pragma unroll
                    for (int half = 0; half < 2; half++)
                        mma_fp16(acc[mt][pr * 2 + half], ah[mt], &bh[pr][half * 2]);
        }
    };

    const int nst = K >> 5;
    load_stage(0, 0);
    if (nst > 1) load_stage(1, 1);
    int slot = 0;
    for (int kc = 0; kc < nst; kc++) {
        if (kc + 1 < nst) CP_WAIT(1); else CP_WAIT(0);
        __syncthreads();                       // stage kc ready, prev compute done
        if (kc + 2 < nst) load_stage((kc + 2) % 3, kc + 2);
        compute(slot);
        slot = (slot + 1 == 3) ? 0 : slot + 1;
    }

    // epilogue: write fp32 directly from fragments
    #pragma unroll
    for (int mt = 0; mt < MT; mt++) {
        #pragma unroll
        for (int nt = 0; nt < 4; nt++) {
            int row = m0 + wm * (MT * 16) + mt * 16 + (lane >> 2);
            int col = n0 + wn * 32 + nt * 8 + (lane & 3) * 2;
            float v[4] = {acc[mt][nt][0], acc[mt][nt][1], acc[mt][nt][2], acc[mt][nt][3]};
            if (EPI == 1) {
                #pragma unroll
                for (int i = 0; i < 4; i++) {
                    float t = v[i] + aux[col + (i & 1)];
                    v[i] = fmaxf(t, 0.f) + log1pf(__expf(-fabsf(t)));
                }
            } else if (EPI == 2) {
                v[0] += aux[(size_t)row * ldc + col];
                v[1] += aux[(size_t)row * ldc + col + 1];
                v[2] += aux[(size_t)(row + 8) * ldc + col];
                v[3] += aux[(size_t)(row + 8) * ldc + col + 1];
            }
            *reinterpret_cast<float2*>(&C[(size_t)row * ldc + col])       = make_float2(v[0], v[1]);
            *reinterpret_cast<float2*>(&C[(size_t)(row + 8) * ldc + col]) = make_float2(v[2], v[3]);
        }
    }
}

// ---------------- merged weight conversion (w_in | w_out | w_dt) ------------
__global__ void cvt_all(const float* __restrict__ w_in, const float* __restrict__ w_out,
                        const float* __restrict__ w_dt,
                        fp16* __restrict__ winh, fp16* __restrict__ woh,
                        fp16* __restrict__ wdth) {
    const int N1 = 2*DI*DIM/4, N2 = DIM*DI/4, N3 = DI*DTRANK/4;
    int i = blockIdx.x * blockDim.x + threadIdx.x;
    const float* s; fp16* d; int k;
    if (i < N1)            { s = w_in;  d = winh; k = i; }
    else if (i < N1 + N2)  { s = w_out; d = woh;  k = i - N1; }
    else if (i < N1+N2+N3) { s = w_dt;  d = wdth; k = i - N1 - N2; }
    else return;
    float4 v = reinterpret_cast<const float4*>(s)[k];
    __half2* hp = reinterpret_cast<__half2*>(d);
    hp[k*2]   = __floats2half2_rn(v.x, v.y);
    hp[k*2+1] = __floats2half2_rn(v.z, v.w);
}

// ---------------- LayerNorm (fp16 output) -----------------------------------
__global__ void ln_kernel(const float* __restrict__ x,
                          const float* __restrict__ w,
                          const float* __restrict__ b,
                          fp16* __restrict__ xnh) {
    int row = blockIdx.x;
    int tid = threadIdx.x;
    const float4* xr = reinterpret_cast<const float4*>(x + row * DIM);
    float4 v = xr[tid];
    float s  = v.x + v.y + v.z + v.w;
    float sq = v.x*v.x + v.y*v.y + v.z*v.z + v.w*v.w;
    __shared__ float red[2][8];
    for (int off = 16; off > 0; off >>= 1) {
        s  += __shfl_xor_sync(0xffffffffu, s,  off);
        sq += __shfl_xor_sync(0xffffffffu, sq, off);
    }
    int warp = tid >> 5, lane = tid & 31;
    if (lane == 0) { red[0][warp] = s; red[1][warp] = sq; }
    __syncthreads();
    if (warp == 0) {
        float a = (lane < 8) ? red[0][lane] : 0.f;
        float c = (lane < 8) ? red[1][lane] : 0.f;
        for (int off = 4; off > 0; off >>= 1) {
            a += __shfl_xor_sync(0xffffffffu, a, off);
            c += __shfl_xor_sync(0xffffffffu, c, off);
        }
        if (lane == 0) { red[0][0] = a; red[1][0] = c; }
    }
    __syncthreads();
    float mu  = red[0][0] * (1.f / DIM);
    float var = red[1][0] * (1.f / DIM) - mu * mu;
    float rs  = rsqrtf(var + 1e-5f);
    const float4* w4 = reinterpret_cast<const float4*>(w);
    const float4* b4 = reinterpret_cast<const float4*>(b);
    float4 ww = w4[tid], bb = b4[tid];
    float o0 = (v.x - mu) * rs * ww.x + bb.x;
    float o1 = (v.y - mu) * rs * ww.y + bb.y;
    float o2 = (v.z - mu) * rs * ww.z + bb.z;
    float o3 = (v.w - mu) * rs * ww.w + bb.w;
    __half2* hp = reinterpret_cast<__half2*>(xnh + (size_t)row * DIM + tid * 4);
    hp[0] = __floats2half2_rn(o0, o1);
    hp[1] = __floats2half2_rn(o2, o3);
}

// ---------------- causal depthwise conv (k=4) + SiLU ------------------------
__global__ void conv_silu_kernel(const float* __restrict__ xz,
                                 const float* __restrict__ cw,
                                 const float* __restrict__ cb,
                                 float* __restrict__ u) {
    int idx = blockIdx.x * blockDim.x + threadIdx.x;
    if (idx >= BB * LL * DI) return;
    int e = idx & (DI - 1);
    int l = (idx >> 11) & (LL - 1);
    int b = idx >> 21;
    float acc = cb[e];
    #pragma unroll
    for (int k = 0; k < 4; k++) {
        int ls = l + k - 3;
        if (ls >= 0)
            acc = fmaf(cw[e * 4 + k], xz[((size_t)(b * LL + ls)) * (2 * DI) + e], acc);
    }
    float s = acc / (1.f + __expf(-acc));
    u[(size_t)(b * LL + l) * DI + e] = s;
}

// ---------------- xproj split-K: partial + reduce(+dtr fp16) ----------------
__global__ void xproj_partial(const float* __restrict__ Au, const float* __restrict__ W,
                              float* __restrict__ part) {
    __shared__ float As[32][33];
    __shared__ float Ws[32][97];
    int tid = threadIdx.x;
    int m0 = blockIdx.x * 32;
    int split = blockIdx.y;
    int kbase = split * (DI / NSPLIT);
    int tx = tid & 15, ty = tid >> 4;
    float acc[2][6];
    #pragma unroll
    for (int i = 0; i < 2; i++)
        #pragma unroll
        for (int j = 0; j < 6; j++) acc[i][j] = 0.f;

    for (int k0 = 0; k0 < DI / NSPLIT; k0 += 32) {
        {
            int row = tid >> 3, j = tid & 7;
            float4 v = *reinterpret_cast<const float4*>(&Au[(size_t)(m0 + row) * DI + kbase + k0 + j * 4]);
            As[j*4+0][row] = v.x; As[j*4+1][row] = v.y;
            As[j*4+2][row] = v.z; As[j*4+3][row] = v.w;
        }
        #pragma unroll
        for (int it = 0; it < 3; it++) {
            int i = tid + it * 256;
            int row = i >> 3, j = i & 7;
            float4 v = *reinterpret_cast<const float4*>(&W[(size_t)row * DI + kbase + k0 + j * 4]);
            Ws[j*4+0][row] = v.x; Ws[j*4+1][row] = v.y;
            Ws[j*4+2][row] = v.z; Ws[j*4+3][row] = v.w;
        }
        __syncthreads();
        #pragma unroll
        for (int kk = 0; kk < 32; kk++) {
            float a0 = As[kk][ty * 2 + 0], a1 = As[kk][ty * 2 + 1];
            float w[6];
            #pragma unroll
            for (int j = 0; j < 6; j++) w[j] = Ws[kk][tx * 6 + j];
            #pragma unroll
            for (int j = 0; j < 6; j++) {
                acc[0][j] = fmaf(a0, w[j], acc[0][j]);
                acc[1][j] = fmaf(a1, w[j], acc[1][j]);
            }
        }
        __syncthreads();
    }
    float* dst = part + (size_t)split * MROWS * XPROJ_N;
    #pragma unroll
    for (int i = 0; i < 2; i++)
        #pragma unroll
        for (int j = 0; j < 6; j++)
            dst[(size_t)(m0 + ty * 2 + i) * XPROJ_N + tx * 6 + j] = acc[i][j];
}

// reduce over splits; cols<64 also emit dt_r fp16 (packed ld=64)
__global__ void xproj_reduce(const float* __restrict__ part, float* __restrict__ xdbl,
                             fp16* __restrict__ dtrh) {
    int i = blockIdx.x * blockDim.x + threadIdx.x;   // over MROWS*24 float4s
    const int TOT4 = MROWS * XPROJ_N / 4;
    if (i >= TOT4) return;
    float4 s = reinterpret_cast<const float4*>(part)[i];
    #pragma unroll
    for (int sp = 1; sp < NSPLIT; sp++) {
        float4 v = reinterpret_cast<const float4*>(part + (size_t)sp * MROWS * XPROJ_N)[i];
        s.x += v.x; s.y += v.y; s.z += v.z; s.w += v.w;
    }
    reinterpret_cast<float4*>(xdbl)[i] = s;
    int row = i / 24, c4 = (i % 24) * 4;
    if (c4 < DTRANK) {
        __half2* hp = reinterpret_cast<__half2*>(dtrh + (size_t)row * DTRANK + c4);
        hp[0] = __floats2half2_rn(s.x, s.y);
        hp[1] = __floats2half2_rn(s.z, s.w);
    }
}

// ---------------- SSM selective scan (writes y as fp16) ---------------------
#define CHUNK 64
__global__ void scan_kernel(const float* __restrict__ dt,
                            const float* __restrict__ u,
                            const float* __restrict__ xdbl,
                            const float* __restrict__ xz,
                            const float* __restrict__ a_log,
                            const float* __restrict__ d_skip,
                            fp16* __restrict__ yh) {
    __shared__ float sB [CHUNK][DSTATE];
    __shared__ float sC [CHUNK][DSTATE];
    __shared__ float sDt[CHUNK][16];
    __shared__ float sU [CHUNK][16];
    __shared__ float sZ [CHUNK][16];
    int tid  = threadIdx.x;
    int g    = tid >> 4;
    int lane = tid & 15;
    int c0   = blockIdx.x * 16;
    int b    = c0 >> 11;
    int e0   = c0 & (DI - 1);
    int e    = e0 + g;
    float A_n = -__expf(a_log[e * DSTATE + lane]);
    float dsk = d_skip[e];
    float h = 0.f;
    int rowbase = b * LL;
    for (int l0 = 0; l0 < LL; l0 += CHUNK) {
        __syncthreads();
        for (int i = tid; i < CHUNK * 2 * DSTATE; i += 256) {
            int r = i >> 5, j = i & 31;
            float v = xdbl[(size_t)(rowbase + l0 + r) * XPROJ_N + DTRANK + j];
            if (j < DSTATE) sB[r][j] = v; else sC[r][j - DSTATE] = v;
        }
        for (int i = tid; i < CHUNK * 16; i += 256) {
            int r = i >> 4, j = i & 15;
            size_t m = (size_t)(rowbase + l0 + r);
            sDt[r][j] = dt[m * DI + e0 + j];
            sU [r][j] = u [m * DI + e0 + j];
            sZ [r][j] = xz[m * (2 * DI) + DI + e0 + j];
        }
        __syncthreads();
        #pragma unroll 4
        for (int r = 0; r < CHUNK; r++) {
            float dtv = sDt[r][g];
            float uv  = sU [r][g];
            float dA  = __expf(dtv * A_n);
            float dBu = dtv * sB[r][lane] * uv;
            h = fmaf(dA, h, dBu);
            float yv = h * sC[r][lane];
            yv += __shfl_xor_sync(0xffffffffu, yv, 8);
            yv += __shfl_xor_sync(0xffffffffu, yv, 4);
            yv += __shfl_xor_sync(0xffffffffu, yv, 2);
            yv += __shfl_xor_sync(0xffffffffu, yv, 1);
            if (lane == 0) {
                float zv = sZ[r][g];
                float sz = zv / (1.f + __expf(-zv));
                float yo = (yv + uv * dsk) * sz;
                yh[(size_t)(rowbase + l0 + r) * DI + e] = __float2half_rn(yo);
            }
        }
    }
}

// ---------------- launch -----------------------------------------------------
extern "C" void kernel_launch(void* const* d_in, const int* in_sizes, int n_in,
                              void* d_out, int out_size) {
    const float* x      = (const float*)d_in[0];
    const float* ln_w   = (const float*)d_in[1];
    const float* ln_b   = (const float*)d_in[2];
    const float* w_in   = (const float*)d_in[3];
    const float* conv_w = (const float*)d_in[4];
    const float* conv_b = (const float*)d_in[5];
    const float* w_xpr  = (const float*)d_in[6];
    const float* w_dt   = (const float*)d_in[7];
    const float* b_dt   = (const float*)d_in[8];
    const float* a_log  = (const float*)d_in[9];
    const float* d_skip = (const float*)d_in[10];
    const float* w_out  = (const float*)d_in[11];
    float* out = (float*)d_out;

    float *xz, *u, *xdbl, *dt, *part;
    fp16 *xnh, *winh, *yh, *woh, *dtrh, *wdth;
    cudaGetSymbolAddress((void**)&xz,   g_xz);
    cudaGetSymbolAddress((void**)&u,    g_u);
    cudaGetSymbolAddress((void**)&xdbl, g_xdbl);
    cudaGetSymbolAddress((void**)&dt,   g_dt);
    cudaGetSymbolAddress((void**)&part, g_part);
    cudaGetSymbolAddress((void**)&xnh,  g_xnh);
    cudaGetSymbolAddress((void**)&winh, g_winh);
    cudaGetSymbolAddress((void**)&yh,   g_yh);
    cudaGetSymbolAddress((void**)&woh,  g_woh);
    cudaGetSymbolAddress((void**)&dtrh, g_dtrh);
    cudaGetSymbolAddress((void**)&wdth, g_wdth);

    const int SMEM128 = 3 * 16384;   // BN=128: 48 KB, 3-stage ring
    const int SMEM64  = 3 * 12288;   // BN=64:  36 KB, 3-stage ring
    cudaFuncSetAttribute((const void*)gemm_f16<0,128>, cudaFuncAttributeMaxDynamicSharedMemorySize, SMEM128);
    cudaFuncSetAttribute((const void*)gemm_f16<1,128>, cudaFuncAttributeMaxDynamicSharedMemorySize, SMEM128);
    cudaFuncSetAttribute((const void*)gemm_f16<2,64>,  cudaFuncAttributeMaxDynamicSharedMemorySize, SMEM64);

    const int NCVT = (2*DI*DIM + DIM*DI + DI*DTRANK) / 4;
    // 1. all weight conversions (one launch)
    cvt_all<<<(NCVT + 255)/256, 256>>>(w_in, w_out, w_dt, winh, woh, wdth);
    // 2. LayerNorm (fp16 output)
    ln_kernel<<<MROWS, 256>>>(x, ln_w, ln_b, xnh);
    // 3. xz = xn @ w_in^T   (2048 x 4096 x 1024)  [fp16 mma, BN=128]
    gemm_f16<0,128><<<dim3(4096/128, MROWS/128), 256, SMEM128>>>(
        xnh, winh, xz, nullptr, DIM, 2*DI);
    // 4. u = silu(conv(xs))  [streaming, coalesced]
    conv_silu_kernel<<<(BB*LL*DI)/256, 256>>>(xz, conv_w, conv_b, u);
    // 5. x_dbl partial = u @ w_xproj^T  [split-K fp32]
    xproj_partial<<<dim3(MROWS/32, NSPLIT), 256>>>(u, w_xpr, part);
    // 6. reduce + dt_r fp16 extract
    xproj_reduce<<<(MROWS*XPROJ_N/4 + 255)/256, 256>>>(part, xdbl, dtrh);
    // 7. dt = softplus(dt_r @ w_dt^T + b_dt)  (2048 x 2048 x 64)  [BN=128]
    gemm_f16<1,128><<<dim3(DI/128, MROWS/128), 256, SMEM128>>>(
        dtrh, wdth, dt, b_dt, DTRANK, DI);
    // 8. selective scan (+ skip + gate, fp16 output)
    scan_kernel<<<(BB*DI)/16, 256>>>(dt, u, xdbl, xz, a_log, d_skip, yh);
    // 9. out = residual + y @ w_out^T  (2048 x 1024 x 2048)  [BN=64, 256 CTAs]
    gemm_f16<2,64><<<dim3(DIM/64, MROWS/128), 256, SMEM64>>>(
        yh, woh, out, x, DI, DIM);
}

// round 11
// speedup vs baseline: 1.2990x; 1.2022x over previous
#include <cuda_runtime.h>
#include <cuda_fp16.h>
#include <math.h>
#include <stdint.h>

// Problem shapes (fixed by the reference)
#define BB      2
#define LL      1024
#define DIM     1024
#define DI      2048          // d_inner
#define MROWS   (BB*LL)       // 2048
#define DTRANK  64
#define DSTATE  16
#define XPROJ_N (DTRANK + 2*DSTATE)  // 96
#define NSPLIT  16

typedef __half fp16;

// ---------------- scratch (device globals; no allocation allowed) ----------
__device__ float g_xz  [MROWS * 2 * DI];
__device__ float g_u   [MROWS * DI];
__device__ float g_xdbl[MROWS * XPROJ_N];
__device__ float g_dt  [MROWS * DI];
__device__ float g_part[NSPLIT * MROWS * XPROJ_N];

__device__ fp16 g_xnh [MROWS * DIM];
__device__ fp16 g_winh[2*DI * DIM];
__device__ fp16 g_yh  [MROWS * DI];
__device__ fp16 g_woh [DIM * DI];
__device__ fp16 g_dtrh[MROWS * DTRANK];
__device__ fp16 g_wdth[DI * DTRANK];

// =================== baseline PTX helpers (no arch-'a' features) ============
__device__ __forceinline__ uint32_t smem_u32(const void* p) {
    uint32_t a;
    asm("{ .reg .u64 t; cvta.to.shared.u64 t, %1; cvt.u32.u64 %0, t; }" : "=r"(a) : "l"(p));
    return a;
}
#define CP_ASYNC16(dst, src) \
    asm volatile("cp.async.cg.shared.global [%0], [%1], 16;" :: "r"(dst), "l"(src))
#define CP_COMMIT() asm volatile("cp.async.commit_group;" ::: "memory")
#define CP_WAIT(n)  asm volatile("cp.async.wait_group %0;" :: "n"(n) : "memory")

__device__ __forceinline__ void ldsm4(uint32_t* r, uint32_t addr) {
    asm volatile("ldmatrix.sync.aligned.m8n8.x4.shared.b16 {%0,%1,%2,%3}, [%4];"
                 : "=r"(r[0]), "=r"(r[1]), "=r"(r[2]), "=r"(r[3]) : "r"(addr));
}
__device__ __forceinline__ void mma_fp16(float* c, const uint32_t* a, const uint32_t* b) {
    asm volatile("mma.sync.aligned.m16n8k16.row.col.f32.f16.f16.f32 "
                 "{%0,%1,%2,%3}, {%4,%5,%6,%7}, {%8,%9}, {%0,%1,%2,%3};"
                 : "+f"(c[0]), "+f"(c[1]), "+f"(c[2]), "+f"(c[3])
                 : "r"(a[0]), "r"(a[1]), "r"(a[2]), "r"(a[3]), "r"(b[0]), "r"(b[1]));
}
// SW64 swizzle for 64-byte stage rows (verified conflict-free for ldsm phases)
__device__ __forceinline__ uint32_t sw64(uint32_t off) { return off ^ ((off >> 3) & 0x30); }

// =================== fp16 mma.sync GEMM: C = A @ B^T ========================
// Pure fp16 A and B. BM=128, BN in {128,64}, BK=32/stage, 3-stage cp.async
// ring, 8 warps, 2 CTAs/SM. All ldsm of a k16-slice hoisted before MMAs.
// EPI: 0 none, 1 softplus+bias, 2 +resid
template<int EPI, int BN>
__global__ void __launch_bounds__(256, 2)
gemm_f16(const fp16* __restrict__ Ah, const fp16* __restrict__ Bh,
         float* __restrict__ C, const float* __restrict__ aux,
         int K, int ldc) {
    extern __shared__ char smem[];
    const uint32_t sb = smem_u32(smem);
    constexpr int ABY = 128 * 64;            // bytes for A per stage
    constexpr int BBY = BN * 64;             // bytes for B per stage
    constexpr int STG = ABY + BBY;           // stage size
    constexpr int MT  = (BN == 128) ? 4 : 2; // m16 tiles per warp
    const int tid = threadIdx.x, wid = tid >> 5, lane = tid & 31;
    const int m0 = blockIdx.y * 128, n0 = blockIdx.x * BN;
    const int wm = (BN == 128) ? (wid >> 2) : (wid >> 1);
    const int wn = (BN == 128) ? (wid & 3)  : (wid & 1);

    float acc[MT][4][4];
    #pragma unroll
    for (int a = 0; a < MT; a++)
        #pragma unroll
        for (int b = 0; b < 4; b++)
            #pragma unroll
            for (int c = 0; c < 4; c++) acc[a][b][c] = 0.f;

    // stage s: [Ah | Bh], 64B SW64 rows of 32 fp16
    auto load_stage = [&](int s, int kc) {
        uint32_t base = sb + s * STG;
        #pragma unroll
        for (int it = 0; it < 2; it++) {          // A: 128 rows
            int i = tid + it * 256;
            int row = i >> 2, j = i & 3;
            uint32_t so = sw64(row * 64 + j * 16);
            CP_ASYNC16(base + so,
                       Ah + (size_t)(m0 + row) * K + kc * 32 + j * 8);
        }
        #pragma unroll
        for (int it = 0; it < BN / 64; it++) {    // B: BN rows
            int i = tid + it * 256;
            int row = i >> 2, j = i & 3;
            uint32_t so = sw64(row * 64 + j * 16);
            CP_ASYNC16(base + ABY + so,
                       Bh + (size_t)(n0 + row) * K + kc * 32 + j * 8);
        }
        CP_COMMIT();
    };

    auto compute = [&](int s) {
        uint32_t pAh = sb + s * STG;
        uint32_t pBh = pAh + ABY;
        #pragma unroll
        for (int kk = 0; kk < 2; kk++) {
            uint32_t bh[2][4], ah[MT][4];
            int grp = lane >> 3, l8 = lane & 7;
            int kbB = kk * 32 + ((grp & 1) << 4);
            #pragma unroll
            for (int pr = 0; pr < 2; pr++) {
                int row = wn * 32 + pr * 16 + ((grp >> 1) << 3) + l8;
                ldsm4(bh[pr], pBh + sw64(row * 64 + kbB));
            }
            int kbA = kk * 32 + ((lane >> 4) << 4);
            #pragma unroll
            for (int mt = 0; mt < MT; mt++) {
                int row = wm * (MT * 16) + mt * 16 + (lane & 15);
                ldsm4(ah[mt], pAh + sw64(row * 64 + kbA));
            }
            #pragma unroll
            for (int mt = 0; mt < MT; mt++)
                #pragma unroll
                for (int pr = 0; pr < 2; pr++)
                    #pragma unroll
                    for (int half = 0; half < 2; half++)
                        mma_fp16(acc[mt][pr * 2 + half], ah[mt], &bh[pr][half * 2]);
        }
    };

    const int nst = K >> 5;
    load_stage(0, 0);
    if (nst > 1) load_stage(1, 1);
    int slot = 0;
    for (int kc = 0; kc < nst; kc++) {
        if (kc + 1 < nst) CP_WAIT(1); else CP_WAIT(0);
        __syncthreads();                       // stage kc ready, prev compute done
        if (kc + 2 < nst) load_stage((kc + 2) % 3, kc + 2);
        compute(slot);
        slot = (slot + 1 == 3) ? 0 : slot + 1;
    }

    // epilogue: write fp32 directly from fragments
    #pragma unroll
    for (int mt = 0; mt < MT; mt++) {
        #pragma unroll
        for (int nt = 0; nt < 4; nt++) {
            int row = m0 + wm * (MT * 16) + mt * 16 + (lane >> 2);
            int col = n0 + wn * 32 + nt * 8 + (lane & 3) * 2;
            float v[4] = {acc[mt][nt][0], acc[mt][nt][1], acc[mt][nt][2], acc[mt][nt][3]};
            if (EPI == 1) {
                #pragma unroll
                for (int i = 0; i < 4; i++) {
                    float t = v[i] + aux[col + (i & 1)];
                    v[i] = fmaxf(t, 0.f) + log1pf(__expf(-fabsf(t)));
                }
            } else if (EPI == 2) {
                v[0] += aux[(size_t)row * ldc + col];
                v[1] += aux[(size_t)row * ldc + col + 1];
                v[2] += aux[(size_t)(row + 8) * ldc + col];
                v[3] += aux[(size_t)(row + 8) * ldc + col + 1];
            }
            *reinterpret_cast<float2*>(&C[(size_t)row * ldc + col])       = make_float2(v[0], v[1]);
            *reinterpret_cast<float2*>(&C[(size_t)(row + 8) * ldc + col]) = make_float2(v[2], v[3]);
        }
    }
}

// ---------------- merged weight conversion (w_in | w_out | w_dt) ------------
__global__ void cvt_all(const float* __restrict__ w_in, const float* __restrict__ w_out,
                        const float* __restrict__ w_dt,
                        fp16* __restrict__ winh, fp16* __restrict__ woh,
                        fp16* __restrict__ wdth) {
    const int N1 = 2*DI*DIM/4, N2 = DIM*DI/4, N3 = DI*DTRANK/4;
    int i = blockIdx.x * blockDim.x + threadIdx.x;
    const float* s; fp16* d; int k;
    if (i < N1)            { s = w_in;  d = winh; k = i; }
    else if (i < N1 + N2)  { s = w_out; d = woh;  k = i - N1; }
    else if (i < N1+N2+N3) { s = w_dt;  d = wdth; k = i - N1 - N2; }
    else return;
    float4 v = reinterpret_cast<const float4*>(s)[k];
    __half2* hp = reinterpret_cast<__half2*>(d);
    hp[k*2]   = __floats2half2_rn(v.x, v.y);
    hp[k*2+1] = __floats2half2_rn(v.z, v.w);
}

// ---------------- LayerNorm (fp16 output) -----------------------------------
__global__ void ln_kernel(const float* __restrict__ x,
                          const float* __restrict__ w,
                          const float* __restrict__ b,
                          fp16* __restrict__ xnh) {
    int row = blockIdx.x;
    int tid = threadIdx.x;
    const float4* xr = reinterpret_cast<const float4*>(x + row * DIM);
    float4 v = xr[tid];
    float s  = v.x + v.y + v.z + v.w;
    float sq = v.x*v.x + v.y*v.y + v.z*v.z + v.w*v.w;
    __shared__ float red[2][8];
    for (int off = 16; off > 0; off >>= 1) {
        s  += __shfl_xor_sync(0xffffffffu, s,  off);
        sq += __shfl_xor_sync(0xffffffffu, sq, off);
    }
    int warp = tid >> 5, lane = tid & 31;
    if (lane == 0) { red[0][warp] = s; red[1][warp] = sq; }
    __syncthreads();
    if (warp == 0) {
        float a = (lane < 8) ? red[0][lane] : 0.f;
        float c = (lane < 8) ? red[1][lane] : 0.f;
        for (int off = 4; off > 0; off >>= 1) {
            a += __shfl_xor_sync(0xffffffffu, a, off);
            c += __shfl_xor_sync(0xffffffffu, c, off);
        }
        if (lane == 0) { red[0][0] = a; red[1][0] = c; }
    }
    __syncthreads();
    float mu  = red[0][0] * (1.f / DIM);
    float var = red[1][0] * (1.f / DIM) - mu * mu;
    float rs  = rsqrtf(var + 1e-5f);
    const float4* w4 = reinterpret_cast<const float4*>(w);
    const float4* b4 = reinterpret_cast<const float4*>(b);
    float4 ww = w4[tid], bb = b4[tid];
    float o0 = (v.x - mu) * rs * ww.x + bb.x;
    float o1 = (v.y - mu) * rs * ww.y + bb.y;
    float o2 = (v.z - mu) * rs * ww.z + bb.z;
    float o3 = (v.w - mu) * rs * ww.w + bb.w;
    __half2* hp = reinterpret_cast<__half2*>(xnh + (size_t)row * DIM + tid * 4);
    hp[0] = __floats2half2_rn(o0, o1);
    hp[1] = __floats2half2_rn(o2, o3);
}

// ---------------- causal depthwise conv (k=4) + SiLU, float4 along e --------
__global__ void conv_silu_kernel(const float* __restrict__ xz,
                                 const float* __restrict__ cw,
                                 const float* __restrict__ cb,
                                 float* __restrict__ u) {
    int i = blockIdx.x * blockDim.x + threadIdx.x;   // over BB*LL*DI/4
    if (i >= BB * LL * DI / 4) return;
    int eg  = i & (DI / 4 - 1);      // e-group (4 consecutive channels)
    int row = i >> 9;                // b*LL + l
    int l   = row & (LL - 1);
    int e0  = eg * 4;

    float4 cbv = reinterpret_cast<const float4*>(cb)[eg];
    float a[4] = {cbv.x, cbv.y, cbv.z, cbv.w};
    float4 w[4];
    #pragma unroll
    for (int ee = 0; ee < 4; ee++) w[ee] = reinterpret_cast<const float4*>(cw)[e0 + ee];

    #pragma unroll
    for (int k = 0; k < 4; k++) {
        if (l + k - 3 >= 0) {
            float4 xv = *reinterpret_cast<const float4*>(
                xz + (size_t)(row + k - 3) * (2 * DI) + e0);
            const float* xp = reinterpret_cast<const float*>(&xv);
            #pragma unroll
            for (int ee = 0; ee < 4; ee++) {
                const float* wp = reinterpret_cast<const float*>(&w[ee]);
                a[ee] = fmaf(wp[k], xp[ee], a[ee]);
            }
        }
    }
    float4 o;
    o.x = a[0] / (1.f + __expf(-a[0]));
    o.y = a[1] / (1.f + __expf(-a[1]));
    o.z = a[2] / (1.f + __expf(-a[2]));
    o.w = a[3] / (1.f + __expf(-a[3]));
    reinterpret_cast<float4*>(u + (size_t)row * DI + e0)[0] = o;
}

// ---------------- xproj split-K: partial + reduce(+dtr fp16) ----------------
__global__ void xproj_partial(const float* __restrict__ Au, const float* __restrict__ W,
                              float* __restrict__ part) {
    __shared__ float As[32][33];
    __shared__ float Ws[32][97];
    int tid = threadIdx.x;
    int m0 = blockIdx.x * 32;
    int split = blockIdx.y;
    int kbase = split * (DI / NSPLIT);
    int tx = tid & 15, ty = tid >> 4;
    float acc[2][6];
    #pragma unroll
    for (int i = 0; i < 2; i++)
        #pragma unroll
        for (int j = 0; j < 6; j++) acc[i][j] = 0.f;

    for (int k0 = 0; k0 < DI / NSPLIT; k0 += 32) {
        {
            int row = tid >> 3, j = tid & 7;
            float4 v = *reinterpret_cast<const float4*>(&Au[(size_t)(m0 + row) * DI + kbase + k0 + j * 4]);
            As[j*4+0][row] = v.x; As[j*4+1][row] = v.y;
            As[j*4+2][row] = v.z; As[j*4+3][row] = v.w;
        }
        #pragma unroll
        for (int it = 0; it < 3; it++) {
            int i = tid + it * 256;
            int row = i >> 3, j = i & 7;
            float4 v = *reinterpret_cast<const float4*>(&W[(size_t)row * DI + kbase + k0 + j * 4]);
            Ws[j*4+0][row] = v.x; Ws[j*4+1][row] = v.y;
            Ws[j*4+2][row] = v.z; Ws[j*4+3][row] = v.w;
        }
        __syncthreads();
        #pragma unroll
        for (int kk = 0; kk < 32; kk++) {
            float a0 = As[kk][ty * 2 + 0], a1 = As[kk][ty * 2 + 1];
            float w[6];
            #pragma unroll
            for (int j = 0; j < 6; j++) w[j] = Ws[kk][tx * 6 + j];
            #pragma unroll
            for (int j = 0; j < 6; j++) {
                acc[0][j] = fmaf(a0, w[j], acc[0][j]);
                acc[1][j] = fmaf(a1, w[j], acc[1][j]);
            }
        }
        __syncthreads();
    }
    float* dst = part + (size_t)split * MROWS * XPROJ_N;
    #pragma unroll
    for (int i = 0; i < 2; i++)
        #pragma unroll
        for (int j = 0; j < 6; j++)
            dst[(size_t)(m0 + ty * 2 + i) * XPROJ_N + tx * 6 + j] = acc[i][j];
}

// reduce over splits; cols<64 also emit dt_r fp16 (packed ld=64)
__global__ void xproj_reduce(const float* __restrict__ part, float* __restrict__ xdbl,
                             fp16* __restrict__ dtrh) {
    int i = blockIdx.x * blockDim.x + threadIdx.x;   // over MROWS*24 float4s
    const int TOT4 = MROWS * XPROJ_N / 4;
    if (i >= TOT4) return;
    float4 s = reinterpret_cast<const float4*>(part)[i];
    #pragma unroll
    for (int sp = 1; sp < NSPLIT; sp++) {
        float4 v = reinterpret_cast<const float4*>(part + (size_t)sp * MROWS * XPROJ_N)[i];
        s.x += v.x; s.y += v.y; s.z += v.z; s.w += v.w;
    }
    reinterpret_cast<float4*>(xdbl)[i] = s;
    int row = i / 24, c4 = (i % 24) * 4;
    if (c4 < DTRANK) {
        __half2* hp = reinterpret_cast<__half2*>(dtrh + (size_t)row * DTRANK + c4);
        hp[0] = __floats2half2_rn(s.x, s.y);
        hp[1] = __floats2half2_rn(s.z, s.w);
    }
}

// ---------------- SSM selective scan (4-way batched reductions) -------------
#define CHUNK 64
__global__ void scan_kernel(const float* __restrict__ dt,
                            const float* __restrict__ u,
                            const float* __restrict__ xdbl,
                            const float* __restrict__ xz,
                            const float* __restrict__ a_log,
                            const float* __restrict__ d_skip,
                            fp16* __restrict__ yh) {
    __shared__ float sB [CHUNK][DSTATE];
    __shared__ float sC [CHUNK][DSTATE];
    __shared__ float sDt[CHUNK][16];
    __shared__ float sU [CHUNK][16];
    __shared__ float sZ [CHUNK][16];
    int tid  = threadIdx.x;
    int g    = tid >> 4;
    int lane = tid & 15;
    int c0   = blockIdx.x * 16;
    int b    = c0 >> 11;
    int e0   = c0 & (DI - 1);
    int e    = e0 + g;
    float A_n = -__expf(a_log[e * DSTATE + lane]);
    float dsk = d_skip[e];
    float h = 0.f;
    int rowbase = b * LL;
    for (int l0 = 0; l0 < LL; l0 += CHUNK) {
        __syncthreads();
        for (int i = tid; i < CHUNK * 2 * DSTATE; i += 256) {
            int r = i >> 5, j = i & 31;
            float v = xdbl[(size_t)(rowbase + l0 + r) * XPROJ_N + DTRANK + j];
            if (j < DSTATE) sB[r][j] = v; else sC[r][j - DSTATE] = v;
        }
        for (int i = tid; i < CHUNK * 16; i += 256) {
            int r = i >> 4, j = i & 15;
            size_t m = (size_t)(rowbase + l0 + r);
            sDt[r][j] = dt[m * DI + e0 + j];
            sU [r][j] = u [m * DI + e0 + j];
            sZ [r][j] = xz[m * (2 * DI) + DI + e0 + j];
        }
        __syncthreads();
        #pragma unroll
        for (int rg = 0; rg < CHUNK; rg += 4) {
            float yv[4];
            #pragma unroll
            for (int q = 0; q < 4; q++) {          // serial h chain (4-cyc fma)
                int r = rg + q;
                float dtv = sDt[r][g];
                float uv  = sU [r][g];
                float dA  = __expf(dtv * A_n);
                float dBu = dtv * sB[r][lane] * uv;
                h = fmaf(dA, h, dBu);
                yv[q] = h * sC[r][lane];
            }
            #pragma unroll
            for (int off = 8; off > 0; off >>= 1)  // 4 trees interleaved (ILP)
                #pragma unroll
                for (int q = 0; q < 4; q++)
                    yv[q] += __shfl_xor_sync(0xffffffffu, yv[q], off);
            if (lane == 0) {
                #pragma unroll
                for (int q = 0; q < 4; q++) {
                    int r = rg + q;
                    float zv = sZ[r][g];
                    float sz = zv / (1.f + __expf(-zv));
                    float uv = sU[r][g];
                    float yo = (yv[q] + uv * dsk) * sz;
                    yh[(size_t)(rowbase + l0 + r) * DI + e] = __float2half_rn(yo);
                }
            }
        }
    }
}

// ---------------- launch -----------------------------------------------------
extern "C" void kernel_launch(void* const* d_in, const int* in_sizes, int n_in,
                              void* d_out, int out_size) {
    const float* x      = (const float*)d_in[0];
    const float* ln_w   = (const float*)d_in[1];
    const float* ln_b   = (const float*)d_in[2];
    const float* w_in   = (const float*)d_in[3];
    const float* conv_w = (const float*)d_in[4];
    const float* conv_b = (const float*)d_in[5];
    const float* w_xpr  = (const float*)d_in[6];
    const float* w_dt   = (const float*)d_in[7];
    const float* b_dt   = (const float*)d_in[8];
    const float* a_log  = (const float*)d_in[9];
    const float* d_skip = (const float*)d_in[10];
    const float* w_out  = (const float*)d_in[11];
    float* out = (float*)d_out;

    float *xz, *u, *xdbl, *dt, *part;
    fp16 *xnh, *winh, *yh, *woh, *dtrh, *wdth;
    cudaGetSymbolAddress((void**)&xz,   g_xz);
    cudaGetSymbolAddress((void**)&u,    g_u);
    cudaGetSymbolAddress((void**)&xdbl, g_xdbl);
    cudaGetSymbolAddress((void**)&dt,   g_dt);
    cudaGetSymbolAddress((void**)&part, g_part);
    cudaGetSymbolAddress((void**)&xnh,  g_xnh);
    cudaGetSymbolAddress((void**)&winh, g_winh);
    cudaGetSymbolAddress((void**)&yh,   g_yh);
    cudaGetSymbolAddress((void**)&woh,  g_woh);
    cudaGetSymbolAddress((void**)&dtrh, g_dtrh);
    cudaGetSymbolAddress((void**)&wdth, g_wdth);

    const int SMEM128 = 3 * 16384;   // BN=128: 48 KB, 3-stage ring
    const int SMEM64  = 3 * 12288;   // BN=64:  36 KB, 3-stage ring
    cudaFuncSetAttribute((const void*)gemm_f16<0,128>, cudaFuncAttributeMaxDynamicSharedMemorySize, SMEM128);
    cudaFuncSetAttribute((const void*)gemm_f16<1,128>, cudaFuncAttributeMaxDynamicSharedMemorySize, SMEM128);
    cudaFuncSetAttribute((const void*)gemm_f16<2,64>,  cudaFuncAttributeMaxDynamicSharedMemorySize, SMEM64);

    const int NCVT = (2*DI*DIM + DIM*DI + DI*DTRANK) / 4;
    // 1. all weight conversions (one launch)
    cvt_all<<<(NCVT + 255)/256, 256>>>(w_in, w_out, w_dt, winh, woh, wdth);
    // 2. LayerNorm (fp16 output)
    ln_kernel<<<MROWS, 256>>>(x, ln_w, ln_b, xnh);
    // 3. xz = xn @ w_in^T   (2048 x 4096 x 1024)  [fp16 mma, BN=128]
    gemm_f16<0,128><<<dim3(4096/128, MROWS/128), 256, SMEM128>>>(
        xnh, winh, xz, nullptr, DIM, 2*DI);
    // 4. u = silu(conv(xs))  [streaming, float4 along e]  <-- profiled slot
    conv_silu_kernel<<<(BB*LL*DI/4 + 255)/256, 256>>>(xz, conv_w, conv_b, u);
    // 5. x_dbl partial = u @ w_xproj^T  [split-K fp32, NSPLIT=16]
    xproj_partial<<<dim3(MROWS/32, NSPLIT), 256>>>(u, w_xpr, part);
    // 6. reduce + dt_r fp16 extract
    xproj_reduce<<<(MROWS*XPROJ_N/4 + 255)/256, 256>>>(part, xdbl, dtrh);
    // 7. dt = softplus(dt_r @ w_dt^T + b_dt)  (2048 x 2048 x 64)  [BN=128]
    gemm_f16<1,128><<<dim3(DI/128, MROWS/128), 256, SMEM128>>>(
        dtrh, wdth, dt, b_dt, DTRANK, DI);
    // 8. selective scan (+ skip + gate, fp16 output, batched reductions)
    scan_kernel<<<(BB*DI)/16, 256>>>(dt, u, xdbl, xz, a_log, d_skip, yh);
    // 9. out = residual + y @ w_out^T  (2048 x 1024 x 2048)  [BN=64, 256 CTAs]
    gemm_f16<2,64><<<dim3(DIM/64, MROWS/128), 256, SMEM64>>>(
        yh, woh, out, x, DI, DIM);
}

// round 12
// speedup vs baseline: 1.4008x; 1.0784x over previous
#include <cuda_runtime.h>
#include <cuda_fp16.h>
#include <math.h>
#include <stdint.h>

// Problem shapes (fixed by the reference)
#define BB      2
#define LL      1024
#define DIM     1024
#define DI      2048          // d_inner
#define MROWS   (BB*LL)       // 2048
#define DTRANK  64
#define DSTATE  16
#define XPROJ_N (DTRANK + 2*DSTATE)  // 96
#define NSPLIT  16

typedef __half fp16;

// ---------------- scratch (device globals; no allocation allowed) ----------
__device__ float g_xz  [MROWS * 2 * DI];
__device__ float g_u   [MROWS * DI];
__device__ float g_xdbl[MROWS * XPROJ_N];
__device__ float g_dt  [MROWS * DI];
__device__ float g_part[NSPLIT * MROWS * XPROJ_N];

__device__ fp16 g_xnh [MROWS * DIM];
__device__ fp16 g_winh[2*DI * DIM];
__device__ fp16 g_yh  [MROWS * DI];
__device__ fp16 g_woh [DIM * DI];
__device__ fp16 g_dtrh[MROWS * DTRANK];
__device__ fp16 g_wdth[DI * DTRANK];

// =================== baseline PTX helpers (no arch-'a' features) ============
__device__ __forceinline__ uint32_t smem_u32(const void* p) {
    uint32_t a;
    asm("{ .reg .u64 t; cvta.to.shared.u64 t, %1; cvt.u32.u64 %0, t; }" : "=r"(a) : "l"(p));
    return a;
}
#define CP_ASYNC16(dst, src) \
    asm volatile("cp.async.cg.shared.global [%0], [%1], 16;" :: "r"(dst), "l"(src))
#define CP_COMMIT() asm volatile("cp.async.commit_group;" ::: "memory")
#define CP_WAIT(n)  asm volatile("cp.async.wait_group %0;" :: "n"(n) : "memory")

__device__ __forceinline__ void ldsm4(uint32_t* r, uint32_t addr) {
    asm volatile("ldmatrix.sync.aligned.m8n8.x4.shared.b16 {%0,%1,%2,%3}, [%4];"
                 : "=r"(r[0]), "=r"(r[1]), "=r"(r[2]), "=r"(r[3]) : "r"(addr));
}
__device__ __forceinline__ void mma_fp16(float* c, const uint32_t* a, const uint32_t* b) {
    asm volatile("mma.sync.aligned.m16n8k16.row.col.f32.f16.f16.f32 "
                 "{%0,%1,%2,%3}, {%4,%5,%6,%7}, {%8,%9}, {%0,%1,%2,%3};"
                 : "+f"(c[0]), "+f"(c[1]), "+f"(c[2]), "+f"(c[3])
                 : "r"(a[0]), "r"(a[1]), "r"(a[2]), "r"(a[3]), "r"(b[0]), "r"(b[1]));
}
// SW64 swizzle for 64-byte stage rows (verified conflict-free for ldsm phases)
__device__ __forceinline__ uint32_t sw64(uint32_t off) { return off ^ ((off >> 3) & 0x30); }

// =================== fp16 mma.sync GEMM: C = A @ B^T ========================
// Pure fp16 A and B. BM=128, BN in {128,64}, BK=32/stage, 3-stage cp.async
// ring, 8 warps, 2 CTAs/SM. All ldsm of a k16-slice hoisted before MMAs.
// EPI: 0 none, 1 softplus+bias, 2 +resid
template<int EPI, int BN>
__global__ void __launch_bounds__(256, 2)
gemm_f16(const fp16* __restrict__ Ah, const fp16* __restrict__ Bh,
         float* __restrict__ C, const float* __restrict__ aux,
         int K, int ldc) {
    extern __shared__ char smem[];
    const uint32_t sb = smem_u32(smem);
    constexpr int ABY = 128 * 64;            // bytes for A per stage
    constexpr int BBY = BN * 64;             // bytes for B per stage
    constexpr int STG = ABY + BBY;           // stage size
    constexpr int MT  = (BN == 128) ? 4 : 2; // m16 tiles per warp
    const int tid = threadIdx.x, wid = tid >> 5, lane = tid & 31;
    const int m0 = blockIdx.y * 128, n0 = blockIdx.x * BN;
    const int wm = (BN == 128) ? (wid >> 2) : (wid >> 1);
    const int wn = (BN == 128) ? (wid & 3)  : (wid & 1);

    float acc[MT][4][4];
    #pragma unroll
    for (int a = 0; a < MT; a++)
        #pragma unroll
        for (int b = 0; b < 4; b++)
            #pragma unroll
            for (int c = 0; c < 4; c++) acc[a][b][c] = 0.f;

    // stage s: [Ah | Bh], 64B SW64 rows of 32 fp16
    auto load_stage = [&](int s, int kc) {
        uint32_t base = sb + s * STG;
        #pragma unroll
        for (int it = 0; it < 2; it++) {          // A: 128 rows
            int i = tid + it * 256;
            int row = i >> 2, j = i & 3;
            uint32_t so = sw64(row * 64 + j * 16);
            CP_ASYNC16(base + so,
                       Ah + (size_t)(m0 + row) * K + kc * 32 + j * 8);
        }
        #pragma unroll
        for (int it = 0; it < BN / 64; it++) {    // B: BN rows
            int i = tid + it * 256;
            int row = i >> 2, j = i & 3;
            uint32_t so = sw64(row * 64 + j * 16);
            CP_ASYNC16(base + ABY + so,
                       Bh + (size_t)(n0 + row) * K + kc * 32 + j * 8);
        }
        CP_COMMIT();
    };

    auto compute = [&](int s) {
        uint32_t pAh = sb + s * STG;
        uint32_t pBh = pAh + ABY;
        #pragma unroll
        for (int kk = 0; kk < 2; kk++) {
            uint32_t bh[2][4], ah[MT][4];
            int grp = lane >> 3, l8 = lane & 7;
            int kbB = kk * 32 + ((grp & 1) << 4);
            #pragma unroll
            for (int pr = 0; pr < 2; pr++) {
                int row = wn * 32 + pr * 16 + ((grp >> 1) << 3) + l8;
                ldsm4(bh[pr], pBh + sw64(row * 64 + kbB));
            }
            int kbA = kk * 32 + ((lane >> 4) << 4);
            #pragma unroll
            for (int mt = 0; mt < MT; mt++) {
                int row = wm * (MT * 16) + mt * 16 + (lane & 15);
                ldsm4(ah[mt], pAh + sw64(row * 64 + kbA));
            }
            #pragma unroll
            for (int mt = 0; mt < MT; mt++)
                #pragma unroll
                for (int pr = 0; pr < 2; pr++)
                    #pragma unroll
                    for (int half = 0; half < 2; half++)
                        mma_fp16(acc[mt][pr * 2 + half], ah[mt], &bh[pr][half * 2]);
        }
    };

    const int nst = K >> 5;
    load_stage(0, 0);
    if (nst > 1) load_stage(1, 1);
    int slot = 0;
    for (int kc = 0; kc < nst; kc++) {
        if (kc + 1 < nst) CP_WAIT(1); else CP_WAIT(0);
        __syncthreads();                       // stage kc ready, prev compute done
        if (kc + 2 < nst) load_stage((kc + 2) % 3, kc + 2);
        compute(slot);
        slot = (slot + 1 == 3) ? 0 : slot + 1;
    }

    // epilogue: write fp32 directly from fragments
    #pragma unroll
    for (int mt = 0; mt < MT; mt++) {
        #pragma unroll
        for (int nt = 0; nt < 4; nt++) {
            int row = m0 + wm * (MT * 16) + mt * 16 + (lane >> 2);
            int col = n0 + wn * 32 + nt * 8 + (lane & 3) * 2;
            float v[4] = {acc[mt][nt][0], acc[mt][nt][1], acc[mt][nt][2], acc[mt][nt][3]};
            if (EPI == 1) {
                #pragma unroll
                for (int i = 0; i < 4; i++) {
                    float t = v[i] + aux[col + (i & 1)];
                    v[i] = fmaxf(t, 0.f) + log1pf(__expf(-fabsf(t)));
                }
            } else if (EPI == 2) {
                v[0] += aux[(size_t)row * ldc + col];
                v[1] += aux[(size_t)row * ldc + col + 1];
                v[2] += aux[(size_t)(row + 8) * ldc + col];
                v[3] += aux[(size_t)(row + 8) * ldc + col + 1];
            }
            *reinterpret_cast<float2*>(&C[(size_t)row * ldc + col])       = make_float2(v[0], v[1]);
            *reinterpret_cast<float2*>(&C[(size_t)(row + 8) * ldc + col]) = make_float2(v[2], v[3]);
        }
    }
}

// ---------------- merged weight conversion (w_in | w_out | w_dt) ------------
__global__ void cvt_all(const float* __restrict__ w_in, const float* __restrict__ w_out,
                        const float* __restrict__ w_dt,
                        fp16* __restrict__ winh, fp16* __restrict__ woh,
                        fp16* __restrict__ wdth) {
    const int N1 = 2*DI*DIM/4, N2 = DIM*DI/4, N3 = DI*DTRANK/4;
    int i = blockIdx.x * blockDim.x + threadIdx.x;
    const float* s; fp16* d; int k;
    if (i < N1)            { s = w_in;  d = winh; k = i; }
    else if (i < N1 + N2)  { s = w_out; d = woh;  k = i - N1; }
    else if (i < N1+N2+N3) { s = w_dt;  d = wdth; k = i - N1 - N2; }
    else return;
    float4 v = reinterpret_cast<const float4*>(s)[k];
    __half2* hp = reinterpret_cast<__half2*>(d);
    hp[k*2]   = __floats2half2_rn(v.x, v.y);
    hp[k*2+1] = __floats2half2_rn(v.z, v.w);
}

// ---------------- LayerNorm (fp16 output) -----------------------------------
__global__ void ln_kernel(const float* __restrict__ x,
                          const float* __restrict__ w,
                          const float* __restrict__ b,
                          fp16* __restrict__ xnh) {
    int row = blockIdx.x;
    int tid = threadIdx.x;
    const float4* xr = reinterpret_cast<const float4*>(x + row * DIM);
    float4 v = xr[tid];
    float s  = v.x + v.y + v.z + v.w;
    float sq = v.x*v.x + v.y*v.y + v.z*v.z + v.w*v.w;
    __shared__ float red[2][8];
    for (int off = 16; off > 0; off >>= 1) {
        s  += __shfl_xor_sync(0xffffffffu, s,  off);
        sq += __shfl_xor_sync(0xffffffffu, sq, off);
    }
    int warp = tid >> 5, lane = tid & 31;
    if (lane == 0) { red[0][warp] = s; red[1][warp] = sq; }
    __syncthreads();
    if (warp == 0) {
        float a = (lane < 8) ? red[0][lane] : 0.f;
        float c = (lane < 8) ? red[1][lane] : 0.f;
        for (int off = 4; off > 0; off >>= 1) {
            a += __shfl_xor_sync(0xffffffffu, a, off);
            c += __shfl_xor_sync(0xffffffffu, c, off);
        }
        if (lane == 0) { red[0][0] = a; red[1][0] = c; }
    }
    __syncthreads();
    float mu  = red[0][0] * (1.f / DIM);
    float var = red[1][0] * (1.f / DIM) - mu * mu;
    float rs  = rsqrtf(var + 1e-5f);
    const float4* w4 = reinterpret_cast<const float4*>(w);
    const float4* b4 = reinterpret_cast<const float4*>(b);
    float4 ww = w4[tid], bb = b4[tid];
    float o0 = (v.x - mu) * rs * ww.x + bb.x;
    float o1 = (v.y - mu) * rs * ww.y + bb.y;
    float o2 = (v.z - mu) * rs * ww.z + bb.z;
    float o3 = (v.w - mu) * rs * ww.w + bb.w;
    __half2* hp = reinterpret_cast<__half2*>(xnh + (size_t)row * DIM + tid * 4);
    hp[0] = __floats2half2_rn(o0, o1);
    hp[1] = __floats2half2_rn(o2, o3);
}

// ---------------- causal depthwise conv (k=4) + SiLU (scalar, streaming) ----
__global__ void conv_silu_kernel(const float* __restrict__ xz,
                                 const float* __restrict__ cw,
                                 const float* __restrict__ cb,
                                 float* __restrict__ u) {
    int idx = blockIdx.x * blockDim.x + threadIdx.x;
    if (idx >= BB * LL * DI) return;
    int e = idx & (DI - 1);
    int l = (idx >> 11) & (LL - 1);
    int b = idx >> 21;
    float acc = cb[e];
    #pragma unroll
    for (int k = 0; k < 4; k++) {
        int ls = l + k - 3;
        if (ls >= 0)
            acc = fmaf(cw[e * 4 + k], xz[((size_t)(b * LL + ls)) * (2 * DI) + e], acc);
    }
    float s = acc / (1.f + __expf(-acc));
    u[(size_t)(b * LL + l) * DI + e] = s;
}

// ---------------- xproj split-K: partial + reduce(+dtr fp16) ----------------
__global__ void xproj_partial(const float* __restrict__ Au, const float* __restrict__ W,
                              float* __restrict__ part) {
    __shared__ float As[32][33];
    __shared__ float Ws[32][97];
    int tid = threadIdx.x;
    int m0 = blockIdx.x * 32;
    int split = blockIdx.y;
    int kbase = split * (DI / NSPLIT);
    int tx = tid & 15, ty = tid >> 4;
    float acc[2][6];
    #pragma unroll
    for (int i = 0; i < 2; i++)
        #pragma unroll
        for (int j = 0; j < 6; j++) acc[i][j] = 0.f;

    for (int k0 = 0; k0 < DI / NSPLIT; k0 += 32) {
        {
            int row = tid >> 3, j = tid & 7;
            float4 v = *reinterpret_cast<const float4*>(&Au[(size_t)(m0 + row) * DI + kbase + k0 + j * 4]);
            As[j*4+0][row] = v.x; As[j*4+1][row] = v.y;
            As[j*4+2][row] = v.z; As[j*4+3][row] = v.w;
        }
        #pragma unroll
        for (int it = 0; it < 3; it++) {
            int i = tid + it * 256;
            int row = i >> 3, j = i & 7;
            float4 v = *reinterpret_cast<const float4*>(&W[(size_t)row * DI + kbase + k0 + j * 4]);
            Ws[j*4+0][row] = v.x; Ws[j*4+1][row] = v.y;
            Ws[j*4+2][row] = v.z; Ws[j*4+3][row] = v.w;
        }
        __syncthreads();
        #pragma unroll
        for (int kk = 0; kk < 32; kk++) {
            float a0 = As[kk][ty * 2 + 0], a1 = As[kk][ty * 2 + 1];
            float w[6];
            #pragma unroll
            for (int j = 0; j < 6; j++) w[j] = Ws[kk][tx * 6 + j];
            #pragma unroll
            for (int j = 0; j < 6; j++) {
                acc[0][j] = fmaf(a0, w[j], acc[0][j]);
                acc[1][j] = fmaf(a1, w[j], acc[1][j]);
            }
        }
        __syncthreads();
    }
    float* dst = part + (size_t)split * MROWS * XPROJ_N;
    #pragma unroll
    for (int i = 0; i < 2; i++)
        #pragma unroll
        for (int j = 0; j < 6; j++)
            dst[(size_t)(m0 + ty * 2 + i) * XPROJ_N + tx * 6 + j] = acc[i][j];
}

// reduce over splits; cols<64 also emit dt_r fp16 (packed ld=64)
__global__ void xproj_reduce(const float* __restrict__ part, float* __restrict__ xdbl,
                             fp16* __restrict__ dtrh) {
    int i = blockIdx.x * blockDim.x + threadIdx.x;   // over MROWS*24 float4s
    const int TOT4 = MROWS * XPROJ_N / 4;
    if (i >= TOT4) return;
    float4 s = reinterpret_cast<const float4*>(part)[i];
    #pragma unroll
    for (int sp = 1; sp < NSPLIT; sp++) {
        float4 v = reinterpret_cast<const float4*>(part + (size_t)sp * MROWS * XPROJ_N)[i];
        s.x += v.x; s.y += v.y; s.z += v.z; s.w += v.w;
    }
    reinterpret_cast<float4*>(xdbl)[i] = s;
    int row = i / 24, c4 = (i % 24) * 4;
    if (c4 < DTRANK) {
        __half2* hp = reinterpret_cast<__half2*>(dtrh + (size_t)row * DTRANK + c4);
        hp[0] = __floats2half2_rn(s.x, s.y);
        hp[1] = __floats2half2_rn(s.z, s.w);
    }
}

// ---------------- SSM selective scan (8-way batched reductions) -------------
#define CHUNK 64
__global__ void scan_kernel(const float* __restrict__ dt,
                            const float* __restrict__ u,
                            const float* __restrict__ xdbl,
                            const float* __restrict__ xz,
                            const float* __restrict__ a_log,
                            const float* __restrict__ d_skip,
                            fp16* __restrict__ yh) {
    __shared__ float sB [CHUNK][DSTATE];
    __shared__ float sC [CHUNK][DSTATE];
    __shared__ float sDt[CHUNK][16];
    __shared__ float sU [CHUNK][16];
    __shared__ float sZ [CHUNK][16];
    int tid  = threadIdx.x;
    int g    = tid >> 4;
    int lane = tid & 15;
    int c0   = blockIdx.x * 16;
    int b    = c0 >> 11;
    int e0   = c0 & (DI - 1);
    int e    = e0 + g;
    float A_n = -__expf(a_log[e * DSTATE + lane]);
    float dsk = d_skip[e];
    float h = 0.f;
    int rowbase = b * LL;
    for (int l0 = 0; l0 < LL; l0 += CHUNK) {
        __syncthreads();
        for (int i = tid; i < CHUNK * 2 * DSTATE; i += 256) {
            int r = i >> 5, j = i & 31;
            float v = xdbl[(size_t)(rowbase + l0 + r) * XPROJ_N + DTRANK + j];
            if (j < DSTATE) sB[r][j] = v; else sC[r][j - DSTATE] = v;
        }
        for (int i = tid; i < CHUNK * 16; i += 256) {
            int r = i >> 4, j = i & 15;
            size_t m = (size_t)(rowbase + l0 + r);
            sDt[r][j] = dt[m * DI + e0 + j];
            sU [r][j] = u [m * DI + e0 + j];
            sZ [r][j] = xz[m * (2 * DI) + DI + e0 + j];
        }
        __syncthreads();
        #pragma unroll
        for (int rg = 0; rg < CHUNK; rg += 8) {
            float yv[8];
            #pragma unroll
            for (int q = 0; q < 8; q++) {          // serial h chain (4-cyc fma)
                int r = rg + q;
                float dtv = sDt[r][g];
                float uv  = sU [r][g];
                float dA  = __expf(dtv * A_n);
                float dBu = dtv * sB[r][lane] * uv;
                h = fmaf(dA, h, dBu);
                yv[q] = h * sC[r][lane];
            }
            #pragma unroll
            for (int off = 8; off > 0; off >>= 1)  // 8 trees interleaved (ILP)
                #pragma unroll
                for (int q = 0; q < 8; q++)
                    yv[q] += __shfl_xor_sync(0xffffffffu, yv[q], off);
            if (lane == 0) {
                #pragma unroll
                for (int q = 0; q < 8; q++) {
                    int r = rg + q;
                    float zv = sZ[r][g];
                    float sz = zv / (1.f + __expf(-zv));
                    float uv = sU[r][g];
                    float yo = (yv[q] + uv * dsk) * sz;
                    yh[(size_t)(rowbase + l0 + r) * DI + e] = __float2half_rn(yo);
                }
            }
        }
    }
}

// ---------------- launch -----------------------------------------------------
extern "C" void kernel_launch(void* const* d_in, const int* in_sizes, int n_in,
                              void* d_out, int out_size) {
    const float* x      = (const float*)d_in[0];
    const float* ln_w   = (const float*)d_in[1];
    const float* ln_b   = (const float*)d_in[2];
    const float* w_in   = (const float*)d_in[3];
    const float* conv_w = (const float*)d_in[4];
    const float* conv_b = (const float*)d_in[5];
    const float* w_xpr  = (const float*)d_in[6];
    const float* w_dt   = (const float*)d_in[7];
    const float* b_dt   = (const float*)d_in[8];
    const float* a_log  = (const float*)d_in[9];
    const float* d_skip = (const float*)d_in[10];
    const float* w_out  = (const float*)d_in[11];
    float* out = (float*)d_out;

    float *xz, *u, *xdbl, *dt, *part;
    fp16 *xnh, *winh, *yh, *woh, *dtrh, *wdth;
    cudaGetSymbolAddress((void**)&xz,   g_xz);
    cudaGetSymbolAddress((void**)&u,    g_u);
    cudaGetSymbolAddress((void**)&xdbl, g_xdbl);
    cudaGetSymbolAddress((void**)&dt,   g_dt);
    cudaGetSymbolAddress((void**)&part, g_part);
    cudaGetSymbolAddress((void**)&xnh,  g_xnh);
    cudaGetSymbolAddress((void**)&winh, g_winh);
    cudaGetSymbolAddress((void**)&yh,   g_yh);
    cudaGetSymbolAddress((void**)&woh,  g_woh);
    cudaGetSymbolAddress((void**)&dtrh, g_dtrh);
    cudaGetSymbolAddress((void**)&wdth, g_wdth);

    const int SMEM128 = 3 * 16384;   // BN=128: 48 KB, 3-stage ring
    const int SMEM64  = 3 * 12288;   // BN=64:  36 KB, 3-stage ring
    cudaFuncSetAttribute((const void*)gemm_f16<0,128>, cudaFuncAttributeMaxDynamicSharedMemorySize, SMEM128);
    cudaFuncSetAttribute((const void*)gemm_f16<1,128>, cudaFuncAttributeMaxDynamicSharedMemorySize, SMEM128);
    cudaFuncSetAttribute((const void*)gemm_f16<2,64>,  cudaFuncAttributeMaxDynamicSharedMemorySize, SMEM64);

    const int NCVT = (2*DI*DIM + DIM*DI + DI*DTRANK) / 4;
    // 1. all weight conversions (one launch)
    cvt_all<<<(NCVT + 255)/256, 256>>>(w_in, w_out, w_dt, winh, woh, wdth);
    // 2. LayerNorm (fp16 output)
    ln_kernel<<<MROWS, 256>>>(x, ln_w, ln_b, xnh);
    // 3. xz = xn @ w_in^T   (2048 x 4096 x 1024)  [fp16 mma, BN=128]
    gemm_f16<0,128><<<dim3(4096/128, MROWS/128), 256, SMEM128>>>(
        xnh, winh, xz, nullptr, DIM, 2*DI);
    // 4. u = silu(conv(xs))  [scalar streaming]  <-- profiled slot
    conv_silu_kernel<<<(BB*LL*DI)/256, 256>>>(xz, conv_w, conv_b, u);
    // 5. x_dbl partial = u @ w_xproj^T  [split-K fp32, NSPLIT=16]
    xproj_partial<<<dim3(MROWS/32, NSPLIT), 256>>>(u, w_xpr, part);
    // 6. reduce + dt_r fp16 extract
    xproj_reduce<<<(MROWS*XPROJ_N/4 + 255)/256, 256>>>(part, xdbl, dtrh);
    // 7. dt = softplus(dt_r @ w_dt^T + b_dt)  (2048 x 2048 x 64)  [BN=128]
    gemm_f16<1,128><<<dim3(DI/128, MROWS/128), 256, SMEM128>>>(
        dtrh, wdth, dt, b_dt, DTRANK, DI);
    // 8. selective scan (+ skip + gate, fp16 output, 8-way batched reductions)
    scan_kernel<<<(BB*DI)/16, 256>>>(dt, u, xdbl, xz, a_log, d_skip, yh);
    // 9. out = residual + y @ w_out^T  (2048 x 1024 x 2048)  [BN=64, 256 CTAs]
    gemm_f16<2,64><<<dim3(DIM/64, MROWS/128), 256, SMEM64>>>(
        yh, woh, out, x, DI, DIM);
}

// round 13
// speedup vs baseline: 1.4213x; 1.0147x over previous
#include <cuda_runtime.h>
#include <cuda_fp16.h>
#include <math.h>
#include <stdint.h>

// Problem shapes (fixed by the reference)
#define BB      2
#define LL      1024
#define DIM     1024
#define DI      2048          // d_inner
#define MROWS   (BB*LL)       // 2048
#define DTRANK  64
#define DSTATE  16
#define XPROJ_N (DTRANK + 2*DSTATE)  // 96
#define NSPLIT  16

typedef __half fp16;

// ---------------- scratch (device globals; no allocation allowed) ----------
__device__ fp16  g_xzh [MROWS * 2 * DI];     // fp16 xz (xs | z)
__device__ float g_u   [MROWS * DI];
__device__ float g_xdbl[MROWS * XPROJ_N];
__device__ float g_dt  [MROWS * DI];
__device__ float g_part[NSPLIT * MROWS * XPROJ_N];

__device__ fp16 g_xnh [MROWS * DIM];
__device__ fp16 g_winh[2*DI * DIM];
__device__ fp16 g_yh  [MROWS * DI];
__device__ fp16 g_woh [DIM * DI];
__device__ fp16 g_dtrh[MROWS * DTRANK];
__device__ fp16 g_wdth[DI * DTRANK];

// =================== baseline PTX helpers (no arch-'a' features) ============
__device__ __forceinline__ uint32_t smem_u32(const void* p) {
    uint32_t a;
    asm("{ .reg .u64 t; cvta.to.shared.u64 t, %1; cvt.u32.u64 %0, t; }" : "=r"(a) : "l"(p));
    return a;
}
#define CP_ASYNC16(dst, src) \
    asm volatile("cp.async.cg.shared.global [%0], [%1], 16;" :: "r"(dst), "l"(src))
#define CP_COMMIT() asm volatile("cp.async.commit_group;" ::: "memory")
#define CP_WAIT(n)  asm volatile("cp.async.wait_group %0;" :: "n"(n) : "memory")

__device__ __forceinline__ void ldsm4(uint32_t* r, uint32_t addr) {
    asm volatile("ldmatrix.sync.aligned.m8n8.x4.shared.b16 {%0,%1,%2,%3}, [%4];"
                 : "=r"(r[0]), "=r"(r[1]), "=r"(r[2]), "=r"(r[3]) : "r"(addr));
}
__device__ __forceinline__ void mma_fp16(float* c, const uint32_t* a, const uint32_t* b) {
    asm volatile("mma.sync.aligned.m16n8k16.row.col.f32.f16.f16.f32 "
                 "{%0,%1,%2,%3}, {%4,%5,%6,%7}, {%8,%9}, {%0,%1,%2,%3};"
                 : "+f"(c[0]), "+f"(c[1]), "+f"(c[2]), "+f"(c[3])
                 : "r"(a[0]), "r"(a[1]), "r"(a[2]), "r"(a[3]), "r"(b[0]), "r"(b[1]));
}
// SW64 swizzle for 64-byte stage rows (verified conflict-free for ldsm phases)
__device__ __forceinline__ uint32_t sw64(uint32_t off) { return off ^ ((off >> 3) & 0x30); }

// =================== fp16 mma.sync GEMM: C = A @ B^T ========================
// Pure fp16 A and B. BM=128, BN in {128,64}, BK=32/stage, 3-stage cp.async
// ring, 8 warps, 2 CTAs/SM. All ldsm of a k16-slice hoisted before MMAs.
// EPI: 0 fp16 store, 1 softplus+bias fp32, 2 +resid fp32
template<int EPI, int BN>
__global__ void __launch_bounds__(256, 2)
gemm_f16(const fp16* __restrict__ Ah, const fp16* __restrict__ Bh,
         void* __restrict__ Cout, const float* __restrict__ aux,
         int K, int ldc) {
    extern __shared__ char smem[];
    const uint32_t sb = smem_u32(smem);
    constexpr int ABY = 128 * 64;            // bytes for A per stage
    constexpr int BBY = BN * 64;             // bytes for B per stage
    constexpr int STG = ABY + BBY;           // stage size
    constexpr int MT  = (BN == 128) ? 4 : 2; // m16 tiles per warp
    const int tid = threadIdx.x, wid = tid >> 5, lane = tid & 31;
    const int m0 = blockIdx.y * 128, n0 = blockIdx.x * BN;
    const int wm = (BN == 128) ? (wid >> 2) : (wid >> 1);
    const int wn = (BN == 128) ? (wid & 3)  : (wid & 1);

    float acc[MT][4][4];
    #pragma unroll
    for (int a = 0; a < MT; a++)
        #pragma unroll
        for (int b = 0; b < 4; b++)
            #pragma unroll
            for (int c = 0; c < 4; c++) acc[a][b][c] = 0.f;

    // stage s: [Ah | Bh], 64B SW64 rows of 32 fp16
    auto load_stage = [&](int s, int kc) {
        uint32_t base = sb + s * STG;
        #pragma unroll
        for (int it = 0; it < 2; it++) {          // A: 128 rows
            int i = tid + it * 256;
            int row = i >> 2, j = i & 3;
            uint32_t so = sw64(row * 64 + j * 16);
            CP_ASYNC16(base + so,
                       Ah + (size_t)(m0 + row) * K + kc * 32 + j * 8);
        }
        #pragma unroll
        for (int it = 0; it < BN / 64; it++) {    // B: BN rows
            int i = tid + it * 256;
            int row = i >> 2, j = i & 3;
            uint32_t so = sw64(row * 64 + j * 16);
            CP_ASYNC16(base + ABY + so,
                       Bh + (size_t)(n0 + row) * K + kc * 32 + j * 8);
        }
        CP_COMMIT();
    };

    auto compute = [&](int s) {
        uint32_t pAh = sb + s * STG;
        uint32_t pBh = pAh + ABY;
        #pragma unroll
        for (int kk = 0; kk < 2; kk++) {
            uint32_t bh[2][4], ah[MT][4];
            int grp = lane >> 3, l8 = lane & 7;
            int kbB = kk * 32 + ((grp & 1) << 4);
            #pragma unroll
            for (int pr = 0; pr < 2; pr++) {
                int row = wn * 32 + pr * 16 + ((grp >> 1) << 3) + l8;
                ldsm4(bh[pr], pBh + sw64(row * 64 + kbB));
            }
            int kbA = kk * 32 + ((lane >> 4) << 4);
            #pragma unroll
            for (int mt = 0; mt < MT; mt++) {
                int row = wm * (MT * 16) + mt * 16 + (lane & 15);
                ldsm4(ah[mt], pAh + sw64(row * 64 + kbA));
            }
            #pragma unroll
            for (int mt = 0; mt < MT; mt++)
                #pragma unroll
                for (int pr = 0; pr < 2; pr++)
                    #pragma unroll
                    for (int half = 0; half < 2; half++)
                        mma_fp16(acc[mt][pr * 2 + half], ah[mt], &bh[pr][half * 2]);
        }
    };

    const int nst = K >> 5;
    load_stage(0, 0);
    if (nst > 1) load_stage(1, 1);
    int slot = 0;
    for (int kc = 0; kc < nst; kc++) {
        if (kc + 1 < nst) CP_WAIT(1); else CP_WAIT(0);
        __syncthreads();                       // stage kc ready, prev compute done
        if (kc + 2 < nst) load_stage((kc + 2) % 3, kc + 2);
        compute(slot);
        slot = (slot + 1 == 3) ? 0 : slot + 1;
    }

    // epilogue
    #pragma unroll
    for (int mt = 0; mt < MT; mt++) {
        #pragma unroll
        for (int nt = 0; nt < 4; nt++) {
            int row = m0 + wm * (MT * 16) + mt * 16 + (lane >> 2);
            int col = n0 + wn * 32 + nt * 8 + (lane & 3) * 2;
            float v[4] = {acc[mt][nt][0], acc[mt][nt][1], acc[mt][nt][2], acc[mt][nt][3]};
            if (EPI == 0) {                    // fp16 store
                fp16* C = (fp16*)Cout;
                *reinterpret_cast<__half2*>(&C[(size_t)row * ldc + col]) =
                    __floats2half2_rn(v[0], v[1]);
                *reinterpret_cast<__half2*>(&C[(size_t)(row + 8) * ldc + col]) =
                    __floats2half2_rn(v[2], v[3]);
            } else {
                float* C = (float*)Cout;
                if (EPI == 1) {
                    #pragma unroll
                    for (int i = 0; i < 4; i++) {
                        float t = v[i] + aux[col + (i & 1)];
                        v[i] = fmaxf(t, 0.f) + log1pf(__expf(-fabsf(t)));
                    }
                } else {
                    v[0] += aux[(size_t)row * ldc + col];
                    v[1] += aux[(size_t)row * ldc + col + 1];
                    v[2] += aux[(size_t)(row + 8) * ldc + col];
                    v[3] += aux[(size_t)(row + 8) * ldc + col + 1];
                }
                *reinterpret_cast<float2*>(&C[(size_t)row * ldc + col])       = make_float2(v[0], v[1]);
                *reinterpret_cast<float2*>(&C[(size_t)(row + 8) * ldc + col]) = make_float2(v[2], v[3]);
            }
        }
    }
}

// ---------------- merged weight conversion (w_in | w_out | w_dt) ------------
__global__ void cvt_all(const float* __restrict__ w_in, const float* __restrict__ w_out,
                        const float* __restrict__ w_dt,
                        fp16* __restrict__ winh, fp16* __restrict__ woh,
                        fp16* __restrict__ wdth) {
    const int N1 = 2*DI*DIM/4, N2 = DIM*DI/4, N3 = DI*DTRANK/4;
    int i = blockIdx.x * blockDim.x + threadIdx.x;
    const float* s; fp16* d; int k;
    if (i < N1)            { s = w_in;  d = winh; k = i; }
    else if (i < N1 + N2)  { s = w_out; d = woh;  k = i - N1; }
    else if (i < N1+N2+N3) { s = w_dt;  d = wdth; k = i - N1 - N2; }
    else return;
    float4 v = reinterpret_cast<const float4*>(s)[k];
    __half2* hp = reinterpret_cast<__half2*>(d);
    hp[k*2]   = __floats2half2_rn(v.x, v.y);
    hp[k*2+1] = __floats2half2_rn(v.z, v.w);
}

// ---------------- LayerNorm (fp16 output) -----------------------------------
__global__ void ln_kernel(const float* __restrict__ x,
                          const float* __restrict__ w,
                          const float* __restrict__ b,
                          fp16* __restrict__ xnh) {
    int row = blockIdx.x;
    int tid = threadIdx.x;
    const float4* xr = reinterpret_cast<const float4*>(x + row * DIM);
    float4 v = xr[tid];
    float s  = v.x + v.y + v.z + v.w;
    float sq = v.x*v.x + v.y*v.y + v.z*v.z + v.w*v.w;
    __shared__ float red[2][8];
    for (int off = 16; off > 0; off >>= 1) {
        s  += __shfl_xor_sync(0xffffffffu, s,  off);
        sq += __shfl_xor_sync(0xffffffffu, sq, off);
    }
    int warp = tid >> 5, lane = tid & 31;
    if (lane == 0) { red[0][warp] = s; red[1][warp] = sq; }
    __syncthreads();
    if (warp == 0) {
        float a = (lane < 8) ? red[0][lane] : 0.f;
        float c = (lane < 8) ? red[1][lane] : 0.f;
        for (int off = 4; off > 0; off >>= 1) {
            a += __shfl_xor_sync(0xffffffffu, a, off);
            c += __shfl_xor_sync(0xffffffffu, c, off);
        }
        if (lane == 0) { red[0][0] = a; red[1][0] = c; }
    }
    __syncthreads();
    float mu  = red[0][0] * (1.f / DIM);
    float var = red[1][0] * (1.f / DIM) - mu * mu;
    float rs  = rsqrtf(var + 1e-5f);
    const float4* w4 = reinterpret_cast<const float4*>(w);
    const float4* b4 = reinterpret_cast<const float4*>(b);
    float4 ww = w4[tid], bb = b4[tid];
    float o0 = (v.x - mu) * rs * ww.x + bb.x;
    float o1 = (v.y - mu) * rs * ww.y + bb.y;
    float o2 = (v.z - mu) * rs * ww.z + bb.z;
    float o3 = (v.w - mu) * rs * ww.w + bb.w;
    __half2* hp = reinterpret_cast<__half2*>(xnh + (size_t)row * DIM + tid * 4);
    hp[0] = __floats2half2_rn(o0, o1);
    hp[1] = __floats2half2_rn(o2, o3);
}

// ---------------- causal depthwise conv (k=4) + SiLU (fp16 in, fp32 out) ----
__global__ void conv_silu_kernel(const fp16* __restrict__ xzh,
                                 const float* __restrict__ cw,
                                 const float* __restrict__ cb,
                                 float* __restrict__ u) {
    int idx = blockIdx.x * blockDim.x + threadIdx.x;
    if (idx >= BB * LL * DI) return;
    int e = idx & (DI - 1);
    int l = (idx >> 11) & (LL - 1);
    int b = idx >> 21;
    float acc = cb[e];
    #pragma unroll
    for (int k = 0; k < 4; k++) {
        int ls = l + k - 3;
        if (ls >= 0)
            acc = fmaf(cw[e * 4 + k],
                       __half2float(xzh[((size_t)(b * LL + ls)) * (2 * DI) + e]), acc);
    }
    float s = acc / (1.f + __expf(-acc));
    u[(size_t)(b * LL + l) * DI + e] = s;
}

// ---------------- xproj split-K: partial + reduce(+dtr fp16) ----------------
__global__ void xproj_partial(const float* __restrict__ Au, const float* __restrict__ W,
                              float* __restrict__ part) {
    __shared__ float As[32][33];
    __shared__ float Ws[32][97];
    int tid = threadIdx.x;
    int m0 = blockIdx.x * 32;
    int split = blockIdx.y;
    int kbase = split * (DI / NSPLIT);
    int tx = tid & 15, ty = tid >> 4;
    float acc[2][6];
    #pragma unroll
    for (int i = 0; i < 2; i++)
        #pragma unroll
        for (int j = 0; j < 6; j++) acc[i][j] = 0.f;

    for (int k0 = 0; k0 < DI / NSPLIT; k0 += 32) {
        {
            int row = tid >> 3, j = tid & 7;
            float4 v = *reinterpret_cast<const float4*>(&Au[(size_t)(m0 + row) * DI + kbase + k0 + j * 4]);
            As[j*4+0][row] = v.x; As[j*4+1][row] = v.y;
            As[j*4+2][row] = v.z; As[j*4+3][row] = v.w;
        }
        #pragma unroll
        for (int it = 0; it < 3; it++) {
            int i = tid + it * 256;
            int row = i >> 3, j = i & 7;
            float4 v = *reinterpret_cast<const float4*>(&W[(size_t)row * DI + kbase + k0 + j * 4]);
            Ws[j*4+0][row] = v.x; Ws[j*4+1][row] = v.y;
            Ws[j*4+2][row] = v.z; Ws[j*4+3][row] = v.w;
        }
        __syncthreads();
        #pragma unroll
        for (int kk = 0; kk < 32; kk++) {
            float a0 = As[kk][ty * 2 + 0], a1 = As[kk][ty * 2 + 1];
            float w[6];
            #pragma unroll
            for (int j = 0; j < 6; j++) w[j] = Ws[kk][tx * 6 + j];
            #pragma unroll
            for (int j = 0; j < 6; j++) {
                acc[0][j] = fmaf(a0, w[j], acc[0][j]);
                acc[1][j] = fmaf(a1, w[j], acc[1][j]);
            }
        }
        __syncthreads();
    }
    float* dst = part + (size_t)split * MROWS * XPROJ_N;
    #pragma unroll
    for (int i = 0; i < 2; i++)
        #pragma unroll
        for (int j = 0; j < 6; j++)
            dst[(size_t)(m0 + ty * 2 + i) * XPROJ_N + tx * 6 + j] = acc[i][j];
}

// reduce over splits; cols<64 also emit dt_r fp16 (packed ld=64)
__global__ void xproj_reduce(const float* __restrict__ part, float* __restrict__ xdbl,
                             fp16* __restrict__ dtrh) {
    int i = blockIdx.x * blockDim.x + threadIdx.x;   // over MROWS*24 float4s
    const int TOT4 = MROWS * XPROJ_N / 4;
    if (i >= TOT4) return;
    float4 s = reinterpret_cast<const float4*>(part)[i];
    #pragma unroll
    for (int sp = 1; sp < NSPLIT; sp++) {
        float4 v = reinterpret_cast<const float4*>(part + (size_t)sp * MROWS * XPROJ_N)[i];
        s.x += v.x; s.y += v.y; s.z += v.z; s.w += v.w;
    }
    reinterpret_cast<float4*>(xdbl)[i] = s;
    int row = i / 24, c4 = (i % 24) * 4;
    if (c4 < DTRANK) {
        __half2* hp = reinterpret_cast<__half2*>(dtrh + (size_t)row * DTRANK + c4);
        hp[0] = __floats2half2_rn(s.x, s.y);
        hp[1] = __floats2half2_rn(s.z, s.w);
    }
}

// ---------------- SSM selective scan (8-way batched reductions) -------------
#define CHUNK 64
__global__ void scan_kernel(const float* __restrict__ dt,
                            const float* __restrict__ u,
                            const float* __restrict__ xdbl,
                            const fp16* __restrict__ xzh,
                            const float* __restrict__ a_log,
                            const float* __restrict__ d_skip,
                            fp16* __restrict__ yh) {
    __shared__ float sB [CHUNK][DSTATE];
    __shared__ float sC [CHUNK][DSTATE];
    __shared__ float sDt[CHUNK][16];
    __shared__ float sU [CHUNK][16];
    __shared__ float sZ [CHUNK][16];
    int tid  = threadIdx.x;
    int g    = tid >> 4;
    int lane = tid & 15;
    int c0   = blockIdx.x * 16;
    int b    = c0 >> 11;
    int e0   = c0 & (DI - 1);
    int e    = e0 + g;
    float A_n = -__expf(a_log[e * DSTATE + lane]);
    float dsk = d_skip[e];
    float h = 0.f;
    int rowbase = b * LL;
    for (int l0 = 0; l0 < LL; l0 += CHUNK) {
        __syncthreads();
        for (int i = tid; i < CHUNK * 2 * DSTATE; i += 256) {
            int r = i >> 5, j = i & 31;
            float v = xdbl[(size_t)(rowbase + l0 + r) * XPROJ_N + DTRANK + j];
            if (j < DSTATE) sB[r][j] = v; else sC[r][j - DSTATE] = v;
        }
        for (int i = tid; i < CHUNK * 16; i += 256) {
            int r = i >> 4, j = i & 15;
            size_t m = (size_t)(rowbase + l0 + r);
            sDt[r][j] = dt[m * DI + e0 + j];
            sU [r][j] = u [m * DI + e0 + j];
            sZ [r][j] = __half2float(xzh[m * (2 * DI) + DI + e0 + j]);
        }
        __syncthreads();
        #pragma unroll
        for (int rg = 0; rg < CHUNK; rg += 8) {
            float yv[8];
            #pragma unroll
            for (int q = 0; q < 8; q++) {          // serial h chain (4-cyc fma)
                int r = rg + q;
                float dtv = sDt[r][g];
                float uv  = sU [r][g];
                float dA  = __expf(dtv * A_n);
                float dBu = dtv * sB[r][lane] * uv;
                h = fmaf(dA, h, dBu);
                yv[q] = h * sC[r][lane];
            }
            #pragma unroll
            for (int off = 8; off > 0; off >>= 1)  // 8 trees interleaved (ILP)
                #pragma unroll
                for (int q = 0; q < 8; q++)
                    yv[q] += __shfl_xor_sync(0xffffffffu, yv[q], off);
            if (lane == 0) {
                #pragma unroll
                for (int q = 0; q < 8; q++) {
                    int r = rg + q;
                    float zv = sZ[r][g];
                    float sz = zv / (1.f + __expf(-zv));
                    float uv = sU[r][g];
                    float yo = (yv[q] + uv * dsk) * sz;
                    yh[(size_t)(rowbase + l0 + r) * DI + e] = __float2half_rn(yo);
                }
            }
        }
    }
}

// ---------------- launch -----------------------------------------------------
extern "C" void kernel_launch(void* const* d_in, const int* in_sizes, int n_in,
                              void* d_out, int out_size) {
    const float* x      = (const float*)d_in[0];
    const float* ln_w   = (const float*)d_in[1];
    const float* ln_b   = (const float*)d_in[2];
    const float* w_in   = (const float*)d_in[3];
    const float* conv_w = (const float*)d_in[4];
    const float* conv_b = (const float*)d_in[5];
    const float* w_xpr  = (const float*)d_in[6];
    const float* w_dt   = (const float*)d_in[7];
    const float* b_dt   = (const float*)d_in[8];
    const float* a_log  = (const float*)d_in[9];
    const float* d_skip = (const float*)d_in[10];
    const float* w_out  = (const float*)d_in[11];
    float* out = (float*)d_out;

    float *u, *xdbl, *dt, *part;
    fp16 *xzh, *xnh, *winh, *yh, *woh, *dtrh, *wdth;
    cudaGetSymbolAddress((void**)&xzh,  g_xzh);
    cudaGetSymbolAddress((void**)&u,    g_u);
    cudaGetSymbolAddress((void**)&xdbl, g_xdbl);
    cudaGetSymbolAddress((void**)&dt,   g_dt);
    cudaGetSymbolAddress((void**)&part, g_part);
    cudaGetSymbolAddress((void**)&xnh,  g_xnh);
    cudaGetSymbolAddress((void**)&winh, g_winh);
    cudaGetSymbolAddress((void**)&yh,   g_yh);
    cudaGetSymbolAddress((void**)&woh,  g_woh);
    cudaGetSymbolAddress((void**)&dtrh, g_dtrh);
    cudaGetSymbolAddress((void**)&wdth, g_wdth);

    const int SMEM128 = 3 * 16384;   // BN=128: 48 KB, 3-stage ring
    const int SMEM64  = 3 * 12288;   // BN=64:  36 KB, 3-stage ring
    cudaFuncSetAttribute((const void*)gemm_f16<0,128>, cudaFuncAttributeMaxDynamicSharedMemorySize, SMEM128);
    cudaFuncSetAttribute((const void*)gemm_f16<1,128>, cudaFuncAttributeMaxDynamicSharedMemorySize, SMEM128);
    cudaFuncSetAttribute((const void*)gemm_f16<2,64>,  cudaFuncAttributeMaxDynamicSharedMemorySize, SMEM64);

    const int NCVT = (2*DI*DIM + DIM*DI + DI*DTRANK) / 4;
    // 1. all weight conversions (one launch)
    cvt_all<<<(NCVT + 255)/256, 256>>>(w_in, w_out, w_dt, winh, woh, wdth);
    // 2. LayerNorm (fp16 output)
    ln_kernel<<<MROWS, 256>>>(x, ln_w, ln_b, xnh);
    // 3. xz = xn @ w_in^T   (2048 x 4096 x 1024)  [fp16 mma, fp16 OUT]
    gemm_f16<0,128><<<dim3(4096/128, MROWS/128), 256, SMEM128>>>(
        xnh, winh, xzh, nullptr, DIM, 2*DI);
    // 4. u = silu(conv(xs))  [fp16 in, fp32 out]  <-- profiled slot
    conv_silu_kernel<<<(BB*LL*DI)/256, 256>>>(xzh, conv_w, conv_b, u);
    // 5. x_dbl partial = u @ w_xproj^T  [split-K fp32, NSPLIT=16]
    xproj_partial<<<dim3(MROWS/32, NSPLIT), 256>>>(u, w_xpr, part);
    // 6. reduce + dt_r fp16 extract
    xproj_reduce<<<(MROWS*XPROJ_N/4 + 255)/256, 256>>>(part, xdbl, dtrh);
    // 7. dt = softplus(dt_r @ w_dt^T + b_dt)  (2048 x 2048 x 64)  [BN=128]
    gemm_f16<1,128><<<dim3(DI/128, MROWS/128), 256, SMEM128>>>(
        dtrh, wdth, dt, b_dt, DTRANK, DI);
    // 8. selective scan (+ skip + gate, fp16 z in / fp16 y out)
    scan_kernel<<<(BB*DI)/16, 256>>>(dt, u, xdbl, xzh, a_log, d_skip, yh);
    // 9. out = residual + y @ w_out^T  (2048 x 1024 x 2048)  [BN=64, 256 CTAs]
    gemm_f16<2,64><<<dim3(DIM/64, MROWS/128), 256, SMEM64>>>(
        yh, woh, out, x, DI, DIM);
}

// round 14
// speedup vs baseline: 1.4370x; 1.0111x over previous
#include <cuda_runtime.h>
#include <cuda_fp16.h>
#include <math.h>
#include <stdint.h>

// Problem shapes (fixed by the reference)
#define BB      2
#define LL      1024
#define DIM     1024
#define DI      2048          // d_inner
#define MROWS   (BB*LL)       // 2048
#define DTRANK  64
#define DSTATE  16
#define XPROJ_N (DTRANK + 2*DSTATE)  // 96
#define NSPLIT  16

typedef __half fp16;

// ---------------- scratch (device globals; no allocation allowed) ----------
__device__ fp16  g_xzh [MROWS * 2 * DI];     // fp16 xz (xs | z)
__device__ fp16  g_uh  [MROWS * DI];         // fp16 u
__device__ float g_xdbl[MROWS * XPROJ_N];
__device__ fp16  g_dth [MROWS * DI];         // fp16 dt
__device__ float g_part[NSPLIT * MROWS * XPROJ_N];

__device__ fp16 g_xnh [MROWS * DIM];
__device__ fp16 g_winh[2*DI * DIM];
__device__ fp16 g_yh  [MROWS * DI];
__device__ fp16 g_woh [DIM * DI];
__device__ fp16 g_dtrh[MROWS * DTRANK];
__device__ fp16 g_wdth[DI * DTRANK];

// =================== baseline PTX helpers (no arch-'a' features) ============
__device__ __forceinline__ uint32_t smem_u32(const void* p) {
    uint32_t a;
    asm("{ .reg .u64 t; cvta.to.shared.u64 t, %1; cvt.u32.u64 %0, t; }" : "=r"(a) : "l"(p));
    return a;
}
#define CP_ASYNC16(dst, src) \
    asm volatile("cp.async.cg.shared.global [%0], [%1], 16;" :: "r"(dst), "l"(src))
#define CP_COMMIT() asm volatile("cp.async.commit_group;" ::: "memory")
#define CP_WAIT(n)  asm volatile("cp.async.wait_group %0;" :: "n"(n) : "memory")

__device__ __forceinline__ void ldsm4(uint32_t* r, uint32_t addr) {
    asm volatile("ldmatrix.sync.aligned.m8n8.x4.shared.b16 {%0,%1,%2,%3}, [%4];"
                 : "=r"(r[0]), "=r"(r[1]), "=r"(r[2]), "=r"(r[3]) : "r"(addr));
}
__device__ __forceinline__ void mma_fp16(float* c, const uint32_t* a, const uint32_t* b) {
    asm volatile("mma.sync.aligned.m16n8k16.row.col.f32.f16.f16.f32 "
                 "{%0,%1,%2,%3}, {%4,%5,%6,%7}, {%8,%9}, {%0,%1,%2,%3};"
                 : "+f"(c[0]), "+f"(c[1]), "+f"(c[2]), "+f"(c[3])
                 : "r"(a[0]), "r"(a[1]), "r"(a[2]), "r"(a[3]), "r"(b[0]), "r"(b[1]));
}
// SW64 swizzle for 64-byte stage rows (verified conflict-free for ldsm phases)
__device__ __forceinline__ uint32_t sw64(uint32_t off) { return off ^ ((off >> 3) & 0x30); }

// =================== fp16 mma.sync GEMM: C = A @ B^T ========================
// Pure fp16 A and B. BM=128, BN in {128,64}, BK=32/stage, 3-stage cp.async
// ring, 8 warps, 2 CTAs/SM. All ldsm of a k16-slice hoisted before MMAs.
// EPI: 0 fp16 store, 1 softplus+bias fp16 store, 2 +resid fp32 store
template<int EPI, int BN>
__global__ void __launch_bounds__(256, 2)
gemm_f16(const fp16* __restrict__ Ah, const fp16* __restrict__ Bh,
         void* __restrict__ Cout, const float* __restrict__ aux,
         int K, int ldc) {
    extern __shared__ char smem[];
    const uint32_t sb = smem_u32(smem);
    constexpr int ABY = 128 * 64;            // bytes for A per stage
    constexpr int BBY = BN * 64;             // bytes for B per stage
    constexpr int STG = ABY + BBY;           // stage size
    constexpr int MT  = (BN == 128) ? 4 : 2; // m16 tiles per warp
    const int tid = threadIdx.x, wid = tid >> 5, lane = tid & 31;
    const int m0 = blockIdx.y * 128, n0 = blockIdx.x * BN;
    const int wm = (BN == 128) ? (wid >> 2) : (wid >> 1);
    const int wn = (BN == 128) ? (wid & 3)  : (wid & 1);

    float acc[MT][4][4];
    #pragma unroll
    for (int a = 0; a < MT; a++)
        #pragma unroll
        for (int b = 0; b < 4; b++)
            #pragma unroll
            for (int c = 0; c < 4; c++) acc[a][b][c] = 0.f;

    // stage s: [Ah | Bh], 64B SW64 rows of 32 fp16
    auto load_stage = [&](int s, int kc) {
        uint32_t base = sb + s * STG;
        #pragma unroll
        for (int it = 0; it < 2; it++) {          // A: 128 rows
            int i = tid + it * 256;
            int row = i >> 2, j = i & 3;
            uint32_t so = sw64(row * 64 + j * 16);
            CP_ASYNC16(base + so,
                       Ah + (size_t)(m0 + row) * K + kc * 32 + j * 8);
        }
        #pragma unroll
        for (int it = 0; it < BN / 64; it++) {    // B: BN rows
            int i = tid + it * 256;
            int row = i >> 2, j = i & 3;
            uint32_t so = sw64(row * 64 + j * 16);
            CP_ASYNC16(base + ABY + so,
                       Bh + (size_t)(n0 + row) * K + kc * 32 + j * 8);
        }
        CP_COMMIT();
    };

    auto compute = [&](int s) {
        uint32_t pAh = sb + s * STG;
        uint32_t pBh = pAh + ABY;
        #pragma unroll
        for (int kk = 0; kk < 2; kk++) {
            uint32_t bh[2][4], ah[MT][4];
            int grp = lane >> 3, l8 = lane & 7;
            int kbB = kk * 32 + ((grp & 1) << 4);
            #pragma unroll
            for (int pr = 0; pr < 2; pr++) {
                int row = wn * 32 + pr * 16 + ((grp >> 1) << 3) + l8;
                ldsm4(bh[pr], pBh + sw64(row * 64 + kbB));
            }
            int kbA = kk * 32 + ((lane >> 4) << 4);
            #pragma unroll
            for (int mt = 0; mt < MT; mt++) {
                int row = wm * (MT * 16) + mt * 16 + (lane & 15);
                ldsm4(ah[mt], pAh + sw64(row * 64 + kbA));
            }
            #pragma unroll
            for (int mt = 0; mt < MT; mt++)
                #pragma unroll
                for (int pr = 0; pr < 2; pr++)
                    #pragma unroll
                    for (int half = 0; half < 2; half++)
                        mma_fp16(acc[mt][pr * 2 + half], ah[mt], &bh[pr][half * 2]);
        }
    };

    const int nst = K >> 5;
    load_stage(0, 0);
    if (nst > 1) load_stage(1, 1);
    int slot = 0;
    for (int kc = 0; kc < nst; kc++) {
        if (kc + 1 < nst) CP_WAIT(1); else CP_WAIT(0);
        __syncthreads();                       // stage kc ready, prev compute done
        if (kc + 2 < nst) load_stage((kc + 2) % 3, kc + 2);
        compute(slot);
        slot = (slot + 1 == 3) ? 0 : slot + 1;
    }

    // epilogue
    #pragma unroll
    for (int mt = 0; mt < MT; mt++) {
        #pragma unroll
        for (int nt = 0; nt < 4; nt++) {
            int row = m0 + wm * (MT * 16) + mt * 16 + (lane >> 2);
            int col = n0 + wn * 32 + nt * 8 + (lane & 3) * 2;
            float v[4] = {acc[mt][nt][0], acc[mt][nt][1], acc[mt][nt][2], acc[mt][nt][3]};
            if (EPI == 0) {                    // plain fp16 store
                fp16* C = (fp16*)Cout;
                *reinterpret_cast<__half2*>(&C[(size_t)row * ldc + col]) =
                    __floats2half2_rn(v[0], v[1]);
                *reinterpret_cast<__half2*>(&C[(size_t)(row + 8) * ldc + col]) =
                    __floats2half2_rn(v[2], v[3]);
            } else if (EPI == 1) {             // softplus + bias, fp16 store
                #pragma unroll
                for (int i = 0; i < 4; i++) {
                    float t = v[i] + aux[col + (i & 1)];
                    v[i] = fmaxf(t, 0.f) + log1pf(__expf(-fabsf(t)));
                }
                fp16* C = (fp16*)Cout;
                *reinterpret_cast<__half2*>(&C[(size_t)row * ldc + col]) =
                    __floats2half2_rn(v[0], v[1]);
                *reinterpret_cast<__half2*>(&C[(size_t)(row + 8) * ldc + col]) =
                    __floats2half2_rn(v[2], v[3]);
            } else {                           // + residual, fp32 store
                float* C = (float*)Cout;
                v[0] += aux[(size_t)row * ldc + col];
                v[1] += aux[(size_t)row * ldc + col + 1];
                v[2] += aux[(size_t)(row + 8) * ldc + col];
                v[3] += aux[(size_t)(row + 8) * ldc + col + 1];
                *reinterpret_cast<float2*>(&C[(size_t)row * ldc + col])       = make_float2(v[0], v[1]);
                *reinterpret_cast<float2*>(&C[(size_t)(row + 8) * ldc + col]) = make_float2(v[2], v[3]);
            }
        }
    }
}

// ---------------- merged weight conversion (w_in | w_out | w_dt) ------------
__global__ void cvt_all(const float* __restrict__ w_in, const float* __restrict__ w_out,
                        const float* __restrict__ w_dt,
                        fp16* __restrict__ winh, fp16* __restrict__ woh,
                        fp16* __restrict__ wdth) {
    const int N1 = 2*DI*DIM/4, N2 = DIM*DI/4, N3 = DI*DTRANK/4;
    int i = blockIdx.x * blockDim.x + threadIdx.x;
    const float* s; fp16* d; int k;
    if (i < N1)            { s = w_in;  d = winh; k = i; }
    else if (i < N1 + N2)  { s = w_out; d = woh;  k = i - N1; }
    else if (i < N1+N2+N3) { s = w_dt;  d = wdth; k = i - N1 - N2; }
    else return;
    float4 v = reinterpret_cast<const float4*>(s)[k];
    __half2* hp = reinterpret_cast<__half2*>(d);
    hp[k*2]   = __floats2half2_rn(v.x, v.y);
    hp[k*2+1] = __floats2half2_rn(v.z, v.w);
}

// ---------------- LayerNorm (fp16 output) -----------------------------------
__global__ void ln_kernel(const float* __restrict__ x,
                          const float* __restrict__ w,
                          const float* __restrict__ b,
                          fp16* __restrict__ xnh) {
    int row = blockIdx.x;
    int tid = threadIdx.x;
    const float4* xr = reinterpret_cast<const float4*>(x + row * DIM);
    float4 v = xr[tid];
    float s  = v.x + v.y + v.z + v.w;
    float sq = v.x*v.x + v.y*v.y + v.z*v.z + v.w*v.w;
    __shared__ float red[2][8];
    for (int off = 16; off > 0; off >>= 1) {
        s  += __shfl_xor_sync(0xffffffffu, s,  off);
        sq += __shfl_xor_sync(0xffffffffu, sq, off);
    }
    int warp = tid >> 5, lane = tid & 31;
    if (lane == 0) { red[0][warp] = s; red[1][warp] = sq; }
    __syncthreads();
    if (warp == 0) {
        float a = (lane < 8) ? red[0][lane] : 0.f;
        float c = (lane < 8) ? red[1][lane] : 0.f;
        for (int off = 4; off > 0; off >>= 1) {
            a += __shfl_xor_sync(0xffffffffu, a, off);
            c += __shfl_xor_sync(0xffffffffu, c, off);
        }
        if (lane == 0) { red[0][0] = a; red[1][0] = c; }
    }
    __syncthreads();
    float mu  = red[0][0] * (1.f / DIM);
    float var = red[1][0] * (1.f / DIM) - mu * mu;
    float rs  = rsqrtf(var + 1e-5f);
    const float4* w4 = reinterpret_cast<const float4*>(w);
    const float4* b4 = reinterpret_cast<const float4*>(b);
    float4 ww = w4[tid], bb = b4[tid];
    float o0 = (v.x - mu) * rs * ww.x + bb.x;
    float o1 = (v.y - mu) * rs * ww.y + bb.y;
    float o2 = (v.z - mu) * rs * ww.z + bb.z;
    float o3 = (v.w - mu) * rs * ww.w + bb.w;
    __half2* hp = reinterpret_cast<__half2*>(xnh + (size_t)row * DIM + tid * 4);
    hp[0] = __floats2half2_rn(o0, o1);
    hp[1] = __floats2half2_rn(o2, o3);
}

// ---------------- causal depthwise conv (k=4) + SiLU (fp16 in/out) ----------
__global__ void conv_silu_kernel(const fp16* __restrict__ xzh,
                                 const float* __restrict__ cw,
                                 const float* __restrict__ cb,
                                 fp16* __restrict__ uh) {
    int idx = blockIdx.x * blockDim.x + threadIdx.x;
    if (idx >= BB * LL * DI) return;
    int e = idx & (DI - 1);
    int l = (idx >> 11) & (LL - 1);
    int b = idx >> 21;
    float acc = cb[e];
    #pragma unroll
    for (int k = 0; k < 4; k++) {
        int ls = l + k - 3;
        if (ls >= 0)
            acc = fmaf(cw[e * 4 + k],
                       __half2float(xzh[((size_t)(b * LL + ls)) * (2 * DI) + e]), acc);
    }
    float s = acc / (1.f + __expf(-acc));
    uh[(size_t)(b * LL + l) * DI + e] = __float2half_rn(s);
}

// ---------------- xproj split-K: partial (fp16 A) + reduce(+dtr fp16) -------
__global__ void xproj_partial(const fp16* __restrict__ Au, const float* __restrict__ W,
                              float* __restrict__ part) {
    __shared__ float As[32][33];
    __shared__ float Ws[32][97];
    int tid = threadIdx.x;
    int m0 = blockIdx.x * 32;
    int split = blockIdx.y;
    int kbase = split * (DI / NSPLIT);
    int tx = tid & 15, ty = tid >> 4;
    float acc[2][6];
    #pragma unroll
    for (int i = 0; i < 2; i++)
        #pragma unroll
        for (int j = 0; j < 6; j++) acc[i][j] = 0.f;

    for (int k0 = 0; k0 < DI / NSPLIT; k0 += 32) {
        {   // A tile 32x32 from fp16 (each thread: 4 halves = 8 bytes)
            int row = tid >> 3, j = tid & 7;
            const __half2* ap = reinterpret_cast<const __half2*>(
                Au + (size_t)(m0 + row) * DI + kbase + k0 + j * 4);
            float2 p0 = __half22float2(ap[0]);
            float2 p1 = __half22float2(ap[1]);
            As[j*4+0][row] = p0.x; As[j*4+1][row] = p0.y;
            As[j*4+2][row] = p1.x; As[j*4+3][row] = p1.y;
        }
        #pragma unroll
        for (int it = 0; it < 3; it++) {
            int i = tid + it * 256;
            int row = i >> 3, j = i & 7;
            float4 v = *reinterpret_cast<const float4*>(&W[(size_t)row * DI + kbase + k0 + j * 4]);
            Ws[j*4+0][row] = v.x; Ws[j*4+1][row] = v.y;
            Ws[j*4+2][row] = v.z; Ws[j*4+3][row] = v.w;
        }
        __syncthreads();
        #pragma unroll
        for (int kk = 0; kk < 32; kk++) {
            float a0 = As[kk][ty * 2 + 0], a1 = As[kk][ty * 2 + 1];
            float w[6];
            #pragma unroll
            for (int j = 0; j < 6; j++) w[j] = Ws[kk][tx * 6 + j];
            #pragma unroll
            for (int j = 0; j < 6; j++) {
                acc[0][j] = fmaf(a0, w[j], acc[0][j]);
                acc[1][j] = fmaf(a1, w[j], acc[1][j]);
            }
        }
        __syncthreads();
    }
    float* dst = part + (size_t)split * MROWS * XPROJ_N;
    #pragma unroll
    for (int i = 0; i < 2; i++)
        #pragma unroll
        for (int j = 0; j < 6; j++)
            dst[(size_t)(m0 + ty * 2 + i) * XPROJ_N + tx * 6 + j] = acc[i][j];
}

// reduce over splits; cols<64 also emit dt_r fp16 (packed ld=64)
__global__ void xproj_reduce(const float* __restrict__ part, float* __restrict__ xdbl,
                             fp16* __restrict__ dtrh) {
    int i = blockIdx.x * blockDim.x + threadIdx.x;   // over MROWS*24 float4s
    const int TOT4 = MROWS * XPROJ_N / 4;
    if (i >= TOT4) return;
    float4 s = reinterpret_cast<const float4*>(part)[i];
    #pragma unroll
    for (int sp = 1; sp < NSPLIT; sp++) {
        float4 v = reinterpret_cast<const float4*>(part + (size_t)sp * MROWS * XPROJ_N)[i];
        s.x += v.x; s.y += v.y; s.z += v.z; s.w += v.w;
    }
    reinterpret_cast<float4*>(xdbl)[i] = s;
    int row = i / 24, c4 = (i % 24) * 4;
    if (c4 < DTRANK) {
        __half2* hp = reinterpret_cast<__half2*>(dtrh + (size_t)row * DTRANK + c4);
        hp[0] = __floats2half2_rn(s.x, s.y);
        hp[1] = __floats2half2_rn(s.z, s.w);
    }
}

// ---------------- SSM selective scan (8-way batched reductions) -------------
#define CHUNK 64
__global__ void scan_kernel(const fp16* __restrict__ dth,
                            const fp16* __restrict__ uh,
                            const float* __restrict__ xdbl,
                            const fp16* __restrict__ xzh,
                            const float* __restrict__ a_log,
                            const float* __restrict__ d_skip,
                            fp16* __restrict__ yh) {
    __shared__ float sB [CHUNK][DSTATE];
    __shared__ float sC [CHUNK][DSTATE];
    __shared__ float sDt[CHUNK][16];
    __shared__ float sU [CHUNK][16];
    __shared__ float sZ [CHUNK][16];
    int tid  = threadIdx.x;
    int g    = tid >> 4;
    int lane = tid & 15;
    int c0   = blockIdx.x * 16;
    int b    = c0 >> 11;
    int e0   = c0 & (DI - 1);
    int e    = e0 + g;
    float A_n = -__expf(a_log[e * DSTATE + lane]);
    float dsk = d_skip[e];
    float h = 0.f;
    int rowbase = b * LL;
    for (int l0 = 0; l0 < LL; l0 += CHUNK) {
        __syncthreads();
        for (int i = tid; i < CHUNK * 2 * DSTATE; i += 256) {
            int r = i >> 5, j = i & 31;
            float v = xdbl[(size_t)(rowbase + l0 + r) * XPROJ_N + DTRANK + j];
            if (j < DSTATE) sB[r][j] = v; else sC[r][j - DSTATE] = v;
        }
        for (int i = tid; i < CHUNK * 16; i += 256) {
            int r = i >> 4, j = i & 15;
            size_t m = (size_t)(rowbase + l0 + r);
            sDt[r][j] = __half2float(dth[m * DI + e0 + j]);
            sU [r][j] = __half2float(uh [m * DI + e0 + j]);
            sZ [r][j] = __half2float(xzh[m * (2 * DI) + DI + e0 + j]);
        }
        __syncthreads();
        #pragma unroll
        for (int rg = 0; rg < CHUNK; rg += 8) {
            float yv[8];
            #pragma unroll
            for (int q = 0; q < 8; q++) {          // serial h chain (4-cyc fma)
                int r = rg + q;
                float dtv = sDt[r][g];
                float uv  = sU [r][g];
                float dA  = __expf(dtv * A_n);
                float dBu = dtv * sB[r][lane] * uv;
                h = fmaf(dA, h, dBu);
                yv[q] = h * sC[r][lane];
            }
            #pragma unroll
            for (int off = 8; off > 0; off >>= 1)  // 8 trees interleaved (ILP)
                #pragma unroll
                for (int q = 0; q < 8; q++)
                    yv[q] += __shfl_xor_sync(0xffffffffu, yv[q], off);
            if (lane == 0) {
                #pragma unroll
                for (int q = 0; q < 8; q++) {
                    int r = rg + q;
                    float zv = sZ[r][g];
                    float sz = zv / (1.f + __expf(-zv));
                    float uv = sU[r][g];
                    float yo = (yv[q] + uv * dsk) * sz;
                    yh[(size_t)(rowbase + l0 + r) * DI + e] = __float2half_rn(yo);
                }
            }
        }
    }
}

// ---------------- launch -----------------------------------------------------
extern "C" void kernel_launch(void* const* d_in, const int* in_sizes, int n_in,
                              void* d_out, int out_size) {
    const float* x      = (const float*)d_in[0];
    const float* ln_w   = (const float*)d_in[1];
    const float* ln_b   = (const float*)d_in[2];
    const float* w_in   = (const float*)d_in[3];
    const float* conv_w = (const float*)d_in[4];
    const float* conv_b = (const float*)d_in[5];
    const float* w_xpr  = (const float*)d_in[6];
    const float* w_dt   = (const float*)d_in[7];
    const float* b_dt   = (const float*)d_in[8];
    const float* a_log  = (const float*)d_in[9];
    const float* d_skip = (const float*)d_in[10];
    const float* w_out  = (const float*)d_in[11];
    float* out = (float*)d_out;

    float *xdbl, *part;
    fp16 *xzh, *uh, *dth, *xnh, *winh, *yh, *woh, *dtrh, *wdth;
    cudaGetSymbolAddress((void**)&xzh,  g_xzh);
    cudaGetSymbolAddress((void**)&uh,   g_uh);
    cudaGetSymbolAddress((void**)&xdbl, g_xdbl);
    cudaGetSymbolAddress((void**)&dth,  g_dth);
    cudaGetSymbolAddress((void**)&part, g_part);
    cudaGetSymbolAddress((void**)&xnh,  g_xnh);
    cudaGetSymbolAddress((void**)&winh, g_winh);
    cudaGetSymbolAddress((void**)&yh,   g_yh);
    cudaGetSymbolAddress((void**)&woh,  g_woh);
    cudaGetSymbolAddress((void**)&dtrh, g_dtrh);
    cudaGetSymbolAddress((void**)&wdth, g_wdth);

    const int SMEM128 = 3 * 16384;   // BN=128: 48 KB, 3-stage ring
    const int SMEM64  = 3 * 12288;   // BN=64:  36 KB, 3-stage ring
    cudaFuncSetAttribute((const void*)gemm_f16<0,128>, cudaFuncAttributeMaxDynamicSharedMemorySize, SMEM128);
    cudaFuncSetAttribute((const void*)gemm_f16<1,128>, cudaFuncAttributeMaxDynamicSharedMemorySize, SMEM128);
    cudaFuncSetAttribute((const void*)gemm_f16<2,64>,  cudaFuncAttributeMaxDynamicSharedMemorySize, SMEM64);

    const int NCVT = (2*DI*DIM + DIM*DI + DI*DTRANK) / 4;
    // 1. all weight conversions (one launch)
    cvt_all<<<(NCVT + 255)/256, 256>>>(w_in, w_out, w_dt, winh, woh, wdth);
    // 2. LayerNorm (fp16 output)
    ln_kernel<<<MROWS, 256>>>(x, ln_w, ln_b, xnh);
    // 3. xz = xn @ w_in^T   (2048 x 4096 x 1024)  [fp16 mma, fp16 OUT]
    gemm_f16<0,128><<<dim3(4096/128, MROWS/128), 256, SMEM128>>>(
        xnh, winh, xzh, nullptr, DIM, 2*DI);
    // 4. u = silu(conv(xs))  [fp16 in/out]  <-- profiled slot
    conv_silu_kernel<<<(BB*LL*DI)/256, 256>>>(xzh, conv_w, conv_b, uh);
    // 5. x_dbl partial = u @ w_xproj^T  [fp16 A, split-K fp32, NSPLIT=16]
    xproj_partial<<<dim3(MROWS/32, NSPLIT), 256>>>(uh, w_xpr, part);
    // 6. reduce + dt_r fp16 extract
    xproj_reduce<<<(MROWS*XPROJ_N/4 + 255)/256, 256>>>(part, xdbl, dtrh);
    // 7. dt = softplus(dt_r @ w_dt^T + b_dt)  [BN=128, fp16 OUT]
    gemm_f16<1,128><<<dim3(DI/128, MROWS/128), 256, SMEM128>>>(
        dtrh, wdth, dth, b_dt, DTRANK, DI);
    // 8. selective scan (fp16 dt/u/z in, fp16 y out)
    scan_kernel<<<(BB*DI)/16, 256>>>(dth, uh, xdbl, xzh, a_log, d_skip, yh);
    // 9. out = residual + y @ w_out^T  (2048 x 1024 x 2048)  [BN=64, 256 CTAs]
    gemm_f16<2,64><<<dim3(DIM/64, MROWS/128), 256, SMEM64>>>(
        yh, woh, out, x, DI, DIM);
}

// round 15
// speedup vs baseline: 1.4751x; 1.0265x over previous
#include <cuda_runtime.h>
#include <cuda_fp16.h>
#include <math.h>
#include <stdint.h>

// Problem shapes (fixed by the reference)
#define BB      2
#define LL      1024
#define DIM     1024
#define DI      2048          // d_inner
#define MROWS   (BB*LL)       // 2048
#define DTRANK  64
#define DSTATE  16
#define XPROJ_N (DTRANK + 2*DSTATE)  // 96
#define NSPLIT  16

typedef __half fp16;

// ---------------- scratch (device globals; no allocation allowed) ----------
__device__ fp16  g_xzh [MROWS * 2 * DI];     // fp16 xz (xs | z)
__device__ fp16  g_uh  [MROWS * DI];         // fp16 u
__device__ float g_xdbl[MROWS * XPROJ_N];
__device__ fp16  g_dth [MROWS * DI];         // fp16 dt
__device__ float g_part[NSPLIT * MROWS * XPROJ_N];

__device__ fp16 g_xnh [MROWS * DIM];
__device__ fp16 g_winh[2*DI * DIM];
__device__ fp16 g_yh  [MROWS * DI];
__device__ fp16 g_woh [DIM * DI];
__device__ fp16 g_dtrh[MROWS * DTRANK];
__device__ fp16 g_wdth[DI * DTRANK];

// =================== baseline PTX helpers (no arch-'a' features) ============
__device__ __forceinline__ uint32_t smem_u32(const void* p) {
    uint32_t a;
    asm("{ .reg .u64 t; cvta.to.shared.u64 t, %1; cvt.u32.u64 %0, t; }" : "=r"(a) : "l"(p));
    return a;
}
#define CP_ASYNC16(dst, src) \
    asm volatile("cp.async.cg.shared.global [%0], [%1], 16;" :: "r"(dst), "l"(src))
#define CP_COMMIT() asm volatile("cp.async.commit_group;" ::: "memory")
#define CP_WAIT(n)  asm volatile("cp.async.wait_group %0;" :: "n"(n) : "memory")

__device__ __forceinline__ void ldsm4(uint32_t* r, uint32_t addr) {
    asm volatile("ldmatrix.sync.aligned.m8n8.x4.shared.b16 {%0,%1,%2,%3}, [%4];"
                 : "=r"(r[0]), "=r"(r[1]), "=r"(r[2]), "=r"(r[3]) : "r"(addr));
}
__device__ __forceinline__ void mma_fp16(float* c, const uint32_t* a, const uint32_t* b) {
    asm volatile("mma.sync.aligned.m16n8k16.row.col.f32.f16.f16.f32 "
                 "{%0,%1,%2,%3}, {%4,%5,%6,%7}, {%8,%9}, {%0,%1,%2,%3};"
                 : "+f"(c[0]), "+f"(c[1]), "+f"(c[2]), "+f"(c[3])
                 : "r"(a[0]), "r"(a[1]), "r"(a[2]), "r"(a[3]), "r"(b[0]), "r"(b[1]));
}
// SW64 swizzle for 64-byte stage rows (verified conflict-free for ldsm phases)
__device__ __forceinline__ uint32_t sw64(uint32_t off) { return off ^ ((off >> 3) & 0x30); }

// =================== fp16 mma.sync GEMM: C = A @ B^T ========================
// Pure fp16 A and B. BM=128, BN in {128,64}, BK=32/stage, 3-stage cp.async
// ring, 8 warps, 2 CTAs/SM. All ldsm of a k16-slice hoisted before MMAs.
// EPI: 0 fp16 store, 1 softplus+bias fp16 store, 2 +resid fp32 store
template<int EPI, int BN>
__global__ void __launch_bounds__(256, 2)
gemm_f16(const fp16* __restrict__ Ah, const fp16* __restrict__ Bh,
         void* __restrict__ Cout, const float* __restrict__ aux,
         int K, int ldc) {
    extern __shared__ char smem[];
    const uint32_t sb = smem_u32(smem);
    constexpr int ABY = 128 * 64;            // bytes for A per stage
    constexpr int BBY = BN * 64;             // bytes for B per stage
    constexpr int STG = ABY + BBY;           // stage size
    constexpr int MT  = (BN == 128) ? 4 : 2; // m16 tiles per warp
    const int tid = threadIdx.x, wid = tid >> 5, lane = tid & 31;
    const int m0 = blockIdx.y * 128, n0 = blockIdx.x * BN;
    const int wm = (BN == 128) ? (wid >> 2) : (wid >> 1);
    const int wn = (BN == 128) ? (wid & 3)  : (wid & 1);

    float acc[MT][4][4];
    #pragma unroll
    for (int a = 0; a < MT; a++)
        #pragma unroll
        for (int b = 0; b < 4; b++)
            #pragma unroll
            for (int c = 0; c < 4; c++) acc[a][b][c] = 0.f;

    // stage s: [Ah | Bh], 64B SW64 rows of 32 fp16
    auto load_stage = [&](int s, int kc) {
        uint32_t base = sb + s * STG;
        #pragma unroll
        for (int it = 0; it < 2; it++) {          // A: 128 rows
            int i = tid + it * 256;
            int row = i >> 2, j = i & 3;
            uint32_t so = sw64(row * 64 + j * 16);
            CP_ASYNC16(base + so,
                       Ah + (size_t)(m0 + row) * K + kc * 32 + j * 8);
        }
        #pragma unroll
        for (int it = 0; it < BN / 64; it++) {    // B: BN rows
            int i = tid + it * 256;
            int row = i >> 2, j = i & 3;
            uint32_t so = sw64(row * 64 + j * 16);
            CP_ASYNC16(base + ABY + so,
                       Bh + (size_t)(n0 + row) * K + kc * 32 + j * 8);
        }
        CP_COMMIT();
    };

    auto compute = [&](int s) {
        uint32_t pAh = sb + s * STG;
        uint32_t pBh = pAh + ABY;
        #pragma unroll
        for (int kk = 0; kk < 2; kk++) {
            uint32_t bh[2][4], ah[MT][4];
            int grp = lane >> 3, l8 = lane & 7;
            int kbB = kk * 32 + ((grp & 1) << 4);
            #pragma unroll
            for (int pr = 0; pr < 2; pr++) {
                int row = wn * 32 + pr * 16 + ((grp >> 1) << 3) + l8;
                ldsm4(bh[pr], pBh + sw64(row * 64 + kbB));
            }
            int kbA = kk * 32 + ((lane >> 4) << 4);
            #pragma unroll
            for (int mt = 0; mt < MT; mt++) {
                int row = wm * (MT * 16) + mt * 16 + (lane & 15);
                ldsm4(ah[mt], pAh + sw64(row * 64 + kbA));
            }
            #pragma unroll
            for (int mt = 0; mt < MT; mt++)
                #pragma unroll
                for (int pr = 0; pr < 2; pr++)
                    #pragma unroll
                    for (int half = 0; half < 2; half++)
                        mma_fp16(acc[mt][pr * 2 + half], ah[mt], &bh[pr][half * 2]);
        }
    };

    const int nst = K >> 5;
    load_stage(0, 0);
    if (nst > 1) load_stage(1, 1);
    int slot = 0;
    for (int kc = 0; kc < nst; kc++) {
        if (kc + 1 < nst) CP_WAIT(1); else CP_WAIT(0);
        __syncthreads();                       // stage kc ready, prev compute done
        if (kc + 2 < nst) load_stage((kc + 2) % 3, kc + 2);
        compute(slot);
        slot = (slot + 1 == 3) ? 0 : slot + 1;
    }

    // epilogue
    #pragma unroll
    for (int mt = 0; mt < MT; mt++) {
        #pragma unroll
        for (int nt = 0; nt < 4; nt++) {
            int row = m0 + wm * (MT * 16) + mt * 16 + (lane >> 2);
            int col = n0 + wn * 32 + nt * 8 + (lane & 3) * 2;
            float v[4] = {acc[mt][nt][0], acc[mt][nt][1], acc[mt][nt][2], acc[mt][nt][3]};
            if (EPI == 0) {                    // plain fp16 store
                fp16* C = (fp16*)Cout;
                *reinterpret_cast<__half2*>(&C[(size_t)row * ldc + col]) =
                    __floats2half2_rn(v[0], v[1]);
                *reinterpret_cast<__half2*>(&C[(size_t)(row + 8) * ldc + col]) =
                    __floats2half2_rn(v[2], v[3]);
            } else if (EPI == 1) {             // softplus + bias, fp16 store
                #pragma unroll
                for (int i = 0; i < 4; i++) {
                    float t = v[i] + aux[col + (i & 1)];
                    v[i] = fmaxf(t, 0.f) + log1pf(__expf(-fabsf(t)));
                }
                fp16* C = (fp16*)Cout;
                *reinterpret_cast<__half2*>(&C[(size_t)row * ldc + col]) =
                    __floats2half2_rn(v[0], v[1]);
                *reinterpret_cast<__half2*>(&C[(size_t)(row + 8) * ldc + col]) =
                    __floats2half2_rn(v[2], v[3]);
            } else {                           // + residual, fp32 store
                float* C = (float*)Cout;
                v[0] += aux[(size_t)row * ldc + col];
                v[1] += aux[(size_t)row * ldc + col + 1];
                v[2] += aux[(size_t)(row + 8) * ldc + col];
                v[3] += aux[(size_t)(row + 8) * ldc + col + 1];
                *reinterpret_cast<float2*>(&C[(size_t)row * ldc + col])       = make_float2(v[0], v[1]);
                *reinterpret_cast<float2*>(&C[(size_t)(row + 8) * ldc + col]) = make_float2(v[2], v[3]);
            }
        }
    }
}

// ---------------- merged cvt_all + LayerNorm (one launch) -------------------
#define N1_CVT (2*DI*DIM/4)
#define N2_CVT (DIM*DI/4)
#define N3_CVT (DI*DTRANK/4)
#define NCVT   (N1_CVT + N2_CVT + N3_CVT)
#define CVTB   ((NCVT + 255) / 256)

__global__ void cvt_ln_kernel(const float* __restrict__ w_in, const float* __restrict__ w_out,
                              const float* __restrict__ w_dt,
                              fp16* __restrict__ winh, fp16* __restrict__ woh,
                              fp16* __restrict__ wdth,
                              const float* __restrict__ x,
                              const float* __restrict__ lw,
                              const float* __restrict__ lb,
                              fp16* __restrict__ xnh) {
    int tid = threadIdx.x;
    if (blockIdx.x < CVTB) {
        int i = blockIdx.x * 256 + tid;
        const float* s; fp16* d; int k;
        if (i < N1_CVT)                { s = w_in;  d = winh; k = i; }
        else if (i < N1_CVT + N2_CVT)  { s = w_out; d = woh;  k = i - N1_CVT; }
        else if (i < NCVT)             { s = w_dt;  d = wdth; k = i - N1_CVT - N2_CVT; }
        else return;
        float4 v = reinterpret_cast<const float4*>(s)[k];
        __half2* hp = reinterpret_cast<__half2*>(d);
        hp[k*2]   = __floats2half2_rn(v.x, v.y);
        hp[k*2+1] = __floats2half2_rn(v.z, v.w);
        return;
    }
    // LayerNorm branch: one block per row
    int row = blockIdx.x - CVTB;
    const float4* xr = reinterpret_cast<const float4*>(x + (size_t)row * DIM);
    float4 v = xr[tid];
    float s  = v.x + v.y + v.z + v.w;
    float sq = v.x*v.x + v.y*v.y + v.z*v.z + v.w*v.w;
    __shared__ float red[2][8];
    for (int off = 16; off > 0; off >>= 1) {
        s  += __shfl_xor_sync(0xffffffffu, s,  off);
        sq += __shfl_xor_sync(0xffffffffu, sq, off);
    }
    int warp = tid >> 5, lane = tid & 31;
    if (lane == 0) { red[0][warp] = s; red[1][warp] = sq; }
    __syncthreads();
    if (warp == 0) {
        float a = (lane < 8) ? red[0][lane] : 0.f;
        float c = (lane < 8) ? red[1][lane] : 0.f;
        for (int off = 4; off > 0; off >>= 1) {
            a += __shfl_xor_sync(0xffffffffu, a, off);
            c += __shfl_xor_sync(0xffffffffu, c, off);
        }
        if (lane == 0) { red[0][0] = a; red[1][0] = c; }
    }
    __syncthreads();
    float mu  = red[0][0] * (1.f / DIM);
    float var = red[1][0] * (1.f / DIM) - mu * mu;
    float rs  = rsqrtf(var + 1e-5f);
    const float4* w4 = reinterpret_cast<const float4*>(lw);
    const float4* b4 = reinterpret_cast<const float4*>(lb);
    float4 ww = w4[tid], bb = b4[tid];
    float o0 = (v.x - mu) * rs * ww.x + bb.x;
    float o1 = (v.y - mu) * rs * ww.y + bb.y;
    float o2 = (v.z - mu) * rs * ww.z + bb.z;
    float o3 = (v.w - mu) * rs * ww.w + bb.w;
    __half2* hp = reinterpret_cast<__half2*>(xnh + (size_t)row * DIM + tid * 4);
    hp[0] = __floats2half2_rn(o0, o1);
    hp[1] = __floats2half2_rn(o2, o3);
}

// ---------------- causal conv (k=4) + SiLU, sliding window (8 l per thread) -
__global__ void conv_silu_kernel(const fp16* __restrict__ xzh,
                                 const float* __restrict__ cw,
                                 const float* __restrict__ cb,
                                 fp16* __restrict__ uh) {
    int idx = blockIdx.x * blockDim.x + threadIdx.x;   // over BB*(LL/8)*DI
    if (idx >= BB * (LL / 8) * DI) return;
    int e  = idx & (DI - 1);
    int lg = idx >> 11;              // group index: 0 .. BB*LL/8-1
    int b  = lg >> 7;                // 128 groups per batch
    int l0 = (lg & 127) * 8;

    float w0 = cw[e*4+0], w1 = cw[e*4+1], w2 = cw[e*4+2], w3 = cw[e*4+3];
    float bias = cb[e];
    size_t base = ((size_t)(b * LL + l0)) * (2 * DI) + e;

    float xv[11];
    #pragma unroll
    for (int t = 0; t < 3; t++) {
        int l = l0 + t - 3;
        xv[t] = (l >= 0) ? __half2float(xzh[base + (ptrdiff_t)(t - 3) * (2 * DI)]) : 0.f;
    }
    #pragma unroll
    for (int t = 0; t < 8; t++)
        xv[t + 3] = __half2float(xzh[base + (size_t)t * (2 * DI)]);

    #pragma unroll
    for (int t = 0; t < 8; t++) {
        float acc = bias;
        acc = fmaf(w0, xv[t],     acc);   // tap k=0 -> row l-3
        acc = fmaf(w1, xv[t + 1], acc);
        acc = fmaf(w2, xv[t + 2], acc);
        acc = fmaf(w3, xv[t + 3], acc);
        float s = acc / (1.f + __expf(-acc));
        uh[(size_t)(b * LL + l0 + t) * DI + e] = __float2half_rn(s);
    }
}

// ---------------- xproj split-K: partial (fp16 A) + reduce(+dtr fp16) -------
__global__ void xproj_partial(const fp16* __restrict__ Au, const float* __restrict__ W,
                              float* __restrict__ part) {
    __shared__ float As[32][33];
    __shared__ float Ws[32][97];
    int tid = threadIdx.x;
    int m0 = blockIdx.x * 32;
    int split = blockIdx.y;
    int kbase = split * (DI / NSPLIT);
    int tx = tid & 15, ty = tid >> 4;
    float acc[2][6];
    #pragma unroll
    for (int i = 0; i < 2; i++)
        #pragma unroll
        for (int j = 0; j < 6; j++) acc[i][j] = 0.f;

    for (int k0 = 0; k0 < DI / NSPLIT; k0 += 32) {
        {   // A tile 32x32 from fp16
            int row = tid >> 3, j = tid & 7;
            const __half2* ap = reinterpret_cast<const __half2*>(
                Au + (size_t)(m0 + row) * DI + kbase + k0 + j * 4);
            float2 p0 = __half22float2(ap[0]);
            float2 p1 = __half22float2(ap[1]);
            As[j*4+0][row] = p0.x; As[j*4+1][row] = p0.y;
            As[j*4+2][row] = p1.x; As[j*4+3][row] = p1.y;
        }
        #pragma unroll
        for (int it = 0; it < 3; it++) {
            int i = tid + it * 256;
            int row = i >> 3, j = i & 7;
            float4 v = *reinterpret_cast<const float4*>(&W[(size_t)row * DI + kbase + k0 + j * 4]);
            Ws[j*4+0][row] = v.x; Ws[j*4+1][row] = v.y;
            Ws[j*4+2][row] = v.z; Ws[j*4+3][row] = v.w;
        }
        __syncthreads();
        #pragma unroll
        for (int kk = 0; kk < 32; kk++) {
            float a0 = As[kk][ty * 2 + 0], a1 = As[kk][ty * 2 + 1];
            float w[6];
            #pragma unroll
            for (int j = 0; j < 6; j++) w[j] = Ws[kk][tx * 6 + j];
            #pragma unroll
            for (int j = 0; j < 6; j++) {
                acc[0][j] = fmaf(a0, w[j], acc[0][j]);
                acc[1][j] = fmaf(a1, w[j], acc[1][j]);
            }
        }
        __syncthreads();
    }
    float* dst = part + (size_t)split * MROWS * XPROJ_N;
    #pragma unroll
    for (int i = 0; i < 2; i++)
        #pragma unroll
        for (int j = 0; j < 6; j++)
            dst[(size_t)(m0 + ty * 2 + i) * XPROJ_N + tx * 6 + j] = acc[i][j];
}

// reduce over splits; cols<64 also emit dt_r fp16 (packed ld=64)
__global__ void xproj_reduce(const float* __restrict__ part, float* __restrict__ xdbl,
                             fp16* __restrict__ dtrh) {
    int i = blockIdx.x * blockDim.x + threadIdx.x;   // over MROWS*24 float4s
    const int TOT4 = MROWS * XPROJ_N / 4;
    if (i >= TOT4) return;
    float4 s = reinterpret_cast<const float4*>(part)[i];
    #pragma unroll
    for (int sp = 1; sp < NSPLIT; sp++) {
        float4 v = reinterpret_cast<const float4*>(part + (size_t)sp * MROWS * XPROJ_N)[i];
        s.x += v.x; s.y += v.y; s.z += v.z; s.w += v.w;
    }
    reinterpret_cast<float4*>(xdbl)[i] = s;
    int row = i / 24, c4 = (i % 24) * 4;
    if (c4 < DTRANK) {
        __half2* hp = reinterpret_cast<__half2*>(dtrh + (size_t)row * DTRANK + c4);
        hp[0] = __floats2half2_rn(s.x, s.y);
        hp[1] = __floats2half2_rn(s.z, s.w);
    }
}

// ---------------- SSM selective scan (8-way batched reductions) -------------
#define CHUNK 64
__global__ void scan_kernel(const fp16* __restrict__ dth,
                            const fp16* __restrict__ uh,
                            const float* __restrict__ xdbl,
                            const fp16* __restrict__ xzh,
                            const float* __restrict__ a_log,
                            const float* __restrict__ d_skip,
                            fp16* __restrict__ yh) {
    __shared__ float sB [CHUNK][DSTATE];
    __shared__ float sC [CHUNK][DSTATE];
    __shared__ float sDt[CHUNK][16];
    __shared__ float sU [CHUNK][16];
    __shared__ float sZ [CHUNK][16];
    int tid  = threadIdx.x;
    int g    = tid >> 4;
    int lane = tid & 15;
    int c0   = blockIdx.x * 16;
    int b    = c0 >> 11;
    int e0   = c0 & (DI - 1);
    int e    = e0 + g;
    float A_n = -__expf(a_log[e * DSTATE + lane]);
    float dsk = d_skip[e];
    float h = 0.f;
    int rowbase = b * LL;
    for (int l0 = 0; l0 < LL; l0 += CHUNK) {
        __syncthreads();
        for (int i = tid; i < CHUNK * 2 * DSTATE; i += 256) {
            int r = i >> 5, j = i & 31;
            float v = xdbl[(size_t)(rowbase + l0 + r) * XPROJ_N + DTRANK + j];
            if (j < DSTATE) sB[r][j] = v; else sC[r][j - DSTATE] = v;
        }
        for (int i = tid; i < CHUNK * 16; i += 256) {
            int r = i >> 4, j = i & 15;
            size_t m = (size_t)(rowbase + l0 + r);
            sDt[r][j] = __half2float(dth[m * DI + e0 + j]);
            sU [r][j] = __half2float(uh [m * DI + e0 + j]);
            sZ [r][j] = __half2float(xzh[m * (2 * DI) + DI + e0 + j]);
        }
        __syncthreads();
        #pragma unroll
        for (int rg = 0; rg < CHUNK; rg += 8) {
            float yv[8];
            #pragma unroll
            for (int q = 0; q < 8; q++) {          // serial h chain (4-cyc fma)
                int r = rg + q;
                float dtv = sDt[r][g];
                float uv  = sU [r][g];
                float dA  = __expf(dtv * A_n);
                float dBu = dtv * sB[r][lane] * uv;
                h = fmaf(dA, h, dBu);
                yv[q] = h * sC[r][lane];
            }
            #pragma unroll
            for (int off = 8; off > 0; off >>= 1)  // 8 trees interleaved (ILP)
                #pragma unroll
                for (int q = 0; q < 8; q++)
                    yv[q] += __shfl_xor_sync(0xffffffffu, yv[q], off);
            if (lane == 0) {
                #pragma unroll
                for (int q = 0; q < 8; q++) {
                    int r = rg + q;
                    float zv = sZ[r][g];
                    float sz = zv / (1.f + __expf(-zv));
                    float uv = sU[r][g];
                    float yo = (yv[q] + uv * dsk) * sz;
                    yh[(size_t)(rowbase + l0 + r) * DI + e] = __float2half_rn(yo);
                }
            }
        }
    }
}

// ---------------- launch -----------------------------------------------------
extern "C" void kernel_launch(void* const* d_in, const int* in_sizes, int n_in,
                              void* d_out, int out_size) {
    const float* x      = (const float*)d_in[0];
    const float* ln_w   = (const float*)d_in[1];
    const float* ln_b   = (const float*)d_in[2];
    const float* w_in   = (const float*)d_in[3];
    const float* conv_w = (const float*)d_in[4];
    const float* conv_b = (const float*)d_in[5];
    const float* w_xpr  = (const float*)d_in[6];
    const float* w_dt   = (const float*)d_in[7];
    const float* b_dt   = (const float*)d_in[8];
    const float* a_log  = (const float*)d_in[9];
    const float* d_skip = (const float*)d_in[10];
    const float* w_out  = (const float*)d_in[11];
    float* out = (float*)d_out;

    float *xdbl, *part;
    fp16 *xzh, *uh, *dth, *xnh, *winh, *yh, *woh, *dtrh, *wdth;
    cudaGetSymbolAddress((void**)&xzh,  g_xzh);
    cudaGetSymbolAddress((void**)&uh,   g_uh);
    cudaGetSymbolAddress((void**)&xdbl, g_xdbl);
    cudaGetSymbolAddress((void**)&dth,  g_dth);
    cudaGetSymbolAddress((void**)&part, g_part);
    cudaGetSymbolAddress((void**)&xnh,  g_xnh);
    cudaGetSymbolAddress((void**)&winh, g_winh);
    cudaGetSymbolAddress((void**)&yh,   g_yh);
    cudaGetSymbolAddress((void**)&woh,  g_woh);
    cudaGetSymbolAddress((void**)&dtrh, g_dtrh);
    cudaGetSymbolAddress((void**)&wdth, g_wdth);

    const int SMEM128 = 3 * 16384;   // BN=128: 48 KB, 3-stage ring
    const int SMEM64  = 3 * 12288;   // BN=64:  36 KB, 3-stage ring
    cudaFuncSetAttribute((const void*)gemm_f16<0,128>, cudaFuncAttributeMaxDynamicSharedMemorySize, SMEM128);
    cudaFuncSetAttribute((const void*)gemm_f16<1,128>, cudaFuncAttributeMaxDynamicSharedMemorySize, SMEM128);
    cudaFuncSetAttribute((const void*)gemm_f16<2,64>,  cudaFuncAttributeMaxDynamicSharedMemorySize, SMEM64);

    // 1. weight conversions + LayerNorm (one launch, block-range dispatch)
    cvt_ln_kernel<<<CVTB + MROWS, 256>>>(w_in, w_out, w_dt, winh, woh, wdth,
                                         x, ln_w, ln_b, xnh);
    // 2. xz = xn @ w_in^T   (2048 x 4096 x 1024)  [fp16 mma, fp16 OUT]
    gemm_f16<0,128><<<dim3(4096/128, MROWS/128), 256, SMEM128>>>(
        xnh, winh, xzh, nullptr, DIM, 2*DI);
    // 3. u = silu(conv(xs))  [sliding window, 8 l per thread]
    conv_silu_kernel<<<(BB*(LL/8)*DI + 255)/256, 256>>>(xzh, conv_w, conv_b, uh);
    // 4. x_dbl partial = u @ w_xproj^T  [fp16 A, split-K, NSPLIT=16]  <-- profiled slot
    xproj_partial<<<dim3(MROWS/32, NSPLIT), 256>>>(uh, w_xpr, part);
    // 5. reduce + dt_r fp16 extract
    xproj_reduce<<<(MROWS*XPROJ_N/4 + 255)/256, 256>>>(part, xdbl, dtrh);
    // 6. dt = softplus(dt_r @ w_dt^T + b_dt)  [BN=128, fp16 OUT]
    gemm_f16<1,128><<<dim3(DI/128, MROWS/128), 256, SMEM128>>>(
        dtrh, wdth, dth, b_dt, DTRANK, DI);
    // 7. selective scan (fp16 dt/u/z in, fp16 y out)
    scan_kernel<<<(BB*DI)/16, 256>>>(dth, uh, xdbl, xzh, a_log, d_skip, yh);
    // 8. out = residual + y @ w_out^T  (2048 x 1024 x 2048)  [BN=64, 256 CTAs]
    gemm_f16<2,64><<<dim3(DIM/64, MROWS/128), 256, SMEM64>>>(
        yh, woh, out, x, DI, DIM);
}

// round 16
// speedup vs baseline: 1.4964x; 1.0144x over previous
#include <cuda_runtime.h>
#include <cuda_fp16.h>
#include <math.h>
#include <stdint.h>

// Problem shapes (fixed by the reference)
#define BB      2
#define LL      1024
#define DIM     1024
#define DI      2048          // d_inner
#define MROWS   (BB*LL)       // 2048
#define DTRANK  64
#define DSTATE  16
#define XPROJ_N 96
#define XPN_PAD 128           // padded N for tensor-core xproj

typedef __half fp16;

// ---------------- scratch (device globals; no allocation allowed) ----------
__device__ fp16  g_xzh [MROWS * 2 * DI];     // fp16 xz (xs | z)
__device__ fp16  g_uh  [MROWS * DI];         // fp16 u
__device__ float g_xdbl[MROWS * XPN_PAD];    // x_dbl, ld=128 (cols 96-127 junk)
__device__ fp16  g_dth [MROWS * DI];         // fp16 dt

__device__ fp16 g_xnh [MROWS * DIM];
__device__ fp16 g_winh[2*DI * DIM];
__device__ fp16 g_yh  [MROWS * DI];
__device__ fp16 g_woh [DIM * DI];
__device__ fp16 g_dtrh[MROWS * DTRANK];
__device__ fp16 g_wdth[DI * DTRANK];
__device__ fp16 g_wxph[XPN_PAD * DI];        // fp16 w_xproj, rows 96-127 zero

// =================== baseline PTX helpers (no arch-'a' features) ============
__device__ __forceinline__ uint32_t smem_u32(const void* p) {
    uint32_t a;
    asm("{ .reg .u64 t; cvta.to.shared.u64 t, %1; cvt.u32.u64 %0, t; }" : "=r"(a) : "l"(p));
    return a;
}
#define CP_ASYNC16(dst, src) \
    asm volatile("cp.async.cg.shared.global [%0], [%1], 16;" :: "r"(dst), "l"(src))
#define CP_COMMIT() asm volatile("cp.async.commit_group;" ::: "memory")
#define CP_WAIT(n)  asm volatile("cp.async.wait_group %0;" :: "n"(n) : "memory")

__device__ __forceinline__ void ldsm4(uint32_t* r, uint32_t addr) {
    asm volatile("ldmatrix.sync.aligned.m8n8.x4.shared.b16 {%0,%1,%2,%3}, [%4];"
                 : "=r"(r[0]), "=r"(r[1]), "=r"(r[2]), "=r"(r[3]) : "r"(addr));
}
__device__ __forceinline__ void mma_fp16(float* c, const uint32_t* a, const uint32_t* b) {
    asm volatile("mma.sync.aligned.m16n8k16.row.col.f32.f16.f16.f32 "
                 "{%0,%1,%2,%3}, {%4,%5,%6,%7}, {%8,%9}, {%0,%1,%2,%3};"
                 : "+f"(c[0]), "+f"(c[1]), "+f"(c[2]), "+f"(c[3])
                 : "r"(a[0]), "r"(a[1]), "r"(a[2]), "r"(a[3]), "r"(b[0]), "r"(b[1]));
}
// SW64 swizzle for 64-byte stage rows (verified conflict-free for ldsm phases)
__device__ __forceinline__ uint32_t sw64(uint32_t off) { return off ^ ((off >> 3) & 0x30); }

// =================== fp16 mma.sync GEMM: C = A @ B^T ========================
// Pure fp16 A and B. BM=128, BN in {128,64}, BK=32/stage, 3-stage cp.async
// ring, 8 warps, 2 CTAs/SM. All ldsm of a k16-slice hoisted before MMAs.
// EPI: 0 fp16 store, 1 softplus+bias fp16 store, 2 +resid fp32 store,
//      3 fp32 store + fp16 dtr extract (cols<64), for the xproj GEMM
template<int EPI, int BN>
__global__ void __launch_bounds__(256, 2)
gemm_f16(const fp16* __restrict__ Ah, const fp16* __restrict__ Bh,
         void* __restrict__ Cout, const float* __restrict__ aux,
         fp16* __restrict__ dtr,
         int K, int ldc) {
    extern __shared__ char smem[];
    const uint32_t sb = smem_u32(smem);
    constexpr int ABY = 128 * 64;            // bytes for A per stage
    constexpr int BBY = BN * 64;             // bytes for B per stage
    constexpr int STG = ABY + BBY;           // stage size
    constexpr int MT  = (BN == 128) ? 4 : 2; // m16 tiles per warp
    const int tid = threadIdx.x, wid = tid >> 5, lane = tid & 31;
    const int m0 = blockIdx.y * 128, n0 = blockIdx.x * BN;
    const int wm = (BN == 128) ? (wid >> 2) : (wid >> 1);
    const int wn = (BN == 128) ? (wid & 3)  : (wid & 1);

    float acc[MT][4][4];
    #pragma unroll
    for (int a = 0; a < MT; a++)
        #pragma unroll
        for (int b = 0; b < 4; b++)
            #pragma unroll
            for (int c = 0; c < 4; c++) acc[a][b][c] = 0.f;

    // stage s: [Ah | Bh], 64B SW64 rows of 32 fp16
    auto load_stage = [&](int s, int kc) {
        uint32_t base = sb + s * STG;
        #pragma unroll
        for (int it = 0; it < 2; it++) {          // A: 128 rows
            int i = tid + it * 256;
            int row = i >> 2, j = i & 3;
            uint32_t so = sw64(row * 64 + j * 16);
            CP_ASYNC16(base + so,
                       Ah + (size_t)(m0 + row) * K + kc * 32 + j * 8);
        }
        #pragma unroll
        for (int it = 0; it < BN / 64; it++) {    // B: BN rows
            int i = tid + it * 256;
            int row = i >> 2, j = i & 3;
            uint32_t so = sw64(row * 64 + j * 16);
            CP_ASYNC16(base + ABY + so,
                       Bh + (size_t)(n0 + row) * K + kc * 32 + j * 8);
        }
        CP_COMMIT();
    };

    auto compute = [&](int s) {
        uint32_t pAh = sb + s * STG;
        uint32_t pBh = pAh + ABY;
        #pragma unroll
        for (int kk = 0; kk < 2; kk++) {
            uint32_t bh[2][4], ah[MT][4];
            int grp = lane >> 3, l8 = lane & 7;
            int kbB = kk * 32 + ((grp & 1) << 4);
            #pragma unroll
            for (int pr = 0; pr < 2; pr++) {
                int row = wn * 32 + pr * 16 + ((grp >> 1) << 3) + l8;
                ldsm4(bh[pr], pBh + sw64(row * 64 + kbB));
            }
            int kbA = kk * 32 + ((lane >> 4) << 4);
            #pragma unroll
            for (int mt = 0; mt < MT; mt++) {
                int row = wm * (MT * 16) + mt * 16 + (lane & 15);
                ldsm4(ah[mt], pAh + sw64(row * 64 + kbA));
            }
            #pragma unroll
            for (int mt = 0; mt < MT; mt++)
                #pragma unroll
                for (int pr = 0; pr < 2; pr++)
                    #pragma unroll
                    for (int half = 0; half < 2; half++)
                        mma_fp16(acc[mt][pr * 2 + half], ah[mt], &bh[pr][half * 2]);
        }
    };

    const int nst = K >> 5;
    load_stage(0, 0);
    if (nst > 1) load_stage(1, 1);
    int slot = 0;
    for (int kc = 0; kc < nst; kc++) {
        if (kc + 1 < nst) CP_WAIT(1); else CP_WAIT(0);
        __syncthreads();                       // stage kc ready, prev compute done
        if (kc + 2 < nst) load_stage((kc + 2) % 3, kc + 2);
        compute(slot);
        slot = (slot + 1 == 3) ? 0 : slot + 1;
    }

    // epilogue
    #pragma unroll
    for (int mt = 0; mt < MT; mt++) {
        #pragma unroll
        for (int nt = 0; nt < 4; nt++) {
            int row = m0 + wm * (MT * 16) + mt * 16 + (lane >> 2);
            int col = n0 + wn * 32 + nt * 8 + (lane & 3) * 2;
            float v[4] = {acc[mt][nt][0], acc[mt][nt][1], acc[mt][nt][2], acc[mt][nt][3]};
            if (EPI == 0) {                    // plain fp16 store
                fp16* C = (fp16*)Cout;
                *reinterpret_cast<__half2*>(&C[(size_t)row * ldc + col]) =
                    __floats2half2_rn(v[0], v[1]);
                *reinterpret_cast<__half2*>(&C[(size_t)(row + 8) * ldc + col]) =
                    __floats2half2_rn(v[2], v[3]);
            } else if (EPI == 1) {             // softplus + bias, fp16 store
                #pragma unroll
                for (int i = 0; i < 4; i++) {
                    float t = v[i] + aux[col + (i & 1)];
                    v[i] = fmaxf(t, 0.f) + log1pf(__expf(-fabsf(t)));
                }
                fp16* C = (fp16*)Cout;
                *reinterpret_cast<__half2*>(&C[(size_t)row * ldc + col]) =
                    __floats2half2_rn(v[0], v[1]);
                *reinterpret_cast<__half2*>(&C[(size_t)(row + 8) * ldc + col]) =
                    __floats2half2_rn(v[2], v[3]);
            } else if (EPI == 2) {             // + residual, fp32 store
                float* C = (float*)Cout;
                v[0] += aux[(size_t)row * ldc + col];
                v[1] += aux[(size_t)row * ldc + col + 1];
                v[2] += aux[(size_t)(row + 8) * ldc + col];
                v[3] += aux[(size_t)(row + 8) * ldc + col + 1];
                *reinterpret_cast<float2*>(&C[(size_t)row * ldc + col])       = make_float2(v[0], v[1]);
                *reinterpret_cast<float2*>(&C[(size_t)(row + 8) * ldc + col]) = make_float2(v[2], v[3]);
            } else {                           // EPI==3: fp32 store + dtr fp16
                float* C = (float*)Cout;
                *reinterpret_cast<float2*>(&C[(size_t)row * ldc + col])       = make_float2(v[0], v[1]);
                *reinterpret_cast<float2*>(&C[(size_t)(row + 8) * ldc + col]) = make_float2(v[2], v[3]);
                if (col < DTRANK) {
                    *reinterpret_cast<__half2*>(&dtr[(size_t)row * DTRANK + col]) =
                        __floats2half2_rn(v[0], v[1]);
                    *reinterpret_cast<__half2*>(&dtr[(size_t)(row + 8) * DTRANK + col]) =
                        __floats2half2_rn(v[2], v[3]);
                }
            }
        }
    }
}

// ---------------- merged cvt (w_in|w_out|w_dt|w_xproj) + LayerNorm ----------
#define N1_CVT (2*DI*DIM/4)
#define N2_CVT (DIM*DI/4)
#define N3_CVT (DI*DTRANK/4)
#define N4_CVT (XPROJ_N*DI/4)
#define NCVT   (N1_CVT + N2_CVT + N3_CVT + N4_CVT)
#define CVTB   ((NCVT + 255) / 256)

__global__ void cvt_ln_kernel(const float* __restrict__ w_in, const float* __restrict__ w_out,
                              const float* __restrict__ w_dt, const float* __restrict__ w_xpr,
                              fp16* __restrict__ winh, fp16* __restrict__ woh,
                              fp16* __restrict__ wdth, fp16* __restrict__ wxph,
                              const float* __restrict__ x,
                              const float* __restrict__ lw,
                              const float* __restrict__ lb,
                              fp16* __restrict__ xnh) {
    int tid = threadIdx.x;
    if (blockIdx.x < CVTB) {
        int i = blockIdx.x * 256 + tid;
        const float* s; fp16* d; int k;
        if (i < N1_CVT)                         { s = w_in;  d = winh; k = i; }
        else if (i < N1_CVT + N2_CVT)           { s = w_out; d = woh;  k = i - N1_CVT; }
        else if (i < N1_CVT + N2_CVT + N3_CVT)  { s = w_dt;  d = wdth; k = i - N1_CVT - N2_CVT; }
        else if (i < NCVT)                      { s = w_xpr; d = wxph; k = i - N1_CVT - N2_CVT - N3_CVT; }
        else return;
        float4 v = reinterpret_cast<const float4*>(s)[k];
        __half2* hp = reinterpret_cast<__half2*>(d);
        hp[k*2]   = __floats2half2_rn(v.x, v.y);
        hp[k*2+1] = __floats2half2_rn(v.z, v.w);
        return;
    }
    // LayerNorm branch: one block per row
    int row = blockIdx.x - CVTB;
    const float4* xr = reinterpret_cast<const float4*>(x + (size_t)row * DIM);
    float4 v = xr[tid];
    float s  = v.x + v.y + v.z + v.w;
    float sq = v.x*v.x + v.y*v.y + v.z*v.z + v.w*v.w;
    __shared__ float red[2][8];
    for (int off = 16; off > 0; off >>= 1) {
        s  += __shfl_xor_sync(0xffffffffu, s,  off);
        sq += __shfl_xor_sync(0xffffffffu, sq, off);
    }
    int warp = tid >> 5, lane = tid & 31;
    if (lane == 0) { red[0][warp] = s; red[1][warp] = sq; }
    __syncthreads();
    if (warp == 0) {
        float a = (lane < 8) ? red[0][lane] : 0.f;
        float c = (lane < 8) ? red[1][lane] : 0.f;
        for (int off = 4; off > 0; off >>= 1) {
            a += __shfl_xor_sync(0xffffffffu, a, off);
            c += __shfl_xor_sync(0xffffffffu, c, off);
        }
        if (lane == 0) { red[0][0] = a; red[1][0] = c; }
    }
    __syncthreads();
    float mu  = red[0][0] * (1.f / DIM);
    float var = red[1][0] * (1.f / DIM) - mu * mu;
    float rs  = rsqrtf(var + 1e-5f);
    const float4* w4 = reinterpret_cast<const float4*>(lw);
    const float4* b4 = reinterpret_cast<const float4*>(lb);
    float4 ww = w4[tid], bb = b4[tid];
    float o0 = (v.x - mu) * rs * ww.x + bb.x;
    float o1 = (v.y - mu) * rs * ww.y + bb.y;
    float o2 = (v.z - mu) * rs * ww.z + bb.z;
    float o3 = (v.w - mu) * rs * ww.w + bb.w;
    __half2* hp = reinterpret_cast<__half2*>(xnh + (size_t)row * DIM + tid * 4);
    hp[0] = __floats2half2_rn(o0, o1);
    hp[1] = __floats2half2_rn(o2, o3);
}

// ---------------- causal conv (k=4) + SiLU, sliding window (8 l per thread) -
__global__ void conv_silu_kernel(const fp16* __restrict__ xzh,
                                 const float* __restrict__ cw,
                                 const float* __restrict__ cb,
                                 fp16* __restrict__ uh) {
    int idx = blockIdx.x * blockDim.x + threadIdx.x;   // over BB*(LL/8)*DI
    if (idx >= BB * (LL / 8) * DI) return;
    int e  = idx & (DI - 1);
    int lg = idx >> 11;              // group index: 0 .. BB*LL/8-1
    int b  = lg >> 7;                // 128 groups per batch
    int l0 = (lg & 127) * 8;

    float w0 = cw[e*4+0], w1 = cw[e*4+1], w2 = cw[e*4+2], w3 = cw[e*4+3];
    float bias = cb[e];
    size_t base = ((size_t)(b * LL + l0)) * (2 * DI) + e;

    float xv[11];
    #pragma unroll
    for (int t = 0; t < 3; t++) {
        int l = l0 + t - 3;
        xv[t] = (l >= 0) ? __half2float(xzh[base + (ptrdiff_t)(t - 3) * (2 * DI)]) : 0.f;
    }
    #pragma unroll
    for (int t = 0; t < 8; t++)
        xv[t + 3] = __half2float(xzh[base + (size_t)t * (2 * DI)]);

    #pragma unroll
    for (int t = 0; t < 8; t++) {
        float acc = bias;
        acc = fmaf(w0, xv[t],     acc);
        acc = fmaf(w1, xv[t + 1], acc);
        acc = fmaf(w2, xv[t + 2], acc);
        acc = fmaf(w3, xv[t + 3], acc);
        float s = acc / (1.f + __expf(-acc));
        uh[(size_t)(b * LL + l0 + t) * DI + e] = __float2half_rn(s);
    }
}

// ---------------- SSM selective scan (8-way batched reductions) -------------
#define CHUNK 64
__global__ void scan_kernel(const fp16* __restrict__ dth,
                            const fp16* __restrict__ uh,
                            const float* __restrict__ xdbl,
                            const fp16* __restrict__ xzh,
                            const float* __restrict__ a_log,
                            const float* __restrict__ d_skip,
                            fp16* __restrict__ yh) {
    __shared__ float sB [CHUNK][DSTATE];
    __shared__ float sC [CHUNK][DSTATE];
    __shared__ float sDt[CHUNK][16];
    __shared__ float sU [CHUNK][16];
    __shared__ float sZ [CHUNK][16];
    int tid  = threadIdx.x;
    int g    = tid >> 4;
    int lane = tid & 15;
    int c0   = blockIdx.x * 16;
    int b    = c0 >> 11;
    int e0   = c0 & (DI - 1);
    int e    = e0 + g;
    float A_n = -__expf(a_log[e * DSTATE + lane]);
    float dsk = d_skip[e];
    float h = 0.f;
    int rowbase = b * LL;
    for (int l0 = 0; l0 < LL; l0 += CHUNK) {
        __syncthreads();
        for (int i = tid; i < CHUNK * 2 * DSTATE; i += 256) {
            int r = i >> 5, j = i & 31;
            float v = xdbl[(size_t)(rowbase + l0 + r) * XPN_PAD + DTRANK + j];
            if (j < DSTATE) sB[r][j] = v; else sC[r][j - DSTATE] = v;
        }
        for (int i = tid; i < CHUNK * 16; i += 256) {
            int r = i >> 4, j = i & 15;
            size_t m = (size_t)(rowbase + l0 + r);
            sDt[r][j] = __half2float(dth[m * DI + e0 + j]);
            sU [r][j] = __half2float(uh [m * DI + e0 + j]);
            sZ [r][j] = __half2float(xzh[m * (2 * DI) + DI + e0 + j]);
        }
        __syncthreads();
        #pragma unroll
        for (int rg = 0; rg < CHUNK; rg += 8) {
            float yv[8];
            #pragma unroll
            for (int q = 0; q < 8; q++) {          // serial h chain (4-cyc fma)
                int r = rg + q;
                float dtv = sDt[r][g];
                float uv  = sU [r][g];
                float dA  = __expf(dtv * A_n);
                float dBu = dtv * sB[r][lane] * uv;
                h = fmaf(dA, h, dBu);
                yv[q] = h * sC[r][lane];
            }
            #pragma unroll
            for (int off = 8; off > 0; off >>= 1)  // 8 trees interleaved (ILP)
                #pragma unroll
                for (int q = 0; q < 8; q++)
                    yv[q] += __shfl_xor_sync(0xffffffffu, yv[q], off);
            if (lane == 0) {
                #pragma unroll
                for (int q = 0; q < 8; q++) {
                    int r = rg + q;
                    float zv = sZ[r][g];
                    float sz = zv / (1.f + __expf(-zv));
                    float uv = sU[r][g];
                    float yo = (yv[q] + uv * dsk) * sz;
                    yh[(size_t)(rowbase + l0 + r) * DI + e] = __float2half_rn(yo);
                }
            }
        }
    }
}

// ---------------- launch -----------------------------------------------------
extern "C" void kernel_launch(void* const* d_in, const int* in_sizes, int n_in,
                              void* d_out, int out_size) {
    const float* x      = (const float*)d_in[0];
    const float* ln_w   = (const float*)d_in[1];
    const float* ln_b   = (const float*)d_in[2];
    const float* w_in   = (const float*)d_in[3];
    const float* conv_w = (const float*)d_in[4];
    const float* conv_b = (const float*)d_in[5];
    const float* w_xpr  = (const float*)d_in[6];
    const float* w_dt   = (const float*)d_in[7];
    const float* b_dt   = (const float*)d_in[8];
    const float* a_log  = (const float*)d_in[9];
    const float* d_skip = (const float*)d_in[10];
    const float* w_out  = (const float*)d_in[11];
    float* out = (float*)d_out;

    float *xdbl;
    fp16 *xzh, *uh, *dth, *xnh, *winh, *yh, *woh, *dtrh, *wdth, *wxph;
    cudaGetSymbolAddress((void**)&xzh,  g_xzh);
    cudaGetSymbolAddress((void**)&uh,   g_uh);
    cudaGetSymbolAddress((void**)&xdbl, g_xdbl);
    cudaGetSymbolAddress((void**)&dth,  g_dth);
    cudaGetSymbolAddress((void**)&xnh,  g_xnh);
    cudaGetSymbolAddress((void**)&winh, g_winh);
    cudaGetSymbolAddress((void**)&yh,   g_yh);
    cudaGetSymbolAddress((void**)&woh,  g_woh);
    cudaGetSymbolAddress((void**)&dtrh, g_dtrh);
    cudaGetSymbolAddress((void**)&wdth, g_wdth);
    cudaGetSymbolAddress((void**)&wxph, g_wxph);

    const int SMEM128 = 3 * 16384;   // BN=128: 48 KB, 3-stage ring
    const int SMEM64  = 3 * 12288;   // BN=64:  36 KB, 3-stage ring
    cudaFuncSetAttribute((const void*)gemm_f16<0,128>, cudaFuncAttributeMaxDynamicSharedMemorySize, SMEM128);
    cudaFuncSetAttribute((const void*)gemm_f16<1,128>, cudaFuncAttributeMaxDynamicSharedMemorySize, SMEM128);
    cudaFuncSetAttribute((const void*)gemm_f16<2,64>,  cudaFuncAttributeMaxDynamicSharedMemorySize, SMEM64);
    cudaFuncSetAttribute((const void*)gemm_f16<3,128>, cudaFuncAttributeMaxDynamicSharedMemorySize, SMEM128);

    // 1. weight conversions (incl. w_xproj) + LayerNorm (one launch)
    cvt_ln_kernel<<<CVTB + MROWS, 256>>>(w_in, w_out, w_dt, w_xpr,
                                         winh, woh, wdth, wxph,
                                         x, ln_w, ln_b, xnh);
    // 2. xz = xn @ w_in^T   (2048 x 4096 x 1024)  [fp16 mma, fp16 OUT]
    gemm_f16<0,128><<<dim3(4096/128, MROWS/128), 256, SMEM128>>>(
        xnh, winh, xzh, nullptr, nullptr, DIM, 2*DI);
    // 3. u = silu(conv(xs))  [sliding window, 8 l per thread]
    conv_silu_kernel<<<(BB*(LL/8)*DI + 255)/256, 256>>>(xzh, conv_w, conv_b, uh);
    // 4. x_dbl = u @ w_xproj^T  (2048 x 128pad x 2048)  [fp16 mma + dtr]  <-- slot
    gemm_f16<3,128><<<dim3(1, MROWS/128), 256, SMEM128>>>(
        uh, wxph, xdbl, nullptr, dtrh, DI, XPN_PAD);
    // 5. dt = softplus(dt_r @ w_dt^T + b_dt)  [BN=128, fp16 OUT]
    gemm_f16<1,128><<<dim3(DI/128, MROWS/128), 256, SMEM128>>>(
        dtrh, wdth, dth, b_dt, nullptr, DTRANK, DI);
    // 6. selective scan (fp16 dt/u/z in, fp16 y out)
    scan_kernel<<<(BB*DI)/16, 256>>>(dth, uh, xdbl, xzh, a_log, d_skip, yh);
    // 7. out = residual + y @ w_out^T  (2048 x 1024 x 2048)  [BN=64, 256 CTAs]
    gemm_f16<2,64><<<dim3(DIM/64, MROWS/128), 256, SMEM64>>>(
        yh, woh, out, x, nullptr, DI, DIM);
}

// round 17
// speedup vs baseline: 1.6383x; 1.0948x over previous
#include <cuda_runtime.h>
#include <cuda_fp16.h>
#include <math.h>
#include <stdint.h>

// Problem shapes (fixed by the reference)
#define BB      2
#define LL      1024
#define DIM     1024
#define DI      2048          // d_inner
#define MROWS   (BB*LL)       // 2048
#define DTRANK  64
#define DSTATE  16
#define XPROJ_N 96
#define XPN_PAD 128           // padded N for tensor-core xproj
#define XSPLIT  8             // split-K ways for xproj GEMM

typedef __half fp16;

// ---------------- scratch (device globals; no allocation allowed) ----------
__device__ fp16  g_xzh [MROWS * 2 * DI];     // fp16 xz (xs | z)
__device__ fp16  g_uh  [MROWS * DI];         // fp16 u
__device__ float g_xdbl[MROWS * XPN_PAD];    // x_dbl, ld=128 (cols 96-127 junk)
__device__ fp16  g_dth [MROWS * DI];         // fp16 dt
__device__ float g_part[XSPLIT * MROWS * XPN_PAD];  // split-K partials (8 MB)

__device__ fp16 g_xnh [MROWS * DIM];
__device__ fp16 g_winh[2*DI * DIM];
__device__ fp16 g_yh  [MROWS * DI];
__device__ fp16 g_woh [DIM * DI];
__device__ fp16 g_dtrh[MROWS * DTRANK];
__device__ fp16 g_wdth[DI * DTRANK];
__device__ fp16 g_wxph[XPN_PAD * DI];        // fp16 w_xproj, rows 96-127 zero

// =================== baseline PTX helpers (no arch-'a' features) ============
__device__ __forceinline__ uint32_t smem_u32(const void* p) {
    uint32_t a;
    asm("{ .reg .u64 t; cvta.to.shared.u64 t, %1; cvt.u32.u64 %0, t; }" : "=r"(a) : "l"(p));
    return a;
}
#define CP_ASYNC16(dst, src) \
    asm volatile("cp.async.cg.shared.global [%0], [%1], 16;" :: "r"(dst), "l"(src))
#define CP_COMMIT() asm volatile("cp.async.commit_group;" ::: "memory")
#define CP_WAIT(n)  asm volatile("cp.async.wait_group %0;" :: "n"(n) : "memory")

__device__ __forceinline__ void ldsm4(uint32_t* r, uint32_t addr) {
    asm volatile("ldmatrix.sync.aligned.m8n8.x4.shared.b16 {%0,%1,%2,%3}, [%4];"
                 : "=r"(r[0]), "=r"(r[1]), "=r"(r[2]), "=r"(r[3]) : "r"(addr));
}
__device__ __forceinline__ void mma_fp16(float* c, const uint32_t* a, const uint32_t* b) {
    asm volatile("mma.sync.aligned.m16n8k16.row.col.f32.f16.f16.f32 "
                 "{%0,%1,%2,%3}, {%4,%5,%6,%7}, {%8,%9}, {%0,%1,%2,%3};"
                 : "+f"(c[0]), "+f"(c[1]), "+f"(c[2]), "+f"(c[3])
                 : "r"(a[0]), "r"(a[1]), "r"(a[2]), "r"(a[3]), "r"(b[0]), "r"(b[1]));
}
// SW64 swizzle for 64-byte stage rows (verified conflict-free for ldsm phases)
__device__ __forceinline__ uint32_t sw64(uint32_t off) { return off ^ ((off >> 3) & 0x30); }

// =================== fp16 mma.sync GEMM: C = A @ B^T ========================
// Pure fp16 A and B. BM=128, BN in {128,64}, BK=32/stage, 3-stage cp.async
// ring, 8 warps, 2 CTAs/SM. All ldsm of a k16-slice hoisted before MMAs.
// EPI: 0 fp16 store, 1 softplus+bias fp16 store, 2 +resid fp32 store,
//      4 split-K fp32 partial store (K = per-split extent, lda = full stride)
template<int EPI, int BN>
__global__ void __launch_bounds__(256, 2)
gemm_f16(const fp16* __restrict__ Ah, const fp16* __restrict__ Bh,
         void* __restrict__ Cout, const float* __restrict__ aux,
         int K, int lda, int ldc) {
    extern __shared__ char smem[];
    const uint32_t sb = smem_u32(smem);
    constexpr int ABY = 128 * 64;            // bytes for A per stage
    constexpr int BBY = BN * 64;             // bytes for B per stage
    constexpr int STG = ABY + BBY;           // stage size
    constexpr int MT  = (BN == 128) ? 4 : 2; // m16 tiles per warp
    const int tid = threadIdx.x, wid = tid >> 5, lane = tid & 31;
    const int m0 = blockIdx.y * 128, n0 = blockIdx.x * BN;
    const int wm = (BN == 128) ? (wid >> 2) : (wid >> 1);
    const int wn = (BN == 128) ? (wid & 3)  : (wid & 1);
    const int koff = (EPI == 4) ? blockIdx.z * K : 0;

    float acc[MT][4][4];
    #pragma unroll
    for (int a = 0; a < MT; a++)
        #pragma unroll
        for (int b = 0; b < 4; b++)
            #pragma unroll
            for (int c = 0; c < 4; c++) acc[a][b][c] = 0.f;

    // stage s: [Ah | Bh], 64B SW64 rows of 32 fp16
    auto load_stage = [&](int s, int kc) {
        uint32_t base = sb + s * STG;
        #pragma unroll
        for (int it = 0; it < 2; it++) {          // A: 128 rows
            int i = tid + it * 256;
            int row = i >> 2, j = i & 3;
            uint32_t so = sw64(row * 64 + j * 16);
            CP_ASYNC16(base + so,
                       Ah + (size_t)(m0 + row) * lda + koff + kc * 32 + j * 8);
        }
        #pragma unroll
        for (int it = 0; it < BN / 64; it++) {    // B: BN rows
            int i = tid + it * 256;
            int row = i >> 2, j = i & 3;
            uint32_t so = sw64(row * 64 + j * 16);
            CP_ASYNC16(base + ABY + so,
                       Bh + (size_t)(n0 + row) * lda + koff + kc * 32 + j * 8);
        }
        CP_COMMIT();
    };

    auto compute = [&](int s) {
        uint32_t pAh = sb + s * STG;
        uint32_t pBh = pAh + ABY;
        #pragma unroll
        for (int kk = 0; kk < 2; kk++) {
            uint32_t bh[2][4], ah[MT][4];
            int grp = lane >> 3, l8 = lane & 7;
            int kbB = kk * 32 + ((grp & 1) << 4);
            #pragma unroll
            for (int pr = 0; pr < 2; pr++) {
                int row = wn * 32 + pr * 16 + ((grp >> 1) << 3) + l8;
                ldsm4(bh[pr], pBh + sw64(row * 64 + kbB));
            }
            int kbA = kk * 32 + ((lane >> 4) << 4);
            #pragma unroll
            for (int mt = 0; mt < MT; mt++) {
                int row = wm * (MT * 16) + mt * 16 + (lane & 15);
                ldsm4(ah[mt], pAh + sw64(row * 64 + kbA));
            }
            #pragma unroll
            for (int mt = 0; mt < MT; mt++)
                #pragma unroll
                for (int pr = 0; pr < 2; pr++)
                    #pragma unroll
                    for (int half = 0; half < 2; half++)
                        mma_fp16(acc[mt][pr * 2 + half], ah[mt], &bh[pr][half * 2]);
        }
    };

    const int nst = K >> 5;
    load_stage(0, 0);
    if (nst > 1) load_stage(1, 1);
    int slot = 0;
    for (int kc = 0; kc < nst; kc++) {
        if (kc + 1 < nst) CP_WAIT(1); else CP_WAIT(0);
        __syncthreads();                       // stage kc ready, prev compute done
        if (kc + 2 < nst) load_stage((kc + 2) % 3, kc + 2);
        compute(slot);
        slot = (slot + 1 == 3) ? 0 : slot + 1;
    }

    // epilogue
    #pragma unroll
    for (int mt = 0; mt < MT; mt++) {
        #pragma unroll
        for (int nt = 0; nt < 4; nt++) {
            int row = m0 + wm * (MT * 16) + mt * 16 + (lane >> 2);
            int col = n0 + wn * 32 + nt * 8 + (lane & 3) * 2;
            float v[4] = {acc[mt][nt][0], acc[mt][nt][1], acc[mt][nt][2], acc[mt][nt][3]};
            if (EPI == 0) {                    // plain fp16 store
                fp16* C = (fp16*)Cout;
                *reinterpret_cast<__half2*>(&C[(size_t)row * ldc + col]) =
                    __floats2half2_rn(v[0], v[1]);
                *reinterpret_cast<__half2*>(&C[(size_t)(row + 8) * ldc + col]) =
                    __floats2half2_rn(v[2], v[3]);
            } else if (EPI == 1) {             // softplus + bias, fp16 store
                #pragma unroll
                for (int i = 0; i < 4; i++) {
                    float t = v[i] + aux[col + (i & 1)];
                    v[i] = fmaxf(t, 0.f) + log1pf(__expf(-fabsf(t)));
                }
                fp16* C = (fp16*)Cout;
                *reinterpret_cast<__half2*>(&C[(size_t)row * ldc + col]) =
                    __floats2half2_rn(v[0], v[1]);
                *reinterpret_cast<__half2*>(&C[(size_t)(row + 8) * ldc + col]) =
                    __floats2half2_rn(v[2], v[3]);
            } else if (EPI == 2) {             // + residual, fp32 store
                float* C = (float*)Cout;
                v[0] += aux[(size_t)row * ldc + col];
                v[1] += aux[(size_t)row * ldc + col + 1];
                v[2] += aux[(size_t)(row + 8) * ldc + col];
                v[3] += aux[(size_t)(row + 8) * ldc + col + 1];
                *reinterpret_cast<float2*>(&C[(size_t)row * ldc + col])       = make_float2(v[0], v[1]);
                *reinterpret_cast<float2*>(&C[(size_t)(row + 8) * ldc + col]) = make_float2(v[2], v[3]);
            } else {                           // EPI==4: split-K fp32 partial
                float* C = (float*)Cout + (size_t)blockIdx.z * MROWS * XPN_PAD;
                *reinterpret_cast<float2*>(&C[(size_t)row * ldc + col])       = make_float2(v[0], v[1]);
                *reinterpret_cast<float2*>(&C[(size_t)(row + 8) * ldc + col]) = make_float2(v[2], v[3]);
            }
        }
    }
}

// ---------------- split-K reduce: part -> xdbl (+ dtr fp16 extract) ---------
__global__ void xdbl_reduce(const float* __restrict__ part, float* __restrict__ xdbl,
                            fp16* __restrict__ dtrh) {
    int i = blockIdx.x * blockDim.x + threadIdx.x;   // over MROWS*32 float4s
    const int TOT4 = MROWS * XPN_PAD / 4;
    if (i >= TOT4) return;
    float4 s = reinterpret_cast<const float4*>(part)[i];
    #pragma unroll
    for (int sp = 1; sp < XSPLIT; sp++) {
        float4 v = reinterpret_cast<const float4*>(part + (size_t)sp * MROWS * XPN_PAD)[i];
        s.x += v.x; s.y += v.y; s.z += v.z; s.w += v.w;
    }
    reinterpret_cast<float4*>(xdbl)[i] = s;
    int row = i >> 5, c4 = (i & 31) * 4;
    if (c4 < DTRANK) {
        __half2* hp = reinterpret_cast<__half2*>(dtrh + (size_t)row * DTRANK + c4);
        hp[0] = __floats2half2_rn(s.x, s.y);
        hp[1] = __floats2half2_rn(s.z, s.w);
    }
}

// ---------------- merged cvt (w_in|w_out|w_dt|w_xproj) + LayerNorm ----------
#define N1_CVT (2*DI*DIM/4)
#define N2_CVT (DIM*DI/4)
#define N3_CVT (DI*DTRANK/4)
#define N4_CVT (XPROJ_N*DI/4)
#define NCVT   (N1_CVT + N2_CVT + N3_CVT + N4_CVT)
#define CVTB   ((NCVT + 255) / 256)

__global__ void cvt_ln_kernel(const float* __restrict__ w_in, const float* __restrict__ w_out,
                              const float* __restrict__ w_dt, const float* __restrict__ w_xpr,
                              fp16* __restrict__ winh, fp16* __restrict__ woh,
                              fp16* __restrict__ wdth, fp16* __restrict__ wxph,
                              const float* __restrict__ x,
                              const float* __restrict__ lw,
                              const float* __restrict__ lb,
                              fp16* __restrict__ xnh) {
    int tid = threadIdx.x;
    if (blockIdx.x < CVTB) {
        int i = blockIdx.x * 256 + tid;
        const float* s; fp16* d; int k;
        if (i < N1_CVT)                         { s = w_in;  d = winh; k = i; }
        else if (i < N1_CVT + N2_CVT)           { s = w_out; d = woh;  k = i - N1_CVT; }
        else if (i < N1_CVT + N2_CVT + N3_CVT)  { s = w_dt;  d = wdth; k = i - N1_CVT - N2_CVT; }
        else if (i < NCVT)                      { s = w_xpr; d = wxph; k = i - N1_CVT - N2_CVT - N3_CVT; }
        else return;
        float4 v = reinterpret_cast<const float4*>(s)[k];
        __half2* hp = reinterpret_cast<__half2*>(d);
        hp[k*2]   = __floats2half2_rn(v.x, v.y);
        hp[k*2+1] = __floats2half2_rn(v.z, v.w);
        return;
    }
    // LayerNorm branch: one block per row
    int row = blockIdx.x - CVTB;
    const float4* xr = reinterpret_cast<const float4*>(x + (size_t)row * DIM);
    float4 v = xr[tid];
    float s  = v.x + v.y + v.z + v.w;
    float sq = v.x*v.x + v.y*v.y + v.z*v.z + v.w*v.w;
    __shared__ float red[2][8];
    for (int off = 16; off > 0; off >>= 1) {
        s  += __shfl_xor_sync(0xffffffffu, s,  off);
        sq += __shfl_xor_sync(0xffffffffu, sq, off);
    }
    int warp = tid >> 5, lane = tid & 31;
    if (lane == 0) { red[0][warp] = s; red[1][warp] = sq; }
    __syncthreads();
    if (warp == 0) {
        float a = (lane < 8) ? red[0][lane] : 0.f;
        float c = (lane < 8) ? red[1][lane] : 0.f;
        for (int off = 4; off > 0; off >>= 1) {
            a += __shfl_xor_sync(0xffffffffu, a, off);
            c += __shfl_xor_sync(0xffffffffu, c, off);
        }
        if (lane == 0) { red[0][0] = a; red[1][0] = c; }
    }
    __syncthreads();
    float mu  = red[0][0] * (1.f / DIM);
    float var = red[1][0] * (1.f / DIM) - mu * mu;
    float rs  = rsqrtf(var + 1e-5f);
    const float4* w4 = reinterpret_cast<const float4*>(lw);
    const float4* b4 = reinterpret_cast<const float4*>(lb);
    float4 ww = w4[tid], bb = b4[tid];
    float o0 = (v.x - mu) * rs * ww.x + bb.x;
    float o1 = (v.y - mu) * rs * ww.y + bb.y;
    float o2 = (v.z - mu) * rs * ww.z + bb.z;
    float o3 = (v.w - mu) * rs * ww.w + bb.w;
    __half2* hp = reinterpret_cast<__half2*>(xnh + (size_t)row * DIM + tid * 4);
    hp[0] = __floats2half2_rn(o0, o1);
    hp[1] = __floats2half2_rn(o2, o3);
}

// ---------------- causal conv (k=4) + SiLU, sliding window (8 l per thread) -
__global__ void conv_silu_kernel(const fp16* __restrict__ xzh,
                                 const float* __restrict__ cw,
                                 const float* __restrict__ cb,
                                 fp16* __restrict__ uh) {
    int idx = blockIdx.x * blockDim.x + threadIdx.x;   // over BB*(LL/8)*DI
    if (idx >= BB * (LL / 8) * DI) return;
    int e  = idx & (DI - 1);
    int lg = idx >> 11;              // group index: 0 .. BB*LL/8-1
    int b  = lg >> 7;                // 128 groups per batch
    int l0 = (lg & 127) * 8;

    float w0 = cw[e*4+0], w1 = cw[e*4+1], w2 = cw[e*4+2], w3 = cw[e*4+3];
    float bias = cb[e];
    size_t base = ((size_t)(b * LL + l0)) * (2 * DI) + e;

    float xv[11];
    #pragma unroll
    for (int t = 0; t < 3; t++) {
        int l = l0 + t - 3;
        xv[t] = (l >= 0) ? __half2float(xzh[base + (ptrdiff_t)(t - 3) * (2 * DI)]) : 0.f;
    }
    #pragma unroll
    for (int t = 0; t < 8; t++)
        xv[t + 3] = __half2float(xzh[base + (size_t)t * (2 * DI)]);

    #pragma unroll
    for (int t = 0; t < 8; t++) {
        float acc = bias;
        acc = fmaf(w0, xv[t],     acc);
        acc = fmaf(w1, xv[t + 1], acc);
        acc = fmaf(w2, xv[t + 2], acc);
        acc = fmaf(w3, xv[t + 3], acc);
        float s = acc / (1.f + __expf(-acc));
        uh[(size_t)(b * LL + l0 + t) * DI + e] = __float2half_rn(s);
    }
}

// ---------------- SSM selective scan (8-way batched reductions) -------------
#define CHUNK 64
__global__ void scan_kernel(const fp16* __restrict__ dth,
                            const fp16* __restrict__ uh,
                            const float* __restrict__ xdbl,
                            const fp16* __restrict__ xzh,
                            const float* __restrict__ a_log,
                            const float* __restrict__ d_skip,
                            fp16* __restrict__ yh) {
    __shared__ float sB [CHUNK][DSTATE];
    __shared__ float sC [CHUNK][DSTATE];
    __shared__ float sDt[CHUNK][16];
    __shared__ float sU [CHUNK][16];
    __shared__ float sZ [CHUNK][16];
    int tid  = threadIdx.x;
    int g    = tid >> 4;
    int lane = tid & 15;
    int c0   = blockIdx.x * 16;
    int b    = c0 >> 11;
    int e0   = c0 & (DI - 1);
    int e    = e0 + g;
    float A_n = -__expf(a_log[e * DSTATE + lane]);
    float dsk = d_skip[e];
    float h = 0.f;
    int rowbase = b * LL;
    for (int l0 = 0; l0 < LL; l0 += CHUNK) {
        __syncthreads();
        for (int i = tid; i < CHUNK * 2 * DSTATE; i += 256) {
            int r = i >> 5, j = i & 31;
            float v = xdbl[(size_t)(rowbase + l0 + r) * XPN_PAD + DTRANK + j];
            if (j < DSTATE) sB[r][j] = v; else sC[r][j - DSTATE] = v;
        }
        for (int i = tid; i < CHUNK * 16; i += 256) {
            int r = i >> 4, j = i & 15;
            size_t m = (size_t)(rowbase + l0 + r);
            sDt[r][j] = __half2float(dth[m * DI + e0 + j]);
            sU [r][j] = __half2float(uh [m * DI + e0 + j]);
            sZ [r][j] = __half2float(xzh[m * (2 * DI) + DI + e0 + j]);
        }
        __syncthreads();
        #pragma unroll
        for (int rg = 0; rg < CHUNK; rg += 8) {
            float yv[8];
            #pragma unroll
            for (int q = 0; q < 8; q++) {          // serial h chain (4-cyc fma)
                int r = rg + q;
                float dtv = sDt[r][g];
                float uv  = sU [r][g];
                float dA  = __expf(dtv * A_n);
                float dBu = dtv * sB[r][lane] * uv;
                h = fmaf(dA, h, dBu);
                yv[q] = h * sC[r][lane];
            }
            #pragma unroll
            for (int off = 8; off > 0; off >>= 1)  // 8 trees interleaved (ILP)
                #pragma unroll
                for (int q = 0; q < 8; q++)
                    yv[q] += __shfl_xor_sync(0xffffffffu, yv[q], off);
            if (lane == 0) {
                #pragma unroll
                for (int q = 0; q < 8; q++) {
                    int r = rg + q;
                    float zv = sZ[r][g];
                    float sz = zv / (1.f + __expf(-zv));
                    float uv = sU[r][g];
                    float yo = (yv[q] + uv * dsk) * sz;
                    yh[(size_t)(rowbase + l0 + r) * DI + e] = __float2half_rn(yo);
                }
            }
        }
    }
}

// ---------------- launch -----------------------------------------------------
extern "C" void kernel_launch(void* const* d_in, const int* in_sizes, int n_in,
                              void* d_out, int out_size) {
    const float* x      = (const float*)d_in[0];
    const float* ln_w   = (const float*)d_in[1];
    const float* ln_b   = (const float*)d_in[2];
    const float* w_in   = (const float*)d_in[3];
    const float* conv_w = (const float*)d_in[4];
    const float* conv_b = (const float*)d_in[5];
    const float* w_xpr  = (const float*)d_in[6];
    const float* w_dt   = (const float*)d_in[7];
    const float* b_dt   = (const float*)d_in[8];
    const float* a_log  = (const float*)d_in[9];
    const float* d_skip = (const float*)d_in[10];
    const float* w_out  = (const float*)d_in[11];
    float* out = (float*)d_out;

    float *xdbl, *part;
    fp16 *xzh, *uh, *dth, *xnh, *winh, *yh, *woh, *dtrh, *wdth, *wxph;
    cudaGetSymbolAddress((void**)&xzh,  g_xzh);
    cudaGetSymbolAddress((void**)&uh,   g_uh);
    cudaGetSymbolAddress((void**)&xdbl, g_xdbl);
    cudaGetSymbolAddress((void**)&dth,  g_dth);
    cudaGetSymbolAddress((void**)&part, g_part);
    cudaGetSymbolAddress((void**)&xnh,  g_xnh);
    cudaGetSymbolAddress((void**)&winh, g_winh);
    cudaGetSymbolAddress((void**)&yh,   g_yh);
    cudaGetSymbolAddress((void**)&woh,  g_woh);
    cudaGetSymbolAddress((void**)&dtrh, g_dtrh);
    cudaGetSymbolAddress((void**)&wdth, g_wdth);
    cudaGetSymbolAddress((void**)&wxph, g_wxph);

    const int SMEM128 = 3 * 16384;   // BN=128: 48 KB, 3-stage ring
    const int SMEM64  = 3 * 12288;   // BN=64:  36 KB, 3-stage ring
    cudaFuncSetAttribute((const void*)gemm_f16<0,128>, cudaFuncAttributeMaxDynamicSharedMemorySize, SMEM128);
    cudaFuncSetAttribute((const void*)gemm_f16<1,128>, cudaFuncAttributeMaxDynamicSharedMemorySize, SMEM128);
    cudaFuncSetAttribute((const void*)gemm_f16<2,64>,  cudaFuncAttributeMaxDynamicSharedMemorySize, SMEM64);
    cudaFuncSetAttribute((const void*)gemm_f16<4,128>, cudaFuncAttributeMaxDynamicSharedMemorySize, SMEM128);

    // 1. weight conversions (incl. w_xproj) + LayerNorm (one launch)
    cvt_ln_kernel<<<CVTB + MROWS, 256>>>(w_in, w_out, w_dt, w_xpr,
                                         winh, woh, wdth, wxph,
                                         x, ln_w, ln_b, xnh);
    // 2. xz = xn @ w_in^T   (2048 x 4096 x 1024)  [fp16 mma, fp16 OUT]
    gemm_f16<0,128><<<dim3(4096/128, MROWS/128), 256, SMEM128>>>(
        xnh, winh, xzh, nullptr, DIM, DIM, 2*DI);
    // 3. u = silu(conv(xs))  [sliding window, 8 l per thread]
    conv_silu_kernel<<<(BB*(LL/8)*DI + 255)/256, 256>>>(xzh, conv_w, conv_b, uh);
    // 4. x_dbl partials = u @ w_xproj^T  [split-K x8, 128 CTAs]  <-- slot
    gemm_f16<4,128><<<dim3(1, MROWS/128, XSPLIT), 256, SMEM128>>>(
        uh, wxph, part, nullptr, DI/XSPLIT, DI, XPN_PAD);
    // 5. reduce partials -> xdbl + dtr fp16 extract
    xdbl_reduce<<<(MROWS*XPN_PAD/4 + 255)/256, 256>>>(part, xdbl, dtrh);
    // 6. dt = softplus(dt_r @ w_dt^T + b_dt)  [BN=128, fp16 OUT]
    gemm_f16<1,128><<<dim3(DI/128, MROWS/128), 256, SMEM128>>>(
        dtrh, wdth, dth, b_dt, DTRANK, DTRANK, DI);
    // 7. selective scan (fp16 dt/u/z in, fp16 y out)
    scan_kernel<<<(BB*DI)/16, 256>>>(dth, uh, xdbl, xzh, a_log, d_skip, yh);
    // 8. out = residual + y @ w_out^T  (2048 x 1024 x 2048)  [BN=64, 256 CTAs]
    gemm_f16<2,64><<<dim3(DIM/64, MROWS/128), 256, SMEM64>>>(
        yh, woh, out, x, DI, DI, DIM);
}